// round 12
// baseline (speedup 1.0000x reference)
#include <cuda_runtime.h>
#include <cuda_fp16.h>
#include <math.h>
#include <stdint.h>

#define BATCH 64
#define CDIM 256
#define TDIM 128
#define JDIM 17
#define TJ 2176     // TDIM*JDIM
#define HCC 43
#define WCC 6
#define HW 258      // HCC*WCC
#define HIDDEN 1024

// scratch (static __device__ globals per harness rules)
__device__ __half g_qkv[(size_t)3 * BATCH * HW * CDIM];  // fp16 [b][t][hw][c]
__device__ __half g_att[(size_t)BATCH * HW * CDIM];      // fp16 [b][hw][c]
__device__ __half g_xn[(size_t)BATCH * CDIM * TJ];       // n1bn(x) fp16
// fp16 weights
__device__ __half g_w1h[8 * 32768];            // W1 per-tile [128 j][256 i]
__device__ __half g_w2h[8 * 32768];            // W2 per-tile [256 c][128 j]
__device__ __half g_qwh[768 * 2304];           // qkv conv weight row-major
__device__ __half g_pwh[256 * 256];            // proj weight row-major

__device__ __forceinline__ float gelu_exact(float v) {
    return 0.5f * v * (1.0f + erff(v * 0.70710678118654752f));
}

__device__ __forceinline__ uint32_t smem_u32(const void* p) {
    uint32_t a;
    asm("{ .reg .u64 t; cvta.to.shared.u64 t, %1; cvt.u32.u64 %0, t; }" : "=r"(a) : "l"(p));
    return a;
}

__device__ __forceinline__ uint32_t h2_to_u32(__half2 h) {
    return *reinterpret_cast<uint32_t*>(&h);
}

#define LDM_X4(r, addr) \
    asm volatile("ldmatrix.sync.aligned.m8n8.x4.shared.b16 {%0,%1,%2,%3}, [%4];" \
        : "=r"((r)[0]), "=r"((r)[1]), "=r"((r)[2]), "=r"((r)[3]) : "r"(addr))

#define LDM_X4_T(r, addr) \
    asm volatile("ldmatrix.sync.aligned.m8n8.x4.trans.shared.b16 {%0,%1,%2,%3}, [%4];" \
        : "=r"((r)[0]), "=r"((r)[1]), "=r"((r)[2]), "=r"((r)[3]) : "r"(addr))

#define MMA16816(d, a, b0, b1) \
    asm volatile("mma.sync.aligned.m16n8k16.row.col.f32.f16.f16.f32 " \
        "{%0,%1,%2,%3}, {%4,%5,%6,%7}, {%8,%9}, {%0,%1,%2,%3};" \
        : "+f"((d)[0]), "+f"((d)[1]), "+f"((d)[2]), "+f"((d)[3]) \
        : "r"((a)[0]), "r"((a)[1]), "r"((a)[2]), "r"((a)[3]), "r"(b0), "r"(b1))

#define CP_ASYNC16(dst, src) \
    asm volatile("cp.async.cg.shared.global [%0], [%1], 16;" :: "r"(dst), "l"(src))
#define CP_COMMIT() asm volatile("cp.async.commit_group;")
#define CP_WAIT1()  asm volatile("cp.async.wait_group 1;" ::: "memory")
#define CP_WAIT0()  asm volatile("cp.async.wait_group 0;" ::: "memory")

// ---------------------------------------------------------------------------
// K0: merged prep — blocks [0,16384): xn = n1bn(x) fp16; rest: weight convert
// ---------------------------------------------------------------------------
__global__ void __launch_bounds__(512) k_prep_all(
    const float* __restrict__ w1, const float* __restrict__ w2,
    const float* __restrict__ qkvw, const float* __restrict__ pw,
    const float* __restrict__ x,
    const float* __restrict__ n1g, const float* __restrict__ n1b,
    const float* __restrict__ n1m, const float* __restrict__ n1v)
{
    const int blk = blockIdx.x;
    if (blk < 16384) {
        __shared__ float ss, tt;
        const int c = blk & 255;
        if (threadIdx.x == 0) {
            float s = n1g[c] * rsqrtf(n1v[c] + 1e-5f);
            ss = s;
            tt = n1b[c] - n1m[c] * s;
        }
        __syncthreads();
        const float* xr = x + (size_t)blk * TJ;
        __half* xo = g_xn + (size_t)blk * TJ;
        float s = ss, t = tt;
        for (int p = threadIdx.x; p < TJ; p += 512)
            xo[p] = __float2half(xr[p] * s + t);
        return;
    }
    int idx = (blk - 16384) * 512 + threadIdx.x;
    if (idx < 262144) {
        int j = idx >> 8, i = idx & 255;
        int nt = j >> 7, jl = j & 127;
        g_w1h[(uint32_t)nt * 32768 + (uint32_t)jl * 256 + i] = __float2half(w1[idx]);
    } else if (idx < 524288) {
        int t = idx - 262144;
        int c = t >> 10, j = t & 1023;
        int nt = j >> 7, jl = j & 127;
        g_w2h[(uint32_t)nt * 32768 + (uint32_t)c * 128 + jl] = __float2half(w2[t]);
    } else if (idx < 2293760) {
        int t = idx - 524288;
        g_qwh[t] = __float2half(qkvw[t]);
    } else {
        int t = idx - 2293760;
        g_pwh[t] = __float2half(pw[t]);
    }
}

// ---------------------------------------------------------------------------
// K1: conv QKV on HMMA, merged M; K chunks of 128 (half the syncs, 4x MMA
// work per sync). Stride 136 buffers.
// ---------------------------------------------------------------------------
#define CV_KTAB  0
#define CV_SO    4608
#define CV_TO    5632
#define CV_PBUF  6656                    // 2 x 34816 = 69632
#define CV_WBUF  76288                   // 2 x 69632 = 139264
#define CV_STAGE CV_PBUF                 // float[128*129]=66048 (reuse)
#define CV_TOT   215552

__global__ void __launch_bounds__(512, 1) k_conv_mma(
    const float* __restrict__ qg, const float* __restrict__ qb,
    const float* __restrict__ qm, const float* __restrict__ qv)
{
    extern __shared__ char smem[];
    const uint32_t sbase = smem_u32(smem);
    const int tid = threadIdx.x;
    const int wid = tid >> 5, lane = tid & 31;
    const int wy = wid & 3, wx = wid >> 2;

    const int m0 = blockIdx.x * 256;
    const int n0 = blockIdx.y * 128;

    uint16_t* ktab = (uint16_t*)(smem + CV_KTAB);
    float*    s_o  = (float*)(smem + CV_SO);
    float*    t_o  = (float*)(smem + CV_TO);

    if (tid < 256) {
        int o = m0 + tid;
        float s = qg[o] * rsqrtf(qv[o] + 1e-5f);
        s_o[tid] = s;
        t_o[tid] = qb[o] - qm[o] * s;
    }
    for (int k = tid; k < 2304; k += 512) {
        int i = k / 9, r = k - i * 9;
        int ky = r / 3, kx = r - ky * 3;
        ktab[k] = (uint16_t)((i << 4) | (ky << 2) | kx);
    }
    __syncthreads();

    const int gl    = tid & 127;
    const int kslot = tid >> 7;            // owns 32 k per chunk
    int p_xo, p_iy, p_ix;
    {
        int g = n0 + gl;
        int b = g / HW, hw = g - b * HW;
        int y = hw / WCC, xx = hw - y * WCC;
        p_xo = b * (CDIM * TJ);
        p_iy = 3 * y - 1;
        p_ix = 3 * xx - 1;
    }

    const uint32_t a_row  = (lane & 7) + ((lane >> 3) & 1) * 8;
    const uint32_t a_koff = (lane >> 4) * 8;
    const uint32_t b_row  = (lane & 7) + (lane >> 4) * 8;
    const uint32_t b_koff = ((lane >> 3) & 1) * 8;

    __align__(16) unsigned short pv[32];

    auto cpW = [&](int kc, int bsel) {
        uint32_t dstb = sbase + CV_WBUF + (uint32_t)bsel * 69632;
#pragma unroll
        for (int t = 0; t < 8; t++) {
            int e = tid + t * 512;
            int row = e >> 4, col = e & 15;
            CP_ASYNC16(dstb + ((uint32_t)row * 136 + col * 8) * 2,
                       (const void*)(g_qwh + (size_t)(m0 + row) * 2304 + kc + col * 8));
        }
    };
    auto gatherP = [&](int kc) {
        const int kb = kc + kslot * 32;
#pragma unroll
        for (int t = 0; t < 32; t++) {
            uint32_t kt = ktab[kb + t];
            int i = kt >> 4, ky = (kt >> 2) & 3, kx = kt & 3;
            int iy = p_iy + ky, ix = p_ix + kx;
            unsigned short v = 0;
            if ((unsigned)iy < (unsigned)TDIM && (unsigned)ix < (unsigned)JDIM)
                v = *(const unsigned short*)&g_xn[p_xo + i * TJ + iy * JDIM + ix];
            pv[t] = v;
        }
    };
    auto storeP = [&](int bsel) {
        char* pb2 = smem + CV_PBUF + bsel * 34816;
        uint32_t off = ((uint32_t)gl * 136 + kslot * 32) * 2;
#pragma unroll
        for (int j = 0; j < 4; j++)
            *(uint4*)(pb2 + off + j * 16) = ((const uint4*)pv)[j];
    };

    float d[4][4][4];
#pragma unroll
    for (int mi = 0; mi < 4; mi++)
#pragma unroll
        for (int nf = 0; nf < 4; nf++)
#pragma unroll
            for (int q = 0; q < 4; q++) d[mi][nf][q] = 0.f;

    cpW(0, 0); CP_COMMIT();
    gatherP(0); storeP(0);

    for (int c = 0; c < 18; c++) {
        if (c < 17) {
            cpW((c + 1) * 128, (c + 1) & 1); CP_COMMIT();
            gatherP((c + 1) * 128);
            CP_WAIT1();
        } else {
            CP_WAIT0();
        }
        __syncthreads();

        const uint32_t wsb = sbase + CV_WBUF + (uint32_t)(c & 1) * 69632;
        const uint32_t psb = sbase + CV_PBUF + (uint32_t)(c & 1) * 34816;
#pragma unroll
        for (int ks = 0; ks < 8; ks++) {
            const int k0 = ks * 16;
            uint32_t b0[4], b1[4];
            LDM_X4(b0, psb + (((uint32_t)(wx * 32)      + b_row) * 136 + k0 + b_koff) * 2);
            LDM_X4(b1, psb + (((uint32_t)(wx * 32 + 16) + b_row) * 136 + k0 + b_koff) * 2);
            uint32_t a[4][4];
#pragma unroll
            for (int mi = 0; mi < 4; mi++)
                LDM_X4(a[mi], wsb + (((uint32_t)(wy * 64 + mi * 16) + a_row) * 136
                                      + k0 + a_koff) * 2);
#pragma unroll
            for (int mi = 0; mi < 4; mi++) {
                MMA16816(d[mi][0], a[mi], b0[0], b0[1]);
                MMA16816(d[mi][1], a[mi], b0[2], b0[3]);
                MMA16816(d[mi][2], a[mi], b1[0], b1[1]);
                MMA16816(d[mi][3], a[mi], b1[2], b1[3]);
            }
        }
        if (c < 17) storeP((c + 1) & 1);
        __syncthreads();
    }

    float* stage = (float*)(smem + CV_STAGE);
    const int tpart = blockIdx.x;
#pragma unroll
    for (int h = 0; h < 2; h++) {
        if ((wy >> 1) == h) {
            int r = lane >> 2, c2 = (lane & 3) * 2;
#pragma unroll
            for (int mi = 0; mi < 4; mi++) {
                int row = wy * 64 + mi * 16 + r - 128 * h;
#pragma unroll
                for (int nf = 0; nf < 4; nf++) {
                    int col = wx * 32 + nf * 8 + c2;
                    stage[col * 129 + row]           = d[mi][nf][0];
                    stage[(col + 1) * 129 + row]     = d[mi][nf][1];
                    stage[col * 129 + row + 8]       = d[mi][nf][2];
                    stage[(col + 1) * 129 + row + 8] = d[mi][nf][3];
                }
            }
        }
        __syncthreads();
        for (int e = tid; e < 16384; e += 512) {
            int gl2 = e >> 7, cl = e & 127;
            int g = n0 + gl2;
            int b = g / HW, hw = g - b * HW;
            int ch = 128 * h + cl;
            float v = stage[gl2 * 129 + cl] * s_o[ch] + t_o[ch];
            g_qkv[(((size_t)b * 3 + tpart) * HW + hw) * CDIM + ch]
                = __float2half(gelu_exact(v));
        }
        __syncthreads();
    }
}

// ---------------------------------------------------------------------------
// K2: attention on HMMA (unchanged from round 11)
// ---------------------------------------------------------------------------
#define AT_STR  40
#define AT_Q    0
#define AT_K    21760
#define AT_V    43520
#define AT_TOT  65280

__global__ void __launch_bounds__(544) k_attn_mma()
{
    extern __shared__ char smem[];
    const uint32_t sbase = smem_u32(smem);
    __half* qs = (__half*)(smem + AT_Q);
    __half* ks = (__half*)(smem + AT_K);
    __half* vs = (__half*)(smem + AT_V);

    const int bh = blockIdx.x;
    const int b = bh >> 3, h = bh & 7;
    const int tid = threadIdx.x;
    const int wid = tid >> 5, lane = tid & 31;

    const __half* qg = g_qkv + (((size_t)b * 3 + 0) * HW) * CDIM + h * 32;
    const __half* kg = g_qkv + (((size_t)b * 3 + 1) * HW) * CDIM + h * 32;
    const __half* vg = g_qkv + (((size_t)b * 3 + 2) * HW) * CDIM + h * 32;

    const __half2 sc2 = __float2half2_rn(0.17677669529663687f);
    for (int e = tid; e < 272 * 4; e += 544) {
        int r = e >> 2, d8 = (e & 3) * 8;
        uint4 q4 = make_uint4(0, 0, 0, 0), k4 = q4, v4 = q4;
        if (r < HW) {
            size_t off = (size_t)r * CDIM + d8;
            q4 = *(const uint4*)(qg + off);
            k4 = *(const uint4*)(kg + off);
            v4 = *(const uint4*)(vg + off);
        }
        __half2* qh = (__half2*)&q4;
#pragma unroll
        for (int j = 0; j < 4; j++) qh[j] = __hmul2(qh[j], sc2);
        *(uint4*)(qs + r * AT_STR + d8) = q4;
        *(uint4*)(ks + r * AT_STR + d8) = k4;
        *(uint4*)(vs + r * AT_STR + d8) = v4;
    }
    __syncthreads();

    const int m0 = wid * 16;
    const uint32_t a_row  = (lane & 7) + ((lane >> 3) & 1) * 8;
    const uint32_t a_koff = (lane >> 4) * 8;
    const uint32_t b_row  = (lane & 7) + (lane >> 4) * 8;
    const uint32_t b_koff = ((lane >> 3) & 1) * 8;
    const uint32_t v_row  = (lane & 7) + ((lane >> 3) & 1) * 8;
    const uint32_t v_col  = (lane >> 4) * 8;

    const uint32_t qs_base = sbase + AT_Q;
    const uint32_t ks_base = sbase + AT_K;
    const uint32_t vs_base = sbase + AT_V;

    uint32_t qa[2][4];
    LDM_X4(qa[0], qs_base + (((uint32_t)m0 + a_row) * AT_STR + 0  + a_koff) * 2);
    LDM_X4(qa[1], qs_base + (((uint32_t)m0 + a_row) * AT_STR + 16 + a_koff) * 2);

    float o[4][4];
#pragma unroll
    for (int nt = 0; nt < 4; nt++)
#pragma unroll
        for (int q = 0; q < 4; q++) o[nt][q] = 0.f;
    float mr = -1e30f, mr8 = -1e30f, lr = 0.f, lr8 = 0.f;

    const int c2 = (lane & 3) * 2;

    for (int jt = 0; jt < 17; jt++) {
        float s0[4] = {0.f, 0.f, 0.f, 0.f};
        float s1[4] = {0.f, 0.f, 0.f, 0.f};
        {
            uint32_t bb[4];
            LDM_X4(bb, ks_base + (((uint32_t)(jt * 16) + b_row) * AT_STR + 0 + b_koff) * 2);
            MMA16816(s0, qa[0], bb[0], bb[1]);
            MMA16816(s1, qa[0], bb[2], bb[3]);
            LDM_X4(bb, ks_base + (((uint32_t)(jt * 16) + b_row) * AT_STR + 16 + b_koff) * 2);
            MMA16816(s0, qa[1], bb[0], bb[1]);
            MMA16816(s1, qa[1], bb[2], bb[3]);
        }
        if (jt == 16) {
            if (256 + c2     >= HW) { s0[0] = -1e30f; s0[2] = -1e30f; }
            if (256 + c2 + 1 >= HW) { s0[1] = -1e30f; s0[3] = -1e30f; }
            if (256 + c2 + 8 >= HW) { s1[0] = -1e30f; s1[2] = -1e30f; }
            if (256 + c2 + 9 >= HW) { s1[1] = -1e30f; s1[3] = -1e30f; }
        }

        float cmr  = fmaxf(fmaxf(s0[0], s0[1]), fmaxf(s1[0], s1[1]));
        float cmr8 = fmaxf(fmaxf(s0[2], s0[3]), fmaxf(s1[2], s1[3]));
        cmr  = fmaxf(cmr,  __shfl_xor_sync(0xffffffffu, cmr, 1));
        cmr  = fmaxf(cmr,  __shfl_xor_sync(0xffffffffu, cmr, 2));
        cmr8 = fmaxf(cmr8, __shfl_xor_sync(0xffffffffu, cmr8, 1));
        cmr8 = fmaxf(cmr8, __shfl_xor_sync(0xffffffffu, cmr8, 2));
        float mnr  = fmaxf(mr, cmr);
        float mnr8 = fmaxf(mr8, cmr8);
        float corr  = __expf(mr - mnr);
        float corr8 = __expf(mr8 - mnr8);
        float p00 = __expf(s0[0] - mnr),  p01 = __expf(s0[1] - mnr);
        float p02 = __expf(s1[0] - mnr),  p03 = __expf(s1[1] - mnr);
        float p80 = __expf(s0[2] - mnr8), p81 = __expf(s0[3] - mnr8);
        float p82 = __expf(s1[2] - mnr8), p83 = __expf(s1[3] - mnr8);
        float ps  = p00 + p01 + p02 + p03;
        float ps8 = p80 + p81 + p82 + p83;
        ps  += __shfl_xor_sync(0xffffffffu, ps, 1);
        ps  += __shfl_xor_sync(0xffffffffu, ps, 2);
        ps8 += __shfl_xor_sync(0xffffffffu, ps8, 1);
        ps8 += __shfl_xor_sync(0xffffffffu, ps8, 2);
        lr  = lr  * corr  + ps;
        lr8 = lr8 * corr8 + ps8;
        mr = mnr; mr8 = mnr8;

        uint32_t pa[4];
        pa[0] = h2_to_u32(__floats2half2_rn(p00, p01));
        pa[1] = h2_to_u32(__floats2half2_rn(p80, p81));
        pa[2] = h2_to_u32(__floats2half2_rn(p02, p03));
        pa[3] = h2_to_u32(__floats2half2_rn(p82, p83));

#pragma unroll
        for (int nt = 0; nt < 4; nt++) {
            o[nt][0] *= corr;  o[nt][1] *= corr;
            o[nt][2] *= corr8; o[nt][3] *= corr8;
        }

        {
            uint32_t vb[4];
            LDM_X4_T(vb, vs_base + (((uint32_t)(jt * 16) + v_row) * AT_STR + 0 + v_col) * 2);
            MMA16816(o[0], pa, vb[0], vb[1]);
            MMA16816(o[1], pa, vb[2], vb[3]);
            LDM_X4_T(vb, vs_base + (((uint32_t)(jt * 16) + v_row) * AT_STR + 16 + v_col) * 2);
            MMA16816(o[2], pa, vb[0], vb[1]);
            MMA16816(o[3], pa, vb[2], vb[3]);
        }
    }

    const int r0 = m0 + (lane >> 2);
    float invr  = 1.f / lr;
    float invr8 = 1.f / lr8;
    if (r0 < HW) {
        __half* og = g_att + ((size_t)b * HW + r0) * CDIM + h * 32 + c2;
#pragma unroll
        for (int nt = 0; nt < 4; nt++)
            *(__half2*)(og + nt * 8) = __floats2half2_rn(o[nt][0] * invr, o[nt][1] * invr);
    }
    if (r0 + 8 < HW) {
        __half* og = g_att + ((size_t)b * HW + r0 + 8) * CDIM + h * 32 + c2;
#pragma unroll
        for (int nt = 0; nt < 4; nt++)
            *(__half2*)(og + nt * 8) = __floats2half2_rn(o[nt][2] * invr8, o[nt][3] * invr8);
    }
}

// ---------------------------------------------------------------------------
// K3: proj on HMMA — FULL weight matrix resident in smem, zero mid-loop syncs
// ---------------------------------------------------------------------------
#define PJ_PB    0
#define PJ_O00   1024
#define PJ_O01   1536
#define PJ_O10   2048
#define PJ_O11   2560
#define PJ_WXT   3072
#define PJ_WYT   3584
#define PJ_PS    4096                    // [128][264] half = 67584
#define PJ_WS    71680                   // [256][264] half = 135168
#define PJ_STAGE PJ_PS
#define PJ_TOT   206848

__global__ void __launch_bounds__(512, 1) k_proj_mma(
    const float* __restrict__ pb,
    const float* __restrict__ x, float* __restrict__ x1)
{
    extern __shared__ char smem[];
    const uint32_t sbase = smem_u32(smem);
    const int tid = threadIdx.x;
    const int wid = tid >> 5, lane = tid & 31;
    const int wy = wid & 3, wx = wid >> 2;

    const int b  = blockIdx.x / 17;
    const int p0 = (blockIdx.x - b * 17) * 128;

    float* pbs = (float*)(smem + PJ_PB);
    int*   o00 = (int*)(smem + PJ_O00);
    int*   o01 = (int*)(smem + PJ_O01);
    int*   o10 = (int*)(smem + PJ_O10);
    int*   o11 = (int*)(smem + PJ_O11);
    float* wxs = (float*)(smem + PJ_WXT);
    float* wys = (float*)(smem + PJ_WYT);

    // stage ENTIRE W (256x256 fp16) via cp.async, overlapped with setup+gather
    {
        uint32_t ws = sbase + PJ_WS;
#pragma unroll
        for (int t = 0; t < 16; t++) {
            int e = tid + t * 512;
            int row = e >> 5, col = e & 31;
            CP_ASYNC16(ws + ((uint32_t)row * 264 + col * 8) * 2,
                       (const void*)(g_pwh + (size_t)row * 256 + col * 8));
        }
        CP_COMMIT();
    }

    if (tid < 128) {
        int p = p0 + tid;
        int t = p / JDIM, j = p - t * JDIM;
        float sy = (t + 0.5f) * (43.0f / 128.0f) - 0.5f;
        sy = fminf(fmaxf(sy, 0.f), 42.f);
        int y0 = (int)sy;
        int y1 = min(y0 + 1, 42);
        float fy = sy - y0;
        float sx = (j + 0.5f) * (6.0f / 17.0f) - 0.5f;
        sx = fminf(fmaxf(sx, 0.f), 5.f);
        int x0 = (int)sx;
        int x1i = min(x0 + 1, 5);
        float fx = sx - x0;
        o00[tid] = (y0 * WCC + x0) * CDIM;
        o01[tid] = (y0 * WCC + x1i) * CDIM;
        o10[tid] = (y1 * WCC + x0) * CDIM;
        o11[tid] = (y1 * WCC + x1i) * CDIM;
        wxs[tid] = fx;
        wys[tid] = fy;
    } else if (tid < 384) {
        pbs[tid - 128] = pb[tid - 128];
    }
    __syncthreads();

    const __half* abase = g_att + (size_t)b * HW * CDIM;
    for (int e = tid; e < 32768; e += 512) {
        int k = e & 255, gl = e >> 8;
        const __half* bp = abase + k;
        float fx = wxs[gl], fy = wys[gl];
        float a00 = __half2float(bp[o00[gl]]);
        float a01 = __half2float(bp[o01[gl]]);
        float a10 = __half2float(bp[o10[gl]]);
        float a11 = __half2float(bp[o11[gl]]);
        float v = (a00 * (1.f - fx) + a01 * fx) * (1.f - fy)
                + (a10 * (1.f - fx) + a11 * fx) * fy;
        *(__half*)(smem + PJ_PS + ((uint32_t)gl * 264 + k) * 2) = __float2half(v);
    }
    CP_WAIT0();
    __syncthreads();

    const uint32_t a_row  = (lane & 7) + ((lane >> 3) & 1) * 8;
    const uint32_t a_koff = (lane >> 4) * 8;
    const uint32_t b_row  = (lane & 7) + (lane >> 4) * 8;
    const uint32_t b_koff = ((lane >> 3) & 1) * 8;
    const uint32_t ps_base = sbase + PJ_PS;
    const uint32_t ws_base = sbase + PJ_WS;

    float d[4][4][4];
#pragma unroll
    for (int mi = 0; mi < 4; mi++)
#pragma unroll
        for (int nf = 0; nf < 4; nf++)
#pragma unroll
            for (int q = 0; q < 4; q++) d[mi][nf][q] = 0.f;

    // full K=256 MMA stream — no syncs, no waits
#pragma unroll 4
    for (int k0 = 0; k0 < 256; k0 += 16) {
        uint32_t b0[4], b1[4];
        LDM_X4(b0, ps_base + (((uint32_t)(wx * 32)      + b_row) * 264 + k0 + b_koff) * 2);
        LDM_X4(b1, ps_base + (((uint32_t)(wx * 32 + 16) + b_row) * 264 + k0 + b_koff) * 2);
        uint32_t a[4][4];
#pragma unroll
        for (int mi = 0; mi < 4; mi++)
            LDM_X4(a[mi], ws_base + (((uint32_t)(wy * 64 + mi * 16) + a_row) * 264
                                      + k0 + a_koff) * 2);
#pragma unroll
        for (int mi = 0; mi < 4; mi++) {
            MMA16816(d[mi][0], a[mi], b0[0], b0[1]);
            MMA16816(d[mi][1], a[mi], b0[2], b0[3]);
            MMA16816(d[mi][2], a[mi], b1[0], b1[1]);
            MMA16816(d[mi][3], a[mi], b1[2], b1[3]);
        }
    }
    __syncthreads();

    float* stage = (float*)(smem + PJ_STAGE);
#pragma unroll
    for (int h = 0; h < 2; h++) {
        if ((wy >> 1) == h) {
            int r = lane >> 2, c2 = (lane & 3) * 2;
#pragma unroll
            for (int mi = 0; mi < 4; mi++) {
                int row = wy * 64 + mi * 16 + r - 128 * h;
#pragma unroll
                for (int nf = 0; nf < 4; nf++) {
                    int col = wx * 32 + nf * 8 + c2;
                    stage[col * 129 + row]           = d[mi][nf][0];
                    stage[(col + 1) * 129 + row]     = d[mi][nf][1];
                    stage[col * 129 + row + 8]       = d[mi][nf][2];
                    stage[(col + 1) * 129 + row + 8] = d[mi][nf][3];
                }
            }
        }
        __syncthreads();
        for (int e = tid; e < 16384; e += 512) {
            int gl = e & 127, cl = e >> 7;
            int ch = 128 * h + cl;
            size_t idx = ((size_t)b * CDIM + ch) * TJ + p0 + gl;
            x1[idx] = x[idx] + stage[gl * 129 + cl] + pbs[ch];
        }
        __syncthreads();
    }
}

// ---------------------------------------------------------------------------
// K4: fused MLP on HMMA, big-tile (unchanged from round 11)
// ---------------------------------------------------------------------------
#define M2_SN   0
#define M2_TN   1024
#define M2_S2   2048
#define M2_T2   3072
#define M2_S1   4096
#define M2_T1   4608
#define M2_XS   5120
#define M2_HS   72704
#define M2_WB   107520
#define M2_ST   M2_XS
#define M2_TOT  181248

__global__ void __launch_bounds__(512, 1) k_mlp_mma2(
    const float* x1,
    const float* __restrict__ b1g, const float* __restrict__ b1b,
    const float* __restrict__ b1m, const float* __restrict__ b1v,
    const float* __restrict__ fb1,
    const float* __restrict__ b2g, const float* __restrict__ b2b,
    const float* __restrict__ b2m, const float* __restrict__ b2v,
    const float* __restrict__ fb2,
    const float* __restrict__ n2g, const float* __restrict__ n2b,
    const float* __restrict__ n2m, const float* __restrict__ n2v,
    float* out)
{
    extern __shared__ char smem[];
    const uint32_t sbase = smem_u32(smem);
    const int tid = threadIdx.x;
    const int wid = tid >> 5, lane = tid & 31;
    const int wy = wid & 3, wx = wid >> 2;

    const int b  = blockIdx.x / 17;
    const int p0 = (blockIdx.x - b * 17) * 128;

    float* sn = (float*)(smem + M2_SN);
    float* tn = (float*)(smem + M2_TN);
    float* s2 = (float*)(smem + M2_S2);
    float* t2 = (float*)(smem + M2_T2);
    float* s1 = (float*)(smem + M2_S1);
    float* t1 = (float*)(smem + M2_T1);

    auto cpW1 = [&](int nt, int c, int bsel) {
        uint32_t dstb = sbase + M2_WB + (uint32_t)bsel * 36864;
        const __half* src = g_w1h + nt * 32768 + c * 64;
#pragma unroll
        for (int t = 0; t < 2; t++) {
            int e = tid + t * 512;
            int row = e >> 3, col = e & 7;
            CP_ASYNC16(dstb + ((uint32_t)row * 72 + col * 8) * 2,
                       (const void*)(src + (size_t)row * 256 + col * 8));
        }
    };
    auto cpW2 = [&](int nt, int c, int bsel) {
        uint32_t dstb = sbase + M2_WB + (uint32_t)bsel * 36864;
        const __half* src = g_w2h + nt * 32768 + c * 64;
#pragma unroll
        for (int t = 0; t < 4; t++) {
            int e = tid + t * 512;
            int row = e >> 3, col = e & 7;
            CP_ASYNC16(dstb + ((uint32_t)row * 72 + col * 8) * 2,
                       (const void*)(src + (size_t)row * 128 + col * 8));
        }
    };

    cpW1(0, 0, 0); CP_COMMIT();

    if (tid < 256) {
        float s = n2g[tid] * rsqrtf(n2v[tid] + 1e-5f);
        sn[tid] = s;
        tn[tid] = n2b[tid] - n2m[tid] * s;
    } else {
        int c = tid - 256;
        float s = b2g[c] * rsqrtf(b2v[c] + 1e-5f);
        s2[c] = s;
        t2[c] = b2b[c] - b2m[c] * s + fb2[c] * s;
    }
    __syncthreads();

    const float* xb = x1 + (size_t)b * CDIM * TJ;
    for (int e = tid; e < 32768; e += 512) {
        int i = e & 255, p = e >> 8;
        float v = xb[(size_t)i * TJ + p0 + p] * sn[i] + tn[i];
        *(__half*)(smem + M2_XS + ((uint32_t)p * 264 + i) * 2) = __float2half(v);
    }

    const uint32_t a_row  = (lane & 7) + ((lane >> 3) & 1) * 8;
    const uint32_t a_koff = (lane >> 4) * 8;
    const uint32_t b_row  = (lane & 7) + (lane >> 4) * 8;
    const uint32_t b_koff = ((lane >> 3) & 1) * 8;

    const uint32_t xs_base = sbase + M2_XS;
    const uint32_t hs_base = sbase + M2_HS;

    float d2[4][4][4];
#pragma unroll
    for (int mi = 0; mi < 4; mi++)
#pragma unroll
        for (int nf = 0; nf < 4; nf++)
#pragma unroll
            for (int q = 0; q < 4; q++) d2[mi][nf][q] = 0.f;

    int buf = 0;

    for (int nt = 0; nt < 8; nt++) {
        if (tid < 128) {
            int j = nt * 128 + tid;
            float s = b1g[j] * rsqrtf(b1v[j] + 1e-5f);
            s1[tid] = s;
            t1[tid] = b1b[j] - b1m[j] * s + fb1[j] * s;
        }

        float d1[2][4][4];
#pragma unroll
        for (int mi = 0; mi < 2; mi++)
#pragma unroll
            for (int nf = 0; nf < 4; nf++)
#pragma unroll
                for (int q = 0; q < 4; q++) d1[mi][nf][q] = 0.f;

        for (int c = 0; c < 4; c++) {
            if (c < 3) cpW1(nt, c + 1, buf ^ 1);
            else       cpW2(nt, 0, buf ^ 1);
            CP_COMMIT(); CP_WAIT1();
            __syncthreads();

            const uint32_t wsb = sbase + M2_WB + (uint32_t)buf * 36864;
#pragma unroll
            for (int ks = 0; ks < 4; ks++) {
                const int k0 = ks * 16;
                const int kg = c * 64 + k0;
                uint32_t b0[4], b1[4];
                LDM_X4(b0, xs_base + (((uint32_t)(wx * 32)      + b_row) * 264 + kg + b_koff) * 2);
                LDM_X4(b1, xs_base + (((uint32_t)(wx * 32 + 16) + b_row) * 264 + kg + b_koff) * 2);
                uint32_t a[2][4];
#pragma unroll
                for (int mi = 0; mi < 2; mi++)
                    LDM_X4(a[mi], wsb + (((uint32_t)(wy * 32 + mi * 16) + a_row) * 72
                                          + k0 + a_koff) * 2);
#pragma unroll
                for (int mi = 0; mi < 2; mi++) {
                    MMA16816(d1[mi][0], a[mi], b0[0], b0[1]);
                    MMA16816(d1[mi][1], a[mi], b0[2], b0[3]);
                    MMA16816(d1[mi][2], a[mi], b1[0], b1[1]);
                    MMA16816(d1[mi][3], a[mi], b1[2], b1[3]);
                }
            }
            buf ^= 1;
            __syncthreads();
        }

        {
            int r = lane >> 2, c2l = (lane & 3) * 2;
#pragma unroll
            for (int mi = 0; mi < 2; mi++) {
                int j = wy * 32 + mi * 16 + r;
                float sj0 = s1[j],     tj0 = t1[j];
                float sj8 = s1[j + 8], tj8 = t1[j + 8];
#pragma unroll
                for (int nf = 0; nf < 4; nf++) {
                    int pos = wx * 32 + nf * 8 + c2l;
                    __half* h0 = (__half*)(smem + M2_HS + ((uint32_t)pos * 136 + j) * 2);
                    __half* h1 = (__half*)(smem + M2_HS + ((uint32_t)(pos + 1) * 136 + j) * 2);
                    h0[0] = __float2half(gelu_exact(d1[mi][nf][0] * sj0 + tj0));
                    h1[0] = __float2half(gelu_exact(d1[mi][nf][1] * sj0 + tj0));
                    h0[8] = __float2half(gelu_exact(d1[mi][nf][2] * sj8 + tj8));
                    h1[8] = __float2half(gelu_exact(d1[mi][nf][3] * sj8 + tj8));
                }
            }
        }

        for (int c = 0; c < 2; c++) {
            if (c == 0)        { cpW2(nt, 1, buf ^ 1); CP_COMMIT(); CP_WAIT1(); }
            else if (nt < 7)   { cpW1(nt + 1, 0, buf ^ 1); CP_COMMIT(); CP_WAIT1(); }
            else               { CP_WAIT0(); }
            __syncthreads();

            const uint32_t wsb = sbase + M2_WB + (uint32_t)buf * 36864;
#pragma unroll
            for (int ks = 0; ks < 4; ks++) {
                const int k0 = ks * 16;
                const int kg = c * 64 + k0;
                uint32_t b0[4], b1[4];
                LDM_X4(b0, hs_base + (((uint32_t)(wx * 32)      + b_row) * 136 + kg + b_koff) * 2);
                LDM_X4(b1, hs_base + (((uint32_t)(wx * 32 + 16) + b_row) * 136 + kg + b_koff) * 2);
                uint32_t a[4][4];
#pragma unroll
                for (int mi = 0; mi < 4; mi++)
                    LDM_X4(a[mi], wsb + (((uint32_t)(wy * 64 + mi * 16) + a_row) * 72
                                          + k0 + a_koff) * 2);
#pragma unroll
                for (int mi = 0; mi < 4; mi++) {
                    MMA16816(d2[mi][0], a[mi], b0[0], b0[1]);
                    MMA16816(d2[mi][1], a[mi], b0[2], b0[3]);
                    MMA16816(d2[mi][2], a[mi], b1[0], b1[1]);
                    MMA16816(d2[mi][3], a[mi], b1[2], b1[3]);
                }
            }
            buf ^= 1;
            __syncthreads();
        }
    }

    float* stage = (float*)(smem + M2_ST);
#pragma unroll
    for (int h = 0; h < 2; h++) {
        if ((wy >> 1) == h) {
            int r = lane >> 2, c2l = (lane & 3) * 2;
#pragma unroll
            for (int mi = 0; mi < 4; mi++) {
                int row = wy * 64 + mi * 16 + r - 128 * h;
#pragma unroll
                for (int nf = 0; nf < 4; nf++) {
                    int col = wx * 32 + nf * 8 + c2l;
                    stage[col * 129 + row]           = d2[mi][nf][0];
                    stage[(col + 1) * 129 + row]     = d2[mi][nf][1];
                    stage[col * 129 + row + 8]       = d2[mi][nf][2];
                    stage[(col + 1) * 129 + row + 8] = d2[mi][nf][3];
                }
            }
        }
        __syncthreads();
        for (int e = tid; e < 16384; e += 512) {
            int gl = e & 127, cl = e >> 7;
            int ch = 128 * h + cl;
            size_t idx = ((size_t)b * CDIM + ch) * TJ + p0 + gl;
            out[idx] = x1[idx] + stage[gl * 129 + cl] * s2[ch] + t2[ch];
        }
        __syncthreads();
    }
}

// ---------------------------------------------------------------------------
extern "C" void kernel_launch(void* const* d_in, const int* in_sizes, int n_in,
                              void* d_out, int out_size)
{
    const float* x    = (const float*)d_in[0];
    const float* n1g  = (const float*)d_in[1];
    const float* n1b  = (const float*)d_in[2];
    const float* n1m  = (const float*)d_in[3];
    const float* n1v  = (const float*)d_in[4];
    const float* qkvw = (const float*)d_in[5];
    const float* qg   = (const float*)d_in[6];
    const float* qb   = (const float*)d_in[7];
    const float* qm   = (const float*)d_in[8];
    const float* qv   = (const float*)d_in[9];
    const float* pw   = (const float*)d_in[10];
    const float* pb   = (const float*)d_in[11];
    const float* n2g  = (const float*)d_in[12];
    const float* n2b  = (const float*)d_in[13];
    const float* n2m  = (const float*)d_in[14];
    const float* n2v  = (const float*)d_in[15];
    const float* w1   = (const float*)d_in[16];
    const float* fb1  = (const float*)d_in[17];
    const float* b1g  = (const float*)d_in[18];
    const float* b1b  = (const float*)d_in[19];
    const float* b1m  = (const float*)d_in[20];
    const float* b1v  = (const float*)d_in[21];
    const float* w2   = (const float*)d_in[22];
    const float* fb2  = (const float*)d_in[23];
    const float* b2g  = (const float*)d_in[24];
    const float* b2b  = (const float*)d_in[25];
    const float* b2m  = (const float*)d_in[26];
    const float* b2v  = (const float*)d_in[27];
    float* out = (float*)d_out;

    cudaFuncSetAttribute(k_attn_mma, cudaFuncAttributeMaxDynamicSharedMemorySize, AT_TOT);
    cudaFuncSetAttribute(k_conv_mma, cudaFuncAttributeMaxDynamicSharedMemorySize, CV_TOT);
    cudaFuncSetAttribute(k_proj_mma, cudaFuncAttributeMaxDynamicSharedMemorySize, PJ_TOT);
    cudaFuncSetAttribute(k_mlp_mma2, cudaFuncAttributeMaxDynamicSharedMemorySize, M2_TOT);

    k_prep_all<<<16384 + 4608, 512>>>(w1, w2, qkvw, pw, x, n1g, n1b, n1m, n1v);
    k_conv_mma<<<dim3(3, 129), 512, CV_TOT>>>(qg, qb, qm, qv);
    k_attn_mma<<<512, 544, AT_TOT>>>();
    k_proj_mma<<<1088, 512, PJ_TOT>>>(pb, x, out);
    k_mlp_mma2<<<1088, 512, M2_TOT>>>(out,
                                      b1g, b1b, b1m, b1v, fb1,
                                      b2g, b2b, b2m, b2v, fb2,
                                      n2g, n2b, n2m, n2v, out);
}

// round 14
// speedup vs baseline: 1.0045x; 1.0045x over previous
#include <cuda_runtime.h>
#include <cuda_fp16.h>
#include <math.h>
#include <stdint.h>

#define BATCH 64
#define CDIM 256
#define TDIM 128
#define JDIM 17
#define TJ 2176     // TDIM*JDIM
#define HCC 43
#define WCC 6
#define HW 258      // HCC*WCC
#define HIDDEN 1024

// scratch (static __device__ globals per harness rules)
__device__ __half g_qkv[(size_t)3 * BATCH * HW * CDIM];  // fp16 [b][t][hw][c]
__device__ __half g_att[(size_t)BATCH * HW * CDIM];      // fp16 [b][hw][c]
__device__ __half g_y[(size_t)BATCH * HW * CDIM];        // proj output (compressed grid)
__device__ __half g_xn[(size_t)BATCH * CDIM * TJ];       // n1bn(x) fp16
// fp16 weights
__device__ __half g_w1h[8 * 32768];            // W1 per-tile [128 j][256 i]
__device__ __half g_w2h[8 * 32768];            // W2 per-tile [256 c][128 j]
__device__ __half g_qwh[768 * 2304];           // qkv conv weight row-major
__device__ __half g_pwh[256 * 256];            // proj weight row-major

__device__ __forceinline__ float gelu_exact(float v) {
    return 0.5f * v * (1.0f + erff(v * 0.70710678118654752f));
}

__device__ __forceinline__ uint32_t smem_u32(const void* p) {
    uint32_t a;
    asm("{ .reg .u64 t; cvta.to.shared.u64 t, %1; cvt.u32.u64 %0, t; }" : "=r"(a) : "l"(p));
    return a;
}

__device__ __forceinline__ uint32_t h2_to_u32(__half2 h) {
    return *reinterpret_cast<uint32_t*>(&h);
}

#define LDM_X4(r, addr) \
    asm volatile("ldmatrix.sync.aligned.m8n8.x4.shared.b16 {%0,%1,%2,%3}, [%4];" \
        : "=r"((r)[0]), "=r"((r)[1]), "=r"((r)[2]), "=r"((r)[3]) : "r"(addr))

#define LDM_X4_T(r, addr) \
    asm volatile("ldmatrix.sync.aligned.m8n8.x4.trans.shared.b16 {%0,%1,%2,%3}, [%4];" \
        : "=r"((r)[0]), "=r"((r)[1]), "=r"((r)[2]), "=r"((r)[3]) : "r"(addr))

#define MMA16816(d, a, b0, b1) \
    asm volatile("mma.sync.aligned.m16n8k16.row.col.f32.f16.f16.f32 " \
        "{%0,%1,%2,%3}, {%4,%5,%6,%7}, {%8,%9}, {%0,%1,%2,%3};" \
        : "+f"((d)[0]), "+f"((d)[1]), "+f"((d)[2]), "+f"((d)[3]) \
        : "r"((a)[0]), "r"((a)[1]), "r"((a)[2]), "r"((a)[3]), "r"(b0), "r"(b1))

#define CP_ASYNC16(dst, src) \
    asm volatile("cp.async.cg.shared.global [%0], [%1], 16;" :: "r"(dst), "l"(src))
#define CP_COMMIT() asm volatile("cp.async.commit_group;")
#define CP_WAIT1()  asm volatile("cp.async.wait_group 1;" ::: "memory")
#define CP_WAIT0()  asm volatile("cp.async.wait_group 0;" ::: "memory")

// ---------------------------------------------------------------------------
// K0: merged prep — blocks [0,16384): xn = n1bn(x) fp16; rest: weight convert
// ---------------------------------------------------------------------------
__global__ void __launch_bounds__(512) k_prep_all(
    const float* __restrict__ w1, const float* __restrict__ w2,
    const float* __restrict__ qkvw, const float* __restrict__ pw,
    const float* __restrict__ x,
    const float* __restrict__ n1g, const float* __restrict__ n1b,
    const float* __restrict__ n1m, const float* __restrict__ n1v)
{
    const int blk = blockIdx.x;
    if (blk < 16384) {
        __shared__ float ss, tt;
        const int c = blk & 255;
        if (threadIdx.x == 0) {
            float s = n1g[c] * rsqrtf(n1v[c] + 1e-5f);
            ss = s;
            tt = n1b[c] - n1m[c] * s;
        }
        __syncthreads();
        const float* xr = x + (size_t)blk * TJ;
        __half* xo = g_xn + (size_t)blk * TJ;
        float s = ss, t = tt;
        for (int p = threadIdx.x; p < TJ; p += 512)
            xo[p] = __float2half(xr[p] * s + t);
        return;
    }
    int idx = (blk - 16384) * 512 + threadIdx.x;
    if (idx < 262144) {
        int j = idx >> 8, i = idx & 255;
        int nt = j >> 7, jl = j & 127;
        g_w1h[(uint32_t)nt * 32768 + (uint32_t)jl * 256 + i] = __float2half(w1[idx]);
    } else if (idx < 524288) {
        int t = idx - 262144;
        int c = t >> 10, j = t & 1023;
        int nt = j >> 7, jl = j & 127;
        g_w2h[(uint32_t)nt * 32768 + (uint32_t)c * 128 + jl] = __float2half(w2[t]);
    } else if (idx < 2293760) {
        int t = idx - 524288;
        g_qwh[t] = __float2half(qkvw[t]);
    } else {
        int t = idx - 2293760;
        g_pwh[t] = __float2half(pw[t]);
    }
}

// ---------------------------------------------------------------------------
// K1: conv QKV on HMMA (unchanged from round 12)
// ---------------------------------------------------------------------------
#define CV_KTAB  0
#define CV_SO    4608
#define CV_TO    5632
#define CV_PBUF  6656
#define CV_WBUF  76288
#define CV_STAGE CV_PBUF
#define CV_TOT   215552

__global__ void __launch_bounds__(512, 1) k_conv_mma(
    const float* __restrict__ qg, const float* __restrict__ qb,
    const float* __restrict__ qm, const float* __restrict__ qv)
{
    extern __shared__ char smem[];
    const uint32_t sbase = smem_u32(smem);
    const int tid = threadIdx.x;
    const int wid = tid >> 5, lane = tid & 31;
    const int wy = wid & 3, wx = wid >> 2;

    const int m0 = blockIdx.x * 256;
    const int n0 = blockIdx.y * 128;

    uint16_t* ktab = (uint16_t*)(smem + CV_KTAB);
    float*    s_o  = (float*)(smem + CV_SO);
    float*    t_o  = (float*)(smem + CV_TO);

    if (tid < 256) {
        int o = m0 + tid;
        float s = qg[o] * rsqrtf(qv[o] + 1e-5f);
        s_o[tid] = s;
        t_o[tid] = qb[o] - qm[o] * s;
    }
    for (int k = tid; k < 2304; k += 512) {
        int i = k / 9, r = k - i * 9;
        int ky = r / 3, kx = r - ky * 3;
        ktab[k] = (uint16_t)((i << 4) | (ky << 2) | kx);
    }
    __syncthreads();

    const int gl    = tid & 127;
    const int kslot = tid >> 7;
    int p_xo, p_iy, p_ix;
    {
        int g = n0 + gl;
        int b = g / HW, hw = g - b * HW;
        int y = hw / WCC, xx = hw - y * WCC;
        p_xo = b * (CDIM * TJ);
        p_iy = 3 * y - 1;
        p_ix = 3 * xx - 1;
    }

    const uint32_t a_row  = (lane & 7) + ((lane >> 3) & 1) * 8;
    const uint32_t a_koff = (lane >> 4) * 8;
    const uint32_t b_row  = (lane & 7) + (lane >> 4) * 8;
    const uint32_t b_koff = ((lane >> 3) & 1) * 8;

    __align__(16) unsigned short pv[32];

    auto cpW = [&](int kc, int bsel) {
        uint32_t dstb = sbase + CV_WBUF + (uint32_t)bsel * 69632;
#pragma unroll
        for (int t = 0; t < 8; t++) {
            int e = tid + t * 512;
            int row = e >> 4, col = e & 15;
            CP_ASYNC16(dstb + ((uint32_t)row * 136 + col * 8) * 2,
                       (const void*)(g_qwh + (size_t)(m0 + row) * 2304 + kc + col * 8));
        }
    };
    auto gatherP = [&](int kc) {
        const int kb = kc + kslot * 32;
#pragma unroll
        for (int t = 0; t < 32; t++) {
            uint32_t kt = ktab[kb + t];
            int i = kt >> 4, ky = (kt >> 2) & 3, kx = kt & 3;
            int iy = p_iy + ky, ix = p_ix + kx;
            unsigned short v = 0;
            if ((unsigned)iy < (unsigned)TDIM && (unsigned)ix < (unsigned)JDIM)
                v = *(const unsigned short*)&g_xn[p_xo + i * TJ + iy * JDIM + ix];
            pv[t] = v;
        }
    };
    auto storeP = [&](int bsel) {
        char* pb2 = smem + CV_PBUF + bsel * 34816;
        uint32_t off = ((uint32_t)gl * 136 + kslot * 32) * 2;
#pragma unroll
        for (int j = 0; j < 4; j++)
            *(uint4*)(pb2 + off + j * 16) = ((const uint4*)pv)[j];
    };

    float d[4][4][4];
#pragma unroll
    for (int mi = 0; mi < 4; mi++)
#pragma unroll
        for (int nf = 0; nf < 4; nf++)
#pragma unroll
            for (int q = 0; q < 4; q++) d[mi][nf][q] = 0.f;

    cpW(0, 0); CP_COMMIT();
    gatherP(0); storeP(0);

    for (int c = 0; c < 18; c++) {
        if (c < 17) {
            cpW((c + 1) * 128, (c + 1) & 1); CP_COMMIT();
            gatherP((c + 1) * 128);
            CP_WAIT1();
        } else {
            CP_WAIT0();
        }
        __syncthreads();

        const uint32_t wsb = sbase + CV_WBUF + (uint32_t)(c & 1) * 69632;
        const uint32_t psb = sbase + CV_PBUF + (uint32_t)(c & 1) * 34816;
#pragma unroll
        for (int ks = 0; ks < 8; ks++) {
            const int k0 = ks * 16;
            uint32_t b0[4], b1[4];
            LDM_X4(b0, psb + (((uint32_t)(wx * 32)      + b_row) * 136 + k0 + b_koff) * 2);
            LDM_X4(b1, psb + (((uint32_t)(wx * 32 + 16) + b_row) * 136 + k0 + b_koff) * 2);
            uint32_t a[4][4];
#pragma unroll
            for (int mi = 0; mi < 4; mi++)
                LDM_X4(a[mi], wsb + (((uint32_t)(wy * 64 + mi * 16) + a_row) * 136
                                      + k0 + a_koff) * 2);
#pragma unroll
            for (int mi = 0; mi < 4; mi++) {
                MMA16816(d[mi][0], a[mi], b0[0], b0[1]);
                MMA16816(d[mi][1], a[mi], b0[2], b0[3]);
                MMA16816(d[mi][2], a[mi], b1[0], b1[1]);
                MMA16816(d[mi][3], a[mi], b1[2], b1[3]);
            }
        }
        if (c < 17) storeP((c + 1) & 1);
        __syncthreads();
    }

    float* stage = (float*)(smem + CV_STAGE);
    const int tpart = blockIdx.x;
#pragma unroll
    for (int h = 0; h < 2; h++) {
        if ((wy >> 1) == h) {
            int r = lane >> 2, c2 = (lane & 3) * 2;
#pragma unroll
            for (int mi = 0; mi < 4; mi++) {
                int row = wy * 64 + mi * 16 + r - 128 * h;
#pragma unroll
                for (int nf = 0; nf < 4; nf++) {
                    int col = wx * 32 + nf * 8 + c2;
                    stage[col * 129 + row]           = d[mi][nf][0];
                    stage[(col + 1) * 129 + row]     = d[mi][nf][1];
                    stage[col * 129 + row + 8]       = d[mi][nf][2];
                    stage[(col + 1) * 129 + row + 8] = d[mi][nf][3];
                }
            }
        }
        __syncthreads();
        for (int e = tid; e < 16384; e += 512) {
            int gl2 = e >> 7, cl = e & 127;
            int g = n0 + gl2;
            int b = g / HW, hw = g - b * HW;
            int ch = 128 * h + cl;
            float v = stage[gl2 * 129 + cl] * s_o[ch] + t_o[ch];
            g_qkv[(((size_t)b * 3 + tpart) * HW + hw) * CDIM + ch]
                = __float2half(gelu_exact(v));
        }
        __syncthreads();
    }
}

// ---------------------------------------------------------------------------
// K2: attention on HMMA (unchanged from round 12)
// ---------------------------------------------------------------------------
#define AT_STR  40
#define AT_Q    0
#define AT_K    21760
#define AT_V    43520
#define AT_TOT  65280

__global__ void __launch_bounds__(544) k_attn_mma()
{
    extern __shared__ char smem[];
    const uint32_t sbase = smem_u32(smem);
    __half* qs = (__half*)(smem + AT_Q);
    __half* ks = (__half*)(smem + AT_K);
    __half* vs = (__half*)(smem + AT_V);

    const int bh = blockIdx.x;
    const int b = bh >> 3, h = bh & 7;
    const int tid = threadIdx.x;
    const int wid = tid >> 5, lane = tid & 31;

    const __half* qg = g_qkv + (((size_t)b * 3 + 0) * HW) * CDIM + h * 32;
    const __half* kg = g_qkv + (((size_t)b * 3 + 1) * HW) * CDIM + h * 32;
    const __half* vg = g_qkv + (((size_t)b * 3 + 2) * HW) * CDIM + h * 32;

    const __half2 sc2 = __float2half2_rn(0.17677669529663687f);
    for (int e = tid; e < 272 * 4; e += 544) {
        int r = e >> 2, d8 = (e & 3) * 8;
        uint4 q4 = make_uint4(0, 0, 0, 0), k4 = q4, v4 = q4;
        if (r < HW) {
            size_t off = (size_t)r * CDIM + d8;
            q4 = *(const uint4*)(qg + off);
            k4 = *(const uint4*)(kg + off);
            v4 = *(const uint4*)(vg + off);
        }
        __half2* qh = (__half2*)&q4;
#pragma unroll
        for (int j = 0; j < 4; j++) qh[j] = __hmul2(qh[j], sc2);
        *(uint4*)(qs + r * AT_STR + d8) = q4;
        *(uint4*)(ks + r * AT_STR + d8) = k4;
        *(uint4*)(vs + r * AT_STR + d8) = v4;
    }
    __syncthreads();

    const int m0 = wid * 16;
    const uint32_t a_row  = (lane & 7) + ((lane >> 3) & 1) * 8;
    const uint32_t a_koff = (lane >> 4) * 8;
    const uint32_t b_row  = (lane & 7) + (lane >> 4) * 8;
    const uint32_t b_koff = ((lane >> 3) & 1) * 8;
    const uint32_t v_row  = (lane & 7) + ((lane >> 3) & 1) * 8;
    const uint32_t v_col  = (lane >> 4) * 8;

    const uint32_t qs_base = sbase + AT_Q;
    const uint32_t ks_base = sbase + AT_K;
    const uint32_t vs_base = sbase + AT_V;

    uint32_t qa[2][4];
    LDM_X4(qa[0], qs_base + (((uint32_t)m0 + a_row) * AT_STR + 0  + a_koff) * 2);
    LDM_X4(qa[1], qs_base + (((uint32_t)m0 + a_row) * AT_STR + 16 + a_koff) * 2);

    float o[4][4];
#pragma unroll
    for (int nt = 0; nt < 4; nt++)
#pragma unroll
        for (int q = 0; q < 4; q++) o[nt][q] = 0.f;
    float mr = -1e30f, mr8 = -1e30f, lr = 0.f, lr8 = 0.f;

    const int c2 = (lane & 3) * 2;

    for (int jt = 0; jt < 17; jt++) {
        float s0[4] = {0.f, 0.f, 0.f, 0.f};
        float s1[4] = {0.f, 0.f, 0.f, 0.f};
        {
            uint32_t bb[4];
            LDM_X4(bb, ks_base + (((uint32_t)(jt * 16) + b_row) * AT_STR + 0 + b_koff) * 2);
            MMA16816(s0, qa[0], bb[0], bb[1]);
            MMA16816(s1, qa[0], bb[2], bb[3]);
            LDM_X4(bb, ks_base + (((uint32_t)(jt * 16) + b_row) * AT_STR + 16 + b_koff) * 2);
            MMA16816(s0, qa[1], bb[0], bb[1]);
            MMA16816(s1, qa[1], bb[2], bb[3]);
        }
        if (jt == 16) {
            if (256 + c2     >= HW) { s0[0] = -1e30f; s0[2] = -1e30f; }
            if (256 + c2 + 1 >= HW) { s0[1] = -1e30f; s0[3] = -1e30f; }
            if (256 + c2 + 8 >= HW) { s1[0] = -1e30f; s1[2] = -1e30f; }
            if (256 + c2 + 9 >= HW) { s1[1] = -1e30f; s1[3] = -1e30f; }
        }

        float cmr  = fmaxf(fmaxf(s0[0], s0[1]), fmaxf(s1[0], s1[1]));
        float cmr8 = fmaxf(fmaxf(s0[2], s0[3]), fmaxf(s1[2], s1[3]));
        cmr  = fmaxf(cmr,  __shfl_xor_sync(0xffffffffu, cmr, 1));
        cmr  = fmaxf(cmr,  __shfl_xor_sync(0xffffffffu, cmr, 2));
        cmr8 = fmaxf(cmr8, __shfl_xor_sync(0xffffffffu, cmr8, 1));
        cmr8 = fmaxf(cmr8, __shfl_xor_sync(0xffffffffu, cmr8, 2));
        float mnr  = fmaxf(mr, cmr);
        float mnr8 = fmaxf(mr8, cmr8);
        float corr  = __expf(mr - mnr);
        float corr8 = __expf(mr8 - mnr8);
        float p00 = __expf(s0[0] - mnr),  p01 = __expf(s0[1] - mnr);
        float p02 = __expf(s1[0] - mnr),  p03 = __expf(s1[1] - mnr);
        float p80 = __expf(s0[2] - mnr8), p81 = __expf(s0[3] - mnr8);
        float p82 = __expf(s1[2] - mnr8), p83 = __expf(s1[3] - mnr8);
        float ps  = p00 + p01 + p02 + p03;
        float ps8 = p80 + p81 + p82 + p83;
        ps  += __shfl_xor_sync(0xffffffffu, ps, 1);
        ps  += __shfl_xor_sync(0xffffffffu, ps, 2);
        ps8 += __shfl_xor_sync(0xffffffffu, ps8, 1);
        ps8 += __shfl_xor_sync(0xffffffffu, ps8, 2);
        lr  = lr  * corr  + ps;
        lr8 = lr8 * corr8 + ps8;
        mr = mnr; mr8 = mnr8;

        uint32_t pa[4];
        pa[0] = h2_to_u32(__floats2half2_rn(p00, p01));
        pa[1] = h2_to_u32(__floats2half2_rn(p80, p81));
        pa[2] = h2_to_u32(__floats2half2_rn(p02, p03));
        pa[3] = h2_to_u32(__floats2half2_rn(p82, p83));

#pragma unroll
        for (int nt = 0; nt < 4; nt++) {
            o[nt][0] *= corr;  o[nt][1] *= corr;
            o[nt][2] *= corr8; o[nt][3] *= corr8;
        }

        {
            uint32_t vb[4];
            LDM_X4_T(vb, vs_base + (((uint32_t)(jt * 16) + v_row) * AT_STR + 0 + v_col) * 2);
            MMA16816(o[0], pa, vb[0], vb[1]);
            MMA16816(o[1], pa, vb[2], vb[3]);
            LDM_X4_T(vb, vs_base + (((uint32_t)(jt * 16) + v_row) * AT_STR + 16 + v_col) * 2);
            MMA16816(o[2], pa, vb[0], vb[1]);
            MMA16816(o[3], pa, vb[2], vb[3]);
        }
    }

    const int r0 = m0 + (lane >> 2);
    float invr  = 1.f / lr;
    float invr8 = 1.f / lr8;
    if (r0 < HW) {
        __half* og = g_att + ((size_t)b * HW + r0) * CDIM + h * 32 + c2;
#pragma unroll
        for (int nt = 0; nt < 4; nt++)
            *(__half2*)(og + nt * 8) = __floats2half2_rn(o[nt][0] * invr, o[nt][1] * invr);
    }
    if (r0 + 8 < HW) {
        __half* og = g_att + ((size_t)b * HW + r0 + 8) * CDIM + h * 32 + c2;
#pragma unroll
        for (int nt = 0; nt < 4; nt++)
            *(__half2*)(og + nt * 8) = __floats2half2_rn(o[nt][2] * invr8, o[nt][3] * invr8);
    }
}

// ---------------------------------------------------------------------------
// K3a: proj on COMPRESSED grid: Y[g][c] = W . att[g][:]  (resize commutes!)
// ---------------------------------------------------------------------------
#define PC_WS    0                       // [256][264] half = 135168
#define PC_PS    135168                  // [128][264] half = 67584
#define PC_STAGE PC_PS                   // float[128*129]=66048 (reuse)
#define PC_TOT   202752

__global__ void __launch_bounds__(512, 1) k_projc_mma()
{
    extern __shared__ char smem[];
    const uint32_t sbase = smem_u32(smem);
    const int tid = threadIdx.x;
    const int wid = tid >> 5, lane = tid & 31;
    const int wy = wid & 3, wx = wid >> 2;

    const int n0 = blockIdx.x * 128;     // global compressed position base

    // stage full W (256x256 fp16)
    {
        uint32_t ws = sbase + PC_WS;
#pragma unroll
        for (int t = 0; t < 16; t++) {
            int e = tid + t * 512;
            int row = e >> 5, col = e & 31;
            CP_ASYNC16(ws + ((uint32_t)row * 264 + col * 8) * 2,
                       (const void*)(g_pwh + (size_t)row * 256 + col * 8));
        }
    }
    // stage P: direct copy of g_att rows [n0, n0+128)
    {
        uint32_t ps = sbase + PC_PS;
#pragma unroll
        for (int t = 0; t < 8; t++) {
            int e = tid + t * 512;
            int gl = e >> 5, col = e & 31;
            CP_ASYNC16(ps + ((uint32_t)gl * 264 + col * 8) * 2,
                       (const void*)(g_att + (size_t)(n0 + gl) * 256 + col * 8));
        }
    }
    CP_COMMIT(); CP_WAIT0();
    __syncthreads();

    const uint32_t a_row  = (lane & 7) + ((lane >> 3) & 1) * 8;
    const uint32_t a_koff = (lane >> 4) * 8;
    const uint32_t b_row  = (lane & 7) + (lane >> 4) * 8;
    const uint32_t b_koff = ((lane >> 3) & 1) * 8;
    const uint32_t ps_base = sbase + PC_PS;
    const uint32_t ws_base = sbase + PC_WS;

    float d[4][4][4];
#pragma unroll
    for (int mi = 0; mi < 4; mi++)
#pragma unroll
        for (int nf = 0; nf < 4; nf++)
#pragma unroll
            for (int q = 0; q < 4; q++) d[mi][nf][q] = 0.f;

#pragma unroll 4
    for (int k0 = 0; k0 < 256; k0 += 16) {
        uint32_t b0[4], b1[4];
        LDM_X4(b0, ps_base + (((uint32_t)(wx * 32)      + b_row) * 264 + k0 + b_koff) * 2);
        LDM_X4(b1, ps_base + (((uint32_t)(wx * 32 + 16) + b_row) * 264 + k0 + b_koff) * 2);
        uint32_t a[4][4];
#pragma unroll
        for (int mi = 0; mi < 4; mi++)
            LDM_X4(a[mi], ws_base + (((uint32_t)(wy * 64 + mi * 16) + a_row) * 264
                                      + k0 + a_koff) * 2);
#pragma unroll
        for (int mi = 0; mi < 4; mi++) {
            MMA16816(d[mi][0], a[mi], b0[0], b0[1]);
            MMA16816(d[mi][1], a[mi], b0[2], b0[3]);
            MMA16816(d[mi][2], a[mi], b1[0], b1[1]);
            MMA16816(d[mi][3], a[mi], b1[2], b1[3]);
        }
    }
    __syncthreads();

    float* stage = (float*)(smem + PC_STAGE);
#pragma unroll
    for (int h = 0; h < 2; h++) {
        if ((wy >> 1) == h) {
            int r = lane >> 2, c2 = (lane & 3) * 2;
#pragma unroll
            for (int mi = 0; mi < 4; mi++) {
                int row = wy * 64 + mi * 16 + r - 128 * h;
#pragma unroll
                for (int nf = 0; nf < 4; nf++) {
                    int col = wx * 32 + nf * 8 + c2;
                    stage[col * 129 + row]           = d[mi][nf][0];
                    stage[(col + 1) * 129 + row]     = d[mi][nf][1];
                    stage[col * 129 + row + 8]       = d[mi][nf][2];
                    stage[(col + 1) * 129 + row + 8] = d[mi][nf][3];
                }
            }
        }
        __syncthreads();
        // write Y[g][c] coalesced over c  (stage is [pos 129-stride][ch])
        for (int e = tid; e < 16384; e += 512) {
            int cl = e & 127, gl = e >> 7;
            g_y[(size_t)(n0 + gl) * 256 + 128 * h + cl]
                = __float2half(stage[gl * 129 + cl]);
        }
        __syncthreads();
    }
}

// ---------------------------------------------------------------------------
// K3b: resize epilogue: x1 = x + bilinear(Y) + pb
// ---------------------------------------------------------------------------
#define RZ_O00  0
#define RZ_O01  512
#define RZ_O10  1024
#define RZ_O11  1536
#define RZ_WX   2048
#define RZ_WY   2560
#define RZ_PB   3072                    // float[256]
#define RZ_ST   4096                    // float[128*257] = 131584
#define RZ_TOT  135680

__global__ void __launch_bounds__(512) k_resize(
    const float* __restrict__ pb,
    const float* __restrict__ x, float* __restrict__ x1)
{
    extern __shared__ char smem[];
    const int tid = threadIdx.x;
    const int b  = blockIdx.y;
    const int p0 = blockIdx.x * 128;

    int*   o00 = (int*)(smem + RZ_O00);
    int*   o01 = (int*)(smem + RZ_O01);
    int*   o10 = (int*)(smem + RZ_O10);
    int*   o11 = (int*)(smem + RZ_O11);
    float* wxs = (float*)(smem + RZ_WX);
    float* wys = (float*)(smem + RZ_WY);
    float* pbs = (float*)(smem + RZ_PB);
    float* stage = (float*)(smem + RZ_ST);

    if (tid < 128) {
        int p = p0 + tid;
        int t = p / JDIM, j = p - t * JDIM;
        float sy = (t + 0.5f) * (43.0f / 128.0f) - 0.5f;
        sy = fminf(fmaxf(sy, 0.f), 42.f);
        int y0 = (int)sy;
        int y1 = min(y0 + 1, 42);
        float fy = sy - y0;
        float sx = (j + 0.5f) * (6.0f / 17.0f) - 0.5f;
        sx = fminf(fmaxf(sx, 0.f), 5.f);
        int x0 = (int)sx;
        int x1i = min(x0 + 1, 5);
        float fx = sx - x0;
        o00[tid] = (y0 * WCC + x0) * CDIM;
        o01[tid] = (y0 * WCC + x1i) * CDIM;
        o10[tid] = (y1 * WCC + x0) * CDIM;
        o11[tid] = (y1 * WCC + x1i) * CDIM;
        wxs[tid] = fx;
        wys[tid] = fy;
    } else if (tid < 384) {
        pbs[tid - 128] = pb[tid - 128];
    }
    __syncthreads();

    const __half* yb = g_y + (size_t)b * HW * CDIM;
    for (int e = tid; e < 32768; e += 512) {
        int c = e & 255, gl = e >> 8;
        const __half* bp = yb + c;
        float fx = wxs[gl], fy = wys[gl];
        float a00 = __half2float(bp[o00[gl]]);
        float a01 = __half2float(bp[o01[gl]]);
        float a10 = __half2float(bp[o10[gl]]);
        float a11 = __half2float(bp[o11[gl]]);
        stage[gl * 257 + c] = (a00 * (1.f - fx) + a01 * fx) * (1.f - fy)
                            + (a10 * (1.f - fx) + a11 * fx) * fy;
    }
    __syncthreads();

    for (int e = tid; e < 32768; e += 512) {
        int ch = e >> 7, gl = e & 127;
        size_t idx = ((size_t)b * CDIM + ch) * TJ + p0 + gl;
        x1[idx] = x[idx] + stage[gl * 257 + ch] + pbs[ch];
    }
}

// ---------------------------------------------------------------------------
// K4: fused MLP on HMMA, big-tile (unchanged from round 12)
// ---------------------------------------------------------------------------
#define M2_SN   0
#define M2_TN   1024
#define M2_S2   2048
#define M2_T2   3072
#define M2_S1   4096
#define M2_T1   4608
#define M2_XS   5120
#define M2_HS   72704
#define M2_WB   107520
#define M2_ST   M2_XS
#define M2_TOT  181248

__global__ void __launch_bounds__(512, 1) k_mlp_mma2(
    const float* x1,
    const float* __restrict__ b1g, const float* __restrict__ b1b,
    const float* __restrict__ b1m, const float* __restrict__ b1v,
    const float* __restrict__ fb1,
    const float* __restrict__ b2g, const float* __restrict__ b2b,
    const float* __restrict__ b2m, const float* __restrict__ b2v,
    const float* __restrict__ fb2,
    const float* __restrict__ n2g, const float* __restrict__ n2b,
    const float* __restrict__ n2m, const float* __restrict__ n2v,
    float* out)
{
    extern __shared__ char smem[];
    const uint32_t sbase = smem_u32(smem);
    const int tid = threadIdx.x;
    const int wid = tid >> 5, lane = tid & 31;
    const int wy = wid & 3, wx = wid >> 2;

    const int b  = blockIdx.x / 17;
    const int p0 = (blockIdx.x - b * 17) * 128;

    float* sn = (float*)(smem + M2_SN);
    float* tn = (float*)(smem + M2_TN);
    float* s2 = (float*)(smem + M2_S2);
    float* t2 = (float*)(smem + M2_T2);
    float* s1 = (float*)(smem + M2_S1);
    float* t1 = (float*)(smem + M2_T1);

    auto cpW1 = [&](int nt, int c, int bsel) {
        uint32_t dstb = sbase + M2_WB + (uint32_t)bsel * 36864;
        const __half* src = g_w1h + nt * 32768 + c * 64;
#pragma unroll
        for (int t = 0; t < 2; t++) {
            int e = tid + t * 512;
            int row = e >> 3, col = e & 7;
            CP_ASYNC16(dstb + ((uint32_t)row * 72 + col * 8) * 2,
                       (const void*)(src + (size_t)row * 256 + col * 8));
        }
    };
    auto cpW2 = [&](int nt, int c, int bsel) {
        uint32_t dstb = sbase + M2_WB + (uint32_t)bsel * 36864;
        const __half* src = g_w2h + nt * 32768 + c * 64;
#pragma unroll
        for (int t = 0; t < 4; t++) {
            int e = tid + t * 512;
            int row = e >> 3, col = e & 7;
            CP_ASYNC16(dstb + ((uint32_t)row * 72 + col * 8) * 2,
                       (const void*)(src + (size_t)row * 128 + col * 8));
        }
    };

    cpW1(0, 0, 0); CP_COMMIT();

    if (tid < 256) {
        float s = n2g[tid] * rsqrtf(n2v[tid] + 1e-5f);
        sn[tid] = s;
        tn[tid] = n2b[tid] - n2m[tid] * s;
    } else {
        int c = tid - 256;
        float s = b2g[c] * rsqrtf(b2v[c] + 1e-5f);
        s2[c] = s;
        t2[c] = b2b[c] - b2m[c] * s + fb2[c] * s;
    }
    __syncthreads();

    const float* xb = x1 + (size_t)b * CDIM * TJ;
    for (int e = tid; e < 32768; e += 512) {
        int i = e & 255, p = e >> 8;
        float v = xb[(size_t)i * TJ + p0 + p] * sn[i] + tn[i];
        *(__half*)(smem + M2_XS + ((uint32_t)p * 264 + i) * 2) = __float2half(v);
    }

    const uint32_t a_row  = (lane & 7) + ((lane >> 3) & 1) * 8;
    const uint32_t a_koff = (lane >> 4) * 8;
    const uint32_t b_row  = (lane & 7) + (lane >> 4) * 8;
    const uint32_t b_koff = ((lane >> 3) & 1) * 8;

    const uint32_t xs_base = sbase + M2_XS;
    const uint32_t hs_base = sbase + M2_HS;

    float d2[4][4][4];
#pragma unroll
    for (int mi = 0; mi < 4; mi++)
#pragma unroll
        for (int nf = 0; nf < 4; nf++)
#pragma unroll
            for (int q = 0; q < 4; q++) d2[mi][nf][q] = 0.f;

    int buf = 0;

    for (int nt = 0; nt < 8; nt++) {
        if (tid < 128) {
            int j = nt * 128 + tid;
            float s = b1g[j] * rsqrtf(b1v[j] + 1e-5f);
            s1[tid] = s;
            t1[tid] = b1b[j] - b1m[j] * s + fb1[j] * s;
        }

        float d1[2][4][4];
#pragma unroll
        for (int mi = 0; mi < 2; mi++)
#pragma unroll
            for (int nf = 0; nf < 4; nf++)
#pragma unroll
                for (int q = 0; q < 4; q++) d1[mi][nf][q] = 0.f;

        for (int c = 0; c < 4; c++) {
            if (c < 3) cpW1(nt, c + 1, buf ^ 1);
            else       cpW2(nt, 0, buf ^ 1);
            CP_COMMIT(); CP_WAIT1();
            __syncthreads();

            const uint32_t wsb = sbase + M2_WB + (uint32_t)buf * 36864;
#pragma unroll
            for (int ks = 0; ks < 4; ks++) {
                const int k0 = ks * 16;
                const int kg = c * 64 + k0;
                uint32_t b0[4], b1[4];
                LDM_X4(b0, xs_base + (((uint32_t)(wx * 32)      + b_row) * 264 + kg + b_koff) * 2);
                LDM_X4(b1, xs_base + (((uint32_t)(wx * 32 + 16) + b_row) * 264 + kg + b_koff) * 2);
                uint32_t a[2][4];
#pragma unroll
                for (int mi = 0; mi < 2; mi++)
                    LDM_X4(a[mi], wsb + (((uint32_t)(wy * 32 + mi * 16) + a_row) * 72
                                          + k0 + a_koff) * 2);
#pragma unroll
                for (int mi = 0; mi < 2; mi++) {
                    MMA16816(d1[mi][0], a[mi], b0[0], b0[1]);
                    MMA16816(d1[mi][1], a[mi], b0[2], b0[3]);
                    MMA16816(d1[mi][2], a[mi], b1[0], b1[1]);
                    MMA16816(d1[mi][3], a[mi], b1[2], b1[3]);
                }
            }
            buf ^= 1;
            __syncthreads();
        }

        {
            int r = lane >> 2, c2l = (lane & 3) * 2;
#pragma unroll
            for (int mi = 0; mi < 2; mi++) {
                int j = wy * 32 + mi * 16 + r;
                float sj0 = s1[j],     tj0 = t1[j];
                float sj8 = s1[j + 8], tj8 = t1[j + 8];
#pragma unroll
                for (int nf = 0; nf < 4; nf++) {
                    int pos = wx * 32 + nf * 8 + c2l;
                    __half* h0 = (__half*)(smem + M2_HS + ((uint32_t)pos * 136 + j) * 2);
                    __half* h1 = (__half*)(smem + M2_HS + ((uint32_t)(pos + 1) * 136 + j) * 2);
                    h0[0] = __float2half(gelu_exact(d1[mi][nf][0] * sj0 + tj0));
                    h1[0] = __float2half(gelu_exact(d1[mi][nf][1] * sj0 + tj0));
                    h0[8] = __float2half(gelu_exact(d1[mi][nf][2] * sj8 + tj8));
                    h1[8] = __float2half(gelu_exact(d1[mi][nf][3] * sj8 + tj8));
                }
            }
        }

        for (int c = 0; c < 2; c++) {
            if (c == 0)        { cpW2(nt, 1, buf ^ 1); CP_COMMIT(); CP_WAIT1(); }
            else if (nt < 7)   { cpW1(nt + 1, 0, buf ^ 1); CP_COMMIT(); CP_WAIT1(); }
            else               { CP_WAIT0(); }
            __syncthreads();

            const uint32_t wsb = sbase + M2_WB + (uint32_t)buf * 36864;
#pragma unroll
            for (int ks = 0; ks < 4; ks++) {
                const int k0 = ks * 16;
                const int kg = c * 64 + k0;
                uint32_t b0[4], b1[4];
                LDM_X4(b0, hs_base + (((uint32_t)(wx * 32)      + b_row) * 136 + kg + b_koff) * 2);
                LDM_X4(b1, hs_base + (((uint32_t)(wx * 32 + 16) + b_row) * 136 + kg + b_koff) * 2);
                uint32_t a[4][4];
#pragma unroll
                for (int mi = 0; mi < 4; mi++)
                    LDM_X4(a[mi], wsb + (((uint32_t)(wy * 64 + mi * 16) + a_row) * 72
                                          + k0 + a_koff) * 2);
#pragma unroll
                for (int mi = 0; mi < 4; mi++) {
                    MMA16816(d2[mi][0], a[mi], b0[0], b0[1]);
                    MMA16816(d2[mi][1], a[mi], b0[2], b0[3]);
                    MMA16816(d2[mi][2], a[mi], b1[0], b1[1]);
                    MMA16816(d2[mi][3], a[mi], b1[2], b1[3]);
                }
            }
            buf ^= 1;
            __syncthreads();
        }
    }

    float* stage = (float*)(smem + M2_ST);
#pragma unroll
    for (int h = 0; h < 2; h++) {
        if ((wy >> 1) == h) {
            int r = lane >> 2, c2l = (lane & 3) * 2;
#pragma unroll
            for (int mi = 0; mi < 4; mi++) {
                int row = wy * 64 + mi * 16 + r - 128 * h;
#pragma unroll
                for (int nf = 0; nf < 4; nf++) {
                    int col = wx * 32 + nf * 8 + c2l;
                    stage[col * 129 + row]           = d2[mi][nf][0];
                    stage[(col + 1) * 129 + row]     = d2[mi][nf][1];
                    stage[col * 129 + row + 8]       = d2[mi][nf][2];
                    stage[(col + 1) * 129 + row + 8] = d2[mi][nf][3];
                }
            }
        }
        __syncthreads();
        for (int e = tid; e < 16384; e += 512) {
            int gl = e & 127, cl = e >> 7;
            int ch = 128 * h + cl;
            size_t idx = ((size_t)b * CDIM + ch) * TJ + p0 + gl;
            out[idx] = x1[idx] + stage[gl * 129 + cl] * s2[ch] + t2[ch];
        }
        __syncthreads();
    }
}

// ---------------------------------------------------------------------------
extern "C" void kernel_launch(void* const* d_in, const int* in_sizes, int n_in,
                              void* d_out, int out_size)
{
    const float* x    = (const float*)d_in[0];
    const float* n1g  = (const float*)d_in[1];
    const float* n1b  = (const float*)d_in[2];
    const float* n1m  = (const float*)d_in[3];
    const float* n1v  = (const float*)d_in[4];
    const float* qkvw = (const float*)d_in[5];
    const float* qg   = (const float*)d_in[6];
    const float* qb   = (const float*)d_in[7];
    const float* qm   = (const float*)d_in[8];
    const float* qv   = (const float*)d_in[9];
    const float* pw   = (const float*)d_in[10];
    const float* pb   = (const float*)d_in[11];
    const float* n2g  = (const float*)d_in[12];
    const float* n2b  = (const float*)d_in[13];
    const float* n2m  = (const float*)d_in[14];
    const float* n2v  = (const float*)d_in[15];
    const float* w1   = (const float*)d_in[16];
    const float* fb1  = (const float*)d_in[17];
    const float* b1g  = (const float*)d_in[18];
    const float* b1b  = (const float*)d_in[19];
    const float* b1m  = (const float*)d_in[20];
    const float* b1v  = (const float*)d_in[21];
    const float* w2   = (const float*)d_in[22];
    const float* fb2  = (const float*)d_in[23];
    const float* b2g  = (const float*)d_in[24];
    const float* b2b  = (const float*)d_in[25];
    const float* b2m  = (const float*)d_in[26];
    const float* b2v  = (const float*)d_in[27];
    float* out = (float*)d_out;

    cudaFuncSetAttribute(k_attn_mma,  cudaFuncAttributeMaxDynamicSharedMemorySize, AT_TOT);
    cudaFuncSetAttribute(k_conv_mma,  cudaFuncAttributeMaxDynamicSharedMemorySize, CV_TOT);
    cudaFuncSetAttribute(k_projc_mma, cudaFuncAttributeMaxDynamicSharedMemorySize, PC_TOT);
    cudaFuncSetAttribute(k_resize,    cudaFuncAttributeMaxDynamicSharedMemorySize, RZ_TOT);
    cudaFuncSetAttribute(k_mlp_mma2,  cudaFuncAttributeMaxDynamicSharedMemorySize, M2_TOT);

    k_prep_all<<<16384 + 4608, 512>>>(w1, w2, qkvw, pw, x, n1g, n1b, n1m, n1v);
    k_conv_mma<<<dim3(3, 129), 512, CV_TOT>>>(qg, qb, qm, qv);
    k_attn_mma<<<512, 544, AT_TOT>>>();
    k_projc_mma<<<129, 512, PC_TOT>>>();
    k_resize<<<dim3(17, 64), 512, RZ_TOT>>>(pb, x, out);
    k_mlp_mma2<<<1088, 512, M2_TOT>>>(out,
                                      b1g, b1b, b1m, b1v, fb1,
                                      b2g, b2b, b2m, b2v, fb2,
                                      n2g, n2b, n2m, n2v, out);
}

// round 15
// speedup vs baseline: 1.0865x; 1.0817x over previous
#include <cuda_runtime.h>
#include <cuda_fp16.h>
#include <math.h>
#include <stdint.h>

#define BATCH 64
#define CDIM 256
#define TDIM 128
#define JDIM 17
#define TJ 2176     // TDIM*JDIM
#define HCC 43
#define WCC 6
#define HW 258      // HCC*WCC
#define HIDDEN 1024

// scratch (static __device__ globals per harness rules)
__device__ __half g_qkv[(size_t)3 * BATCH * HW * CDIM];  // fp16 [b][t][hw][c]
__device__ __half g_att[(size_t)BATCH * HW * CDIM];      // fp16 [b][hw][c]
__device__ __half g_y[(size_t)BATCH * HW * CDIM];        // proj output (compressed grid)
__device__ __half g_xn[(size_t)BATCH * CDIM * TJ];       // n1bn(x) fp16
// fp16 weights
__device__ __half g_w1h[8 * 32768];            // W1 per-tile [128 j][256 i]
__device__ __half g_w2h[8 * 32768];            // W2 per-tile [256 c][128 j]
__device__ __half g_qwh[768 * 2304];           // qkv conv weight row-major
__device__ __half g_pwh[256 * 256];            // proj weight row-major

__device__ __forceinline__ float gelu_exact(float v) {
    return 0.5f * v * (1.0f + erff(v * 0.70710678118654752f));
}

__device__ __forceinline__ uint32_t smem_u32(const void* p) {
    uint32_t a;
    asm("{ .reg .u64 t; cvta.to.shared.u64 t, %1; cvt.u32.u64 %0, t; }" : "=r"(a) : "l"(p));
    return a;
}

__device__ __forceinline__ uint32_t h2_to_u32(__half2 h) {
    return *reinterpret_cast<uint32_t*>(&h);
}

#define LDM_X4(r, addr) \
    asm volatile("ldmatrix.sync.aligned.m8n8.x4.shared.b16 {%0,%1,%2,%3}, [%4];" \
        : "=r"((r)[0]), "=r"((r)[1]), "=r"((r)[2]), "=r"((r)[3]) : "r"(addr))

#define LDM_X4_T(r, addr) \
    asm volatile("ldmatrix.sync.aligned.m8n8.x4.trans.shared.b16 {%0,%1,%2,%3}, [%4];" \
        : "=r"((r)[0]), "=r"((r)[1]), "=r"((r)[2]), "=r"((r)[3]) : "r"(addr))

#define MMA16816(d, a, b0, b1) \
    asm volatile("mma.sync.aligned.m16n8k16.row.col.f32.f16.f16.f32 " \
        "{%0,%1,%2,%3}, {%4,%5,%6,%7}, {%8,%9}, {%0,%1,%2,%3};" \
        : "+f"((d)[0]), "+f"((d)[1]), "+f"((d)[2]), "+f"((d)[3]) \
        : "r"((a)[0]), "r"((a)[1]), "r"((a)[2]), "r"((a)[3]), "r"(b0), "r"(b1))

#define CP_ASYNC16(dst, src) \
    asm volatile("cp.async.cg.shared.global [%0], [%1], 16;" :: "r"(dst), "l"(src))
#define CP_COMMIT() asm volatile("cp.async.commit_group;")
#define CP_WAIT1()  asm volatile("cp.async.wait_group 1;" ::: "memory")
#define CP_WAIT0()  asm volatile("cp.async.wait_group 0;" ::: "memory")

// ---------------------------------------------------------------------------
// K0: merged prep — blocks [0,16384): xn = n1bn(x) fp16; rest: weight convert
// ---------------------------------------------------------------------------
__global__ void __launch_bounds__(512) k_prep_all(
    const float* __restrict__ w1, const float* __restrict__ w2,
    const float* __restrict__ qkvw, const float* __restrict__ pw,
    const float* __restrict__ x,
    const float* __restrict__ n1g, const float* __restrict__ n1b,
    const float* __restrict__ n1m, const float* __restrict__ n1v)
{
    const int blk = blockIdx.x;
    if (blk < 16384) {
        __shared__ float ss, tt;
        const int c = blk & 255;
        if (threadIdx.x == 0) {
            float s = n1g[c] * rsqrtf(n1v[c] + 1e-5f);
            ss = s;
            tt = n1b[c] - n1m[c] * s;
        }
        __syncthreads();
        const float* xr = x + (size_t)blk * TJ;
        __half* xo = g_xn + (size_t)blk * TJ;
        float s = ss, t = tt;
        for (int p = threadIdx.x; p < TJ; p += 512)
            xo[p] = __float2half(xr[p] * s + t);
        return;
    }
    int idx = (blk - 16384) * 512 + threadIdx.x;
    if (idx < 262144) {
        int j = idx >> 8, i = idx & 255;
        int nt = j >> 7, jl = j & 127;
        g_w1h[(uint32_t)nt * 32768 + (uint32_t)jl * 256 + i] = __float2half(w1[idx]);
    } else if (idx < 524288) {
        int t = idx - 262144;
        int c = t >> 10, j = t & 1023;
        int nt = j >> 7, jl = j & 127;
        g_w2h[(uint32_t)nt * 32768 + (uint32_t)c * 128 + jl] = __float2half(w2[t]);
    } else if (idx < 2293760) {
        int t = idx - 524288;
        g_qwh[t] = __float2half(qkvw[t]);
    } else {
        int t = idx - 2293760;
        g_pwh[t] = __float2half(pw[t]);
    }
}

// ---------------------------------------------------------------------------
// K1: conv QKV on HMMA (unchanged)
// ---------------------------------------------------------------------------
#define CV_KTAB  0
#define CV_SO    4608
#define CV_TO    5632
#define CV_PBUF  6656
#define CV_WBUF  76288
#define CV_STAGE CV_PBUF
#define CV_TOT   215552

__global__ void __launch_bounds__(512, 1) k_conv_mma(
    const float* __restrict__ qg, const float* __restrict__ qb,
    const float* __restrict__ qm, const float* __restrict__ qv)
{
    extern __shared__ char smem[];
    const uint32_t sbase = smem_u32(smem);
    const int tid = threadIdx.x;
    const int wid = tid >> 5, lane = tid & 31;
    const int wy = wid & 3, wx = wid >> 2;

    const int m0 = blockIdx.x * 256;
    const int n0 = blockIdx.y * 128;

    uint16_t* ktab = (uint16_t*)(smem + CV_KTAB);
    float*    s_o  = (float*)(smem + CV_SO);
    float*    t_o  = (float*)(smem + CV_TO);

    if (tid < 256) {
        int o = m0 + tid;
        float s = qg[o] * rsqrtf(qv[o] + 1e-5f);
        s_o[tid] = s;
        t_o[tid] = qb[o] - qm[o] * s;
    }
    for (int k = tid; k < 2304; k += 512) {
        int i = k / 9, r = k - i * 9;
        int ky = r / 3, kx = r - ky * 3;
        ktab[k] = (uint16_t)((i << 4) | (ky << 2) | kx);
    }
    __syncthreads();

    const int gl    = tid & 127;
    const int kslot = tid >> 7;
    int p_xo, p_iy, p_ix;
    {
        int g = n0 + gl;
        int b = g / HW, hw = g - b * HW;
        int y = hw / WCC, xx = hw - y * WCC;
        p_xo = b * (CDIM * TJ);
        p_iy = 3 * y - 1;
        p_ix = 3 * xx - 1;
    }

    const uint32_t a_row  = (lane & 7) + ((lane >> 3) & 1) * 8;
    const uint32_t a_koff = (lane >> 4) * 8;
    const uint32_t b_row  = (lane & 7) + (lane >> 4) * 8;
    const uint32_t b_koff = ((lane >> 3) & 1) * 8;

    __align__(16) unsigned short pv[32];

    auto cpW = [&](int kc, int bsel) {
        uint32_t dstb = sbase + CV_WBUF + (uint32_t)bsel * 69632;
#pragma unroll
        for (int t = 0; t < 8; t++) {
            int e = tid + t * 512;
            int row = e >> 4, col = e & 15;
            CP_ASYNC16(dstb + ((uint32_t)row * 136 + col * 8) * 2,
                       (const void*)(g_qwh + (size_t)(m0 + row) * 2304 + kc + col * 8));
        }
    };
    auto gatherP = [&](int kc) {
        const int kb = kc + kslot * 32;
#pragma unroll
        for (int t = 0; t < 32; t++) {
            uint32_t kt = ktab[kb + t];
            int i = kt >> 4, ky = (kt >> 2) & 3, kx = kt & 3;
            int iy = p_iy + ky, ix = p_ix + kx;
            unsigned short v = 0;
            if ((unsigned)iy < (unsigned)TDIM && (unsigned)ix < (unsigned)JDIM)
                v = *(const unsigned short*)&g_xn[p_xo + i * TJ + iy * JDIM + ix];
            pv[t] = v;
        }
    };
    auto storeP = [&](int bsel) {
        char* pb2 = smem + CV_PBUF + bsel * 34816;
        uint32_t off = ((uint32_t)gl * 136 + kslot * 32) * 2;
#pragma unroll
        for (int j = 0; j < 4; j++)
            *(uint4*)(pb2 + off + j * 16) = ((const uint4*)pv)[j];
    };

    float d[4][4][4];
#pragma unroll
    for (int mi = 0; mi < 4; mi++)
#pragma unroll
        for (int nf = 0; nf < 4; nf++)
#pragma unroll
            for (int q = 0; q < 4; q++) d[mi][nf][q] = 0.f;

    cpW(0, 0); CP_COMMIT();
    gatherP(0); storeP(0);

    for (int c = 0; c < 18; c++) {
        if (c < 17) {
            cpW((c + 1) * 128, (c + 1) & 1); CP_COMMIT();
            gatherP((c + 1) * 128);
            CP_WAIT1();
        } else {
            CP_WAIT0();
        }
        __syncthreads();

        const uint32_t wsb = sbase + CV_WBUF + (uint32_t)(c & 1) * 69632;
        const uint32_t psb = sbase + CV_PBUF + (uint32_t)(c & 1) * 34816;
#pragma unroll
        for (int ks = 0; ks < 8; ks++) {
            const int k0 = ks * 16;
            uint32_t b0[4], b1[4];
            LDM_X4(b0, psb + (((uint32_t)(wx * 32)      + b_row) * 136 + k0 + b_koff) * 2);
            LDM_X4(b1, psb + (((uint32_t)(wx * 32 + 16) + b_row) * 136 + k0 + b_koff) * 2);
            uint32_t a[4][4];
#pragma unroll
            for (int mi = 0; mi < 4; mi++)
                LDM_X4(a[mi], wsb + (((uint32_t)(wy * 64 + mi * 16) + a_row) * 136
                                      + k0 + a_koff) * 2);
#pragma unroll
            for (int mi = 0; mi < 4; mi++) {
                MMA16816(d[mi][0], a[mi], b0[0], b0[1]);
                MMA16816(d[mi][1], a[mi], b0[2], b0[3]);
                MMA16816(d[mi][2], a[mi], b1[0], b1[1]);
                MMA16816(d[mi][3], a[mi], b1[2], b1[3]);
            }
        }
        if (c < 17) storeP((c + 1) & 1);
        __syncthreads();
    }

    float* stage = (float*)(smem + CV_STAGE);
    const int tpart = blockIdx.x;
#pragma unroll
    for (int h = 0; h < 2; h++) {
        if ((wy >> 1) == h) {
            int r = lane >> 2, c2 = (lane & 3) * 2;
#pragma unroll
            for (int mi = 0; mi < 4; mi++) {
                int row = wy * 64 + mi * 16 + r - 128 * h;
#pragma unroll
                for (int nf = 0; nf < 4; nf++) {
                    int col = wx * 32 + nf * 8 + c2;
                    stage[col * 129 + row]           = d[mi][nf][0];
                    stage[(col + 1) * 129 + row]     = d[mi][nf][1];
                    stage[col * 129 + row + 8]       = d[mi][nf][2];
                    stage[(col + 1) * 129 + row + 8] = d[mi][nf][3];
                }
            }
        }
        __syncthreads();
        for (int e = tid; e < 16384; e += 512) {
            int gl2 = e >> 7, cl = e & 127;
            int g = n0 + gl2;
            int b = g / HW, hw = g - b * HW;
            int ch = 128 * h + cl;
            float v = stage[gl2 * 129 + cl] * s_o[ch] + t_o[ch];
            g_qkv[(((size_t)b * 3 + tpart) * HW + hw) * CDIM + ch]
                = __float2half(gelu_exact(v));
        }
        __syncthreads();
    }
}

// ---------------------------------------------------------------------------
// K2: attention on HMMA (unchanged)
// ---------------------------------------------------------------------------
#define AT_STR  40
#define AT_Q    0
#define AT_K    21760
#define AT_V    43520
#define AT_TOT  65280

__global__ void __launch_bounds__(544) k_attn_mma()
{
    extern __shared__ char smem[];
    const uint32_t sbase = smem_u32(smem);
    __half* qs = (__half*)(smem + AT_Q);
    __half* ks = (__half*)(smem + AT_K);
    __half* vs = (__half*)(smem + AT_V);

    const int bh = blockIdx.x;
    const int b = bh >> 3, h = bh & 7;
    const int tid = threadIdx.x;
    const int wid = tid >> 5, lane = tid & 31;

    const __half* qg = g_qkv + (((size_t)b * 3 + 0) * HW) * CDIM + h * 32;
    const __half* kg = g_qkv + (((size_t)b * 3 + 1) * HW) * CDIM + h * 32;
    const __half* vg = g_qkv + (((size_t)b * 3 + 2) * HW) * CDIM + h * 32;

    const __half2 sc2 = __float2half2_rn(0.17677669529663687f);
    for (int e = tid; e < 272 * 4; e += 544) {
        int r = e >> 2, d8 = (e & 3) * 8;
        uint4 q4 = make_uint4(0, 0, 0, 0), k4 = q4, v4 = q4;
        if (r < HW) {
            size_t off = (size_t)r * CDIM + d8;
            q4 = *(const uint4*)(qg + off);
            k4 = *(const uint4*)(kg + off);
            v4 = *(const uint4*)(vg + off);
        }
        __half2* qh = (__half2*)&q4;
#pragma unroll
        for (int j = 0; j < 4; j++) qh[j] = __hmul2(qh[j], sc2);
        *(uint4*)(qs + r * AT_STR + d8) = q4;
        *(uint4*)(ks + r * AT_STR + d8) = k4;
        *(uint4*)(vs + r * AT_STR + d8) = v4;
    }
    __syncthreads();

    const int m0 = wid * 16;
    const uint32_t a_row  = (lane & 7) + ((lane >> 3) & 1) * 8;
    const uint32_t a_koff = (lane >> 4) * 8;
    const uint32_t b_row  = (lane & 7) + (lane >> 4) * 8;
    const uint32_t b_koff = ((lane >> 3) & 1) * 8;
    const uint32_t v_row  = (lane & 7) + ((lane >> 3) & 1) * 8;
    const uint32_t v_col  = (lane >> 4) * 8;

    const uint32_t qs_base = sbase + AT_Q;
    const uint32_t ks_base = sbase + AT_K;
    const uint32_t vs_base = sbase + AT_V;

    uint32_t qa[2][4];
    LDM_X4(qa[0], qs_base + (((uint32_t)m0 + a_row) * AT_STR + 0  + a_koff) * 2);
    LDM_X4(qa[1], qs_base + (((uint32_t)m0 + a_row) * AT_STR + 16 + a_koff) * 2);

    float o[4][4];
#pragma unroll
    for (int nt = 0; nt < 4; nt++)
#pragma unroll
        for (int q = 0; q < 4; q++) o[nt][q] = 0.f;
    float mr = -1e30f, mr8 = -1e30f, lr = 0.f, lr8 = 0.f;

    const int c2 = (lane & 3) * 2;

    for (int jt = 0; jt < 17; jt++) {
        float s0[4] = {0.f, 0.f, 0.f, 0.f};
        float s1[4] = {0.f, 0.f, 0.f, 0.f};
        {
            uint32_t bb[4];
            LDM_X4(bb, ks_base + (((uint32_t)(jt * 16) + b_row) * AT_STR + 0 + b_koff) * 2);
            MMA16816(s0, qa[0], bb[0], bb[1]);
            MMA16816(s1, qa[0], bb[2], bb[3]);
            LDM_X4(bb, ks_base + (((uint32_t)(jt * 16) + b_row) * AT_STR + 16 + b_koff) * 2);
            MMA16816(s0, qa[1], bb[0], bb[1]);
            MMA16816(s1, qa[1], bb[2], bb[3]);
        }
        if (jt == 16) {
            if (256 + c2     >= HW) { s0[0] = -1e30f; s0[2] = -1e30f; }
            if (256 + c2 + 1 >= HW) { s0[1] = -1e30f; s0[3] = -1e30f; }
            if (256 + c2 + 8 >= HW) { s1[0] = -1e30f; s1[2] = -1e30f; }
            if (256 + c2 + 9 >= HW) { s1[1] = -1e30f; s1[3] = -1e30f; }
        }

        float cmr  = fmaxf(fmaxf(s0[0], s0[1]), fmaxf(s1[0], s1[1]));
        float cmr8 = fmaxf(fmaxf(s0[2], s0[3]), fmaxf(s1[2], s1[3]));
        cmr  = fmaxf(cmr,  __shfl_xor_sync(0xffffffffu, cmr, 1));
        cmr  = fmaxf(cmr,  __shfl_xor_sync(0xffffffffu, cmr, 2));
        cmr8 = fmaxf(cmr8, __shfl_xor_sync(0xffffffffu, cmr8, 1));
        cmr8 = fmaxf(cmr8, __shfl_xor_sync(0xffffffffu, cmr8, 2));
        float mnr  = fmaxf(mr, cmr);
        float mnr8 = fmaxf(mr8, cmr8);
        float corr  = __expf(mr - mnr);
        float corr8 = __expf(mr8 - mnr8);
        float p00 = __expf(s0[0] - mnr),  p01 = __expf(s0[1] - mnr);
        float p02 = __expf(s1[0] - mnr),  p03 = __expf(s1[1] - mnr);
        float p80 = __expf(s0[2] - mnr8), p81 = __expf(s0[3] - mnr8);
        float p82 = __expf(s1[2] - mnr8), p83 = __expf(s1[3] - mnr8);
        float ps  = p00 + p01 + p02 + p03;
        float ps8 = p80 + p81 + p82 + p83;
        ps  += __shfl_xor_sync(0xffffffffu, ps, 1);
        ps  += __shfl_xor_sync(0xffffffffu, ps, 2);
        ps8 += __shfl_xor_sync(0xffffffffu, ps8, 1);
        ps8 += __shfl_xor_sync(0xffffffffu, ps8, 2);
        lr  = lr  * corr  + ps;
        lr8 = lr8 * corr8 + ps8;
        mr = mnr; mr8 = mnr8;

        uint32_t pa[4];
        pa[0] = h2_to_u32(__floats2half2_rn(p00, p01));
        pa[1] = h2_to_u32(__floats2half2_rn(p80, p81));
        pa[2] = h2_to_u32(__floats2half2_rn(p02, p03));
        pa[3] = h2_to_u32(__floats2half2_rn(p82, p83));

#pragma unroll
        for (int nt = 0; nt < 4; nt++) {
            o[nt][0] *= corr;  o[nt][1] *= corr;
            o[nt][2] *= corr8; o[nt][3] *= corr8;
        }

        {
            uint32_t vb[4];
            LDM_X4_T(vb, vs_base + (((uint32_t)(jt * 16) + v_row) * AT_STR + 0 + v_col) * 2);
            MMA16816(o[0], pa, vb[0], vb[1]);
            MMA16816(o[1], pa, vb[2], vb[3]);
            LDM_X4_T(vb, vs_base + (((uint32_t)(jt * 16) + v_row) * AT_STR + 16 + v_col) * 2);
            MMA16816(o[2], pa, vb[0], vb[1]);
            MMA16816(o[3], pa, vb[2], vb[3]);
        }
    }

    const int r0 = m0 + (lane >> 2);
    float invr  = 1.f / lr;
    float invr8 = 1.f / lr8;
    if (r0 < HW) {
        __half* og = g_att + ((size_t)b * HW + r0) * CDIM + h * 32 + c2;
#pragma unroll
        for (int nt = 0; nt < 4; nt++)
            *(__half2*)(og + nt * 8) = __floats2half2_rn(o[nt][0] * invr, o[nt][1] * invr);
    }
    if (r0 + 8 < HW) {
        __half* og = g_att + ((size_t)b * HW + r0 + 8) * CDIM + h * 32 + c2;
#pragma unroll
        for (int nt = 0; nt < 4; nt++)
            *(__half2*)(og + nt * 8) = __floats2half2_rn(o[nt][2] * invr8, o[nt][3] * invr8);
    }
}

// ---------------------------------------------------------------------------
// K3a: proj on COMPRESSED grid (unchanged from round 14 — 16 us)
// ---------------------------------------------------------------------------
#define PC_WS    0
#define PC_PS    135168
#define PC_STAGE PC_PS
#define PC_TOT   202752

__global__ void __launch_bounds__(512, 1) k_projc_mma()
{
    extern __shared__ char smem[];
    const uint32_t sbase = smem_u32(smem);
    const int tid = threadIdx.x;
    const int wid = tid >> 5, lane = tid & 31;
    const int wy = wid & 3, wx = wid >> 2;

    const int n0 = blockIdx.x * 128;

    {
        uint32_t ws = sbase + PC_WS;
#pragma unroll
        for (int t = 0; t < 16; t++) {
            int e = tid + t * 512;
            int row = e >> 5, col = e & 31;
            CP_ASYNC16(ws + ((uint32_t)row * 264 + col * 8) * 2,
                       (const void*)(g_pwh + (size_t)row * 256 + col * 8));
        }
    }
    {
        uint32_t ps = sbase + PC_PS;
#pragma unroll
        for (int t = 0; t < 8; t++) {
            int e = tid + t * 512;
            int gl = e >> 5, col = e & 31;
            CP_ASYNC16(ps + ((uint32_t)gl * 264 + col * 8) * 2,
                       (const void*)(g_att + (size_t)(n0 + gl) * 256 + col * 8));
        }
    }
    CP_COMMIT(); CP_WAIT0();
    __syncthreads();

    const uint32_t a_row  = (lane & 7) + ((lane >> 3) & 1) * 8;
    const uint32_t a_koff = (lane >> 4) * 8;
    const uint32_t b_row  = (lane & 7) + (lane >> 4) * 8;
    const uint32_t b_koff = ((lane >> 3) & 1) * 8;
    const uint32_t ps_base = sbase + PC_PS;
    const uint32_t ws_base = sbase + PC_WS;

    float d[4][4][4];
#pragma unroll
    for (int mi = 0; mi < 4; mi++)
#pragma unroll
        for (int nf = 0; nf < 4; nf++)
#pragma unroll
            for (int q = 0; q < 4; q++) d[mi][nf][q] = 0.f;

#pragma unroll 4
    for (int k0 = 0; k0 < 256; k0 += 16) {
        uint32_t b0[4], b1[4];
        LDM_X4(b0, ps_base + (((uint32_t)(wx * 32)      + b_row) * 264 + k0 + b_koff) * 2);
        LDM_X4(b1, ps_base + (((uint32_t)(wx * 32 + 16) + b_row) * 264 + k0 + b_koff) * 2);
        uint32_t a[4][4];
#pragma unroll
        for (int mi = 0; mi < 4; mi++)
            LDM_X4(a[mi], ws_base + (((uint32_t)(wy * 64 + mi * 16) + a_row) * 264
                                      + k0 + a_koff) * 2);
#pragma unroll
        for (int mi = 0; mi < 4; mi++) {
            MMA16816(d[mi][0], a[mi], b0[0], b0[1]);
            MMA16816(d[mi][1], a[mi], b0[2], b0[3]);
            MMA16816(d[mi][2], a[mi], b1[0], b1[1]);
            MMA16816(d[mi][3], a[mi], b1[2], b1[3]);
        }
    }
    __syncthreads();

    float* stage = (float*)(smem + PC_STAGE);
#pragma unroll
    for (int h = 0; h < 2; h++) {
        if ((wy >> 1) == h) {
            int r = lane >> 2, c2 = (lane & 3) * 2;
#pragma unroll
            for (int mi = 0; mi < 4; mi++) {
                int row = wy * 64 + mi * 16 + r - 128 * h;
#pragma unroll
                for (int nf = 0; nf < 4; nf++) {
                    int col = wx * 32 + nf * 8 + c2;
                    stage[col * 129 + row]           = d[mi][nf][0];
                    stage[(col + 1) * 129 + row]     = d[mi][nf][1];
                    stage[col * 129 + row + 8]       = d[mi][nf][2];
                    stage[(col + 1) * 129 + row + 8] = d[mi][nf][3];
                }
            }
        }
        __syncthreads();
        for (int e = tid; e < 16384; e += 512) {
            int cl = e & 127, gl = e >> 7;
            g_y[(size_t)(n0 + gl) * 256 + 128 * h + cl]
                = __float2half(stage[gl * 129 + cl]);
        }
        __syncthreads();
    }
}

// ---------------------------------------------------------------------------
// K3b: resize epilogue, high occupancy: 256 thr / 64 positions, fp16 stage
// ---------------------------------------------------------------------------
#define RZ_O00  0                       // int[64]
#define RZ_O01  256
#define RZ_O10  512
#define RZ_O11  768
#define RZ_WX   1024                    // float[64]
#define RZ_WY   1280
#define RZ_PB   1536                    // float[256]
#define RZ_ST   2560                    // half[64*258] = 33024
#define RZ_TOT  35584

__global__ void __launch_bounds__(256) k_resize(
    const float* __restrict__ pb,
    const float* __restrict__ x, float* __restrict__ x1)
{
    extern __shared__ char smem[];
    const int tid = threadIdx.x;
    const int b  = blockIdx.y;
    const int p0 = blockIdx.x * 64;

    int*   o00 = (int*)(smem + RZ_O00);
    int*   o01 = (int*)(smem + RZ_O01);
    int*   o10 = (int*)(smem + RZ_O10);
    int*   o11 = (int*)(smem + RZ_O11);
    float* wxs = (float*)(smem + RZ_WX);
    float* wys = (float*)(smem + RZ_WY);
    float* pbs = (float*)(smem + RZ_PB);
    __half* stage = (__half*)(smem + RZ_ST);

    if (tid < 64) {
        int p = p0 + tid;
        int t = p / JDIM, j = p - t * JDIM;
        float sy = (t + 0.5f) * (43.0f / 128.0f) - 0.5f;
        sy = fminf(fmaxf(sy, 0.f), 42.f);
        int y0 = (int)sy;
        int y1 = min(y0 + 1, 42);
        float fy = sy - y0;
        float sx = (j + 0.5f) * (6.0f / 17.0f) - 0.5f;
        sx = fminf(fmaxf(sx, 0.f), 5.f);
        int x0 = (int)sx;
        int x1i = min(x0 + 1, 5);
        float fx = sx - x0;
        o00[tid] = (y0 * WCC + x0) * CDIM;
        o01[tid] = (y0 * WCC + x1i) * CDIM;
        o10[tid] = (y1 * WCC + x0) * CDIM;
        o11[tid] = (y1 * WCC + x1i) * CDIM;
        wxs[tid] = fx;
        wys[tid] = fy;
    }
    pbs[tid] = pb[tid];
    __syncthreads();

    const __half* yb = g_y + (size_t)b * HW * CDIM;
    for (int e = tid; e < 16384; e += 256) {
        int c = e & 255, gl = e >> 8;
        const __half* bp = yb + c;
        float fx = wxs[gl], fy = wys[gl];
        float a00 = __half2float(bp[o00[gl]]);
        float a01 = __half2float(bp[o01[gl]]);
        float a10 = __half2float(bp[o10[gl]]);
        float a11 = __half2float(bp[o11[gl]]);
        float v = (a00 * (1.f - fx) + a01 * fx) * (1.f - fy)
                + (a10 * (1.f - fx) + a11 * fx) * fy;
        stage[gl * 258 + c] = __float2half(v);
    }
    __syncthreads();

    for (int e = tid; e < 16384; e += 256) {
        int ch = e >> 6, gl = e & 63;
        size_t idx = ((size_t)b * CDIM + ch) * TJ + p0 + gl;
        x1[idx] = x[idx] + __half2float(stage[gl * 258 + ch]) + pbs[ch];
    }
}

// ---------------------------------------------------------------------------
// K4: fused MLP on HMMA, big-tile (unchanged)
// ---------------------------------------------------------------------------
#define M2_SN   0
#define M2_TN   1024
#define M2_S2   2048
#define M2_T2   3072
#define M2_S1   4096
#define M2_T1   4608
#define M2_XS   5120
#define M2_HS   72704
#define M2_WB   107520
#define M2_ST   M2_XS
#define M2_TOT  181248

__global__ void __launch_bounds__(512, 1) k_mlp_mma2(
    const float* x1,
    const float* __restrict__ b1g, const float* __restrict__ b1b,
    const float* __restrict__ b1m, const float* __restrict__ b1v,
    const float* __restrict__ fb1,
    const float* __restrict__ b2g, const float* __restrict__ b2b,
    const float* __restrict__ b2m, const float* __restrict__ b2v,
    const float* __restrict__ fb2,
    const float* __restrict__ n2g, const float* __restrict__ n2b,
    const float* __restrict__ n2m, const float* __restrict__ n2v,
    float* out)
{
    extern __shared__ char smem[];
    const uint32_t sbase = smem_u32(smem);
    const int tid = threadIdx.x;
    const int wid = tid >> 5, lane = tid & 31;
    const int wy = wid & 3, wx = wid >> 2;

    const int b  = blockIdx.x / 17;
    const int p0 = (blockIdx.x - b * 17) * 128;

    float* sn = (float*)(smem + M2_SN);
    float* tn = (float*)(smem + M2_TN);
    float* s2 = (float*)(smem + M2_S2);
    float* t2 = (float*)(smem + M2_T2);
    float* s1 = (float*)(smem + M2_S1);
    float* t1 = (float*)(smem + M2_T1);

    auto cpW1 = [&](int nt, int c, int bsel) {
        uint32_t dstb = sbase + M2_WB + (uint32_t)bsel * 36864;
        const __half* src = g_w1h + nt * 32768 + c * 64;
#pragma unroll
        for (int t = 0; t < 2; t++) {
            int e = tid + t * 512;
            int row = e >> 3, col = e & 7;
            CP_ASYNC16(dstb + ((uint32_t)row * 72 + col * 8) * 2,
                       (const void*)(src + (size_t)row * 256 + col * 8));
        }
    };
    auto cpW2 = [&](int nt, int c, int bsel) {
        uint32_t dstb = sbase + M2_WB + (uint32_t)bsel * 36864;
        const __half* src = g_w2h + nt * 32768 + c * 64;
#pragma unroll
        for (int t = 0; t < 4; t++) {
            int e = tid + t * 512;
            int row = e >> 3, col = e & 7;
            CP_ASYNC16(dstb + ((uint32_t)row * 72 + col * 8) * 2,
                       (const void*)(src + (size_t)row * 128 + col * 8));
        }
    };

    cpW1(0, 0, 0); CP_COMMIT();

    if (tid < 256) {
        float s = n2g[tid] * rsqrtf(n2v[tid] + 1e-5f);
        sn[tid] = s;
        tn[tid] = n2b[tid] - n2m[tid] * s;
    } else {
        int c = tid - 256;
        float s = b2g[c] * rsqrtf(b2v[c] + 1e-5f);
        s2[c] = s;
        t2[c] = b2b[c] - b2m[c] * s + fb2[c] * s;
    }
    __syncthreads();

    const float* xb = x1 + (size_t)b * CDIM * TJ;
    for (int e = tid; e < 32768; e += 512) {
        int i = e & 255, p = e >> 8;
        float v = xb[(size_t)i * TJ + p0 + p] * sn[i] + tn[i];
        *(__half*)(smem + M2_XS + ((uint32_t)p * 264 + i) * 2) = __float2half(v);
    }

    const uint32_t a_row  = (lane & 7) + ((lane >> 3) & 1) * 8;
    const uint32_t a_koff = (lane >> 4) * 8;
    const uint32_t b_row  = (lane & 7) + (lane >> 4) * 8;
    const uint32_t b_koff = ((lane >> 3) & 1) * 8;

    const uint32_t xs_base = sbase + M2_XS;
    const uint32_t hs_base = sbase + M2_HS;

    float d2[4][4][4];
#pragma unroll
    for (int mi = 0; mi < 4; mi++)
#pragma unroll
        for (int nf = 0; nf < 4; nf++)
#pragma unroll
            for (int q = 0; q < 4; q++) d2[mi][nf][q] = 0.f;

    int buf = 0;

    for (int nt = 0; nt < 8; nt++) {
        if (tid < 128) {
            int j = nt * 128 + tid;
            float s = b1g[j] * rsqrtf(b1v[j] + 1e-5f);
            s1[tid] = s;
            t1[tid] = b1b[j] - b1m[j] * s + fb1[j] * s;
        }

        float d1[2][4][4];
#pragma unroll
        for (int mi = 0; mi < 2; mi++)
#pragma unroll
            for (int nf = 0; nf < 4; nf++)
#pragma unroll
                for (int q = 0; q < 4; q++) d1[mi][nf][q] = 0.f;

        for (int c = 0; c < 4; c++) {
            if (c < 3) cpW1(nt, c + 1, buf ^ 1);
            else       cpW2(nt, 0, buf ^ 1);
            CP_COMMIT(); CP_WAIT1();
            __syncthreads();

            const uint32_t wsb = sbase + M2_WB + (uint32_t)buf * 36864;
#pragma unroll
            for (int ks = 0; ks < 4; ks++) {
                const int k0 = ks * 16;
                const int kg = c * 64 + k0;
                uint32_t b0[4], b1[4];
                LDM_X4(b0, xs_base + (((uint32_t)(wx * 32)      + b_row) * 264 + kg + b_koff) * 2);
                LDM_X4(b1, xs_base + (((uint32_t)(wx * 32 + 16) + b_row) * 264 + kg + b_koff) * 2);
                uint32_t a[2][4];
#pragma unroll
                for (int mi = 0; mi < 2; mi++)
                    LDM_X4(a[mi], wsb + (((uint32_t)(wy * 32 + mi * 16) + a_row) * 72
                                          + k0 + a_koff) * 2);
#pragma unroll
                for (int mi = 0; mi < 2; mi++) {
                    MMA16816(d1[mi][0], a[mi], b0[0], b0[1]);
                    MMA16816(d1[mi][1], a[mi], b0[2], b0[3]);
                    MMA16816(d1[mi][2], a[mi], b1[0], b1[1]);
                    MMA16816(d1[mi][3], a[mi], b1[2], b1[3]);
                }
            }
            buf ^= 1;
            __syncthreads();
        }

        {
            int r = lane >> 2, c2l = (lane & 3) * 2;
#pragma unroll
            for (int mi = 0; mi < 2; mi++) {
                int j = wy * 32 + mi * 16 + r;
                float sj0 = s1[j],     tj0 = t1[j];
                float sj8 = s1[j + 8], tj8 = t1[j + 8];
#pragma unroll
                for (int nf = 0; nf < 4; nf++) {
                    int pos = wx * 32 + nf * 8 + c2l;
                    __half* h0 = (__half*)(smem + M2_HS + ((uint32_t)pos * 136 + j) * 2);
                    __half* h1 = (__half*)(smem + M2_HS + ((uint32_t)(pos + 1) * 136 + j) * 2);
                    h0[0] = __float2half(gelu_exact(d1[mi][nf][0] * sj0 + tj0));
                    h1[0] = __float2half(gelu_exact(d1[mi][nf][1] * sj0 + tj0));
                    h0[8] = __float2half(gelu_exact(d1[mi][nf][2] * sj8 + tj8));
                    h1[8] = __float2half(gelu_exact(d1[mi][nf][3] * sj8 + tj8));
                }
            }
        }

        for (int c = 0; c < 2; c++) {
            if (c == 0)        { cpW2(nt, 1, buf ^ 1); CP_COMMIT(); CP_WAIT1(); }
            else if (nt < 7)   { cpW1(nt + 1, 0, buf ^ 1); CP_COMMIT(); CP_WAIT1(); }
            else               { CP_WAIT0(); }
            __syncthreads();

            const uint32_t wsb = sbase + M2_WB + (uint32_t)buf * 36864;
#pragma unroll
            for (int ks = 0; ks < 4; ks++) {
                const int k0 = ks * 16;
                const int kg = c * 64 + k0;
                uint32_t b0[4], b1[4];
                LDM_X4(b0, hs_base + (((uint32_t)(wx * 32)      + b_row) * 136 + kg + b_koff) * 2);
                LDM_X4(b1, hs_base + (((uint32_t)(wx * 32 + 16) + b_row) * 136 + kg + b_koff) * 2);
                uint32_t a[4][4];
#pragma unroll
                for (int mi = 0; mi < 4; mi++)
                    LDM_X4(a[mi], wsb + (((uint32_t)(wy * 64 + mi * 16) + a_row) * 72
                                          + k0 + a_koff) * 2);
#pragma unroll
                for (int mi = 0; mi < 4; mi++) {
                    MMA16816(d2[mi][0], a[mi], b0[0], b0[1]);
                    MMA16816(d2[mi][1], a[mi], b0[2], b0[3]);
                    MMA16816(d2[mi][2], a[mi], b1[0], b1[1]);
                    MMA16816(d2[mi][3], a[mi], b1[2], b1[3]);
                }
            }
            buf ^= 1;
            __syncthreads();
        }
    }

    float* stage = (float*)(smem + M2_ST);
#pragma unroll
    for (int h = 0; h < 2; h++) {
        if ((wy >> 1) == h) {
            int r = lane >> 2, c2l = (lane & 3) * 2;
#pragma unroll
            for (int mi = 0; mi < 4; mi++) {
                int row = wy * 64 + mi * 16 + r - 128 * h;
#pragma unroll
                for (int nf = 0; nf < 4; nf++) {
                    int col = wx * 32 + nf * 8 + c2l;
                    stage[col * 129 + row]           = d2[mi][nf][0];
                    stage[(col + 1) * 129 + row]     = d2[mi][nf][1];
                    stage[col * 129 + row + 8]       = d2[mi][nf][2];
                    stage[(col + 1) * 129 + row + 8] = d2[mi][nf][3];
                }
            }
        }
        __syncthreads();
        for (int e = tid; e < 16384; e += 512) {
            int gl = e & 127, cl = e >> 7;
            int ch = 128 * h + cl;
            size_t idx = ((size_t)b * CDIM + ch) * TJ + p0 + gl;
            out[idx] = x1[idx] + stage[gl * 129 + cl] * s2[ch] + t2[ch];
        }
        __syncthreads();
    }
}

// ---------------------------------------------------------------------------
extern "C" void kernel_launch(void* const* d_in, const int* in_sizes, int n_in,
                              void* d_out, int out_size)
{
    const float* x    = (const float*)d_in[0];
    const float* n1g  = (const float*)d_in[1];
    const float* n1b  = (const float*)d_in[2];
    const float* n1m  = (const float*)d_in[3];
    const float* n1v  = (const float*)d_in[4];
    const float* qkvw = (const float*)d_in[5];
    const float* qg   = (const float*)d_in[6];
    const float* qb   = (const float*)d_in[7];
    const float* qm   = (const float*)d_in[8];
    const float* qv   = (const float*)d_in[9];
    const float* pw   = (const float*)d_in[10];
    const float* pb   = (const float*)d_in[11];
    const float* n2g  = (const float*)d_in[12];
    const float* n2b  = (const float*)d_in[13];
    const float* n2m  = (const float*)d_in[14];
    const float* n2v  = (const float*)d_in[15];
    const float* w1   = (const float*)d_in[16];
    const float* fb1  = (const float*)d_in[17];
    const float* b1g  = (const float*)d_in[18];
    const float* b1b  = (const float*)d_in[19];
    const float* b1m  = (const float*)d_in[20];
    const float* b1v  = (const float*)d_in[21];
    const float* w2   = (const float*)d_in[22];
    const float* fb2  = (const float*)d_in[23];
    const float* b2g  = (const float*)d_in[24];
    const float* b2b  = (const float*)d_in[25];
    const float* b2m  = (const float*)d_in[26];
    const float* b2v  = (const float*)d_in[27];
    float* out = (float*)d_out;

    cudaFuncSetAttribute(k_attn_mma,  cudaFuncAttributeMaxDynamicSharedMemorySize, AT_TOT);
    cudaFuncSetAttribute(k_conv_mma,  cudaFuncAttributeMaxDynamicSharedMemorySize, CV_TOT);
    cudaFuncSetAttribute(k_projc_mma, cudaFuncAttributeMaxDynamicSharedMemorySize, PC_TOT);
    cudaFuncSetAttribute(k_resize,    cudaFuncAttributeMaxDynamicSharedMemorySize, RZ_TOT);
    cudaFuncSetAttribute(k_mlp_mma2,  cudaFuncAttributeMaxDynamicSharedMemorySize, M2_TOT);

    k_prep_all<<<16384 + 4608, 512>>>(w1, w2, qkvw, pw, x, n1g, n1b, n1m, n1v);
    k_conv_mma<<<dim3(3, 129), 512, CV_TOT>>>(qg, qb, qm, qv);
    k_attn_mma<<<512, 544, AT_TOT>>>();
    k_projc_mma<<<129, 512, PC_TOT>>>();
    k_resize<<<dim3(34, 64), 256, RZ_TOT>>>(pb, x, out);
    k_mlp_mma2<<<1088, 512, M2_TOT>>>(out,
                                      b1g, b1b, b1m, b1v, fb1,
                                      b2g, b2b, b2m, b2v, fb2,
                                      n2g, n2b, n2m, n2v, out);
}

// round 16
// speedup vs baseline: 1.1348x; 1.0445x over previous
#include <cuda_runtime.h>
#include <cuda_fp16.h>
#include <math.h>
#include <stdint.h>

#define BATCH 64
#define CDIM 256
#define TDIM 128
#define JDIM 17
#define TJ 2176     // TDIM*JDIM
#define HCC 43
#define WCC 6
#define HW 258      // HCC*WCC
#define HIDDEN 1024

// scratch (static __device__ globals per harness rules)
__device__ __half g_qkv[(size_t)3 * BATCH * HW * CDIM];  // fp16 [b][t][hw][c]
__device__ __half g_att[(size_t)BATCH * HW * CDIM];      // fp16 [b][hw][c]
__device__ __half g_y[(size_t)BATCH * HW * CDIM];        // proj output (compressed grid)
__device__ __half g_xn[(size_t)BATCH * CDIM * TJ];       // n1bn(x) fp16
// fp16 weights
__device__ __half g_w1h[8 * 32768];            // W1 per-tile [128 j][256 i]
__device__ __half g_w2h[8 * 32768];            // W2 per-tile [256 c][128 j]
__device__ __half g_qwh[768 * 2304];           // qkv conv weight row-major
__device__ __half g_pwh[256 * 256];            // proj weight row-major

__device__ __forceinline__ float gelu_exact(float v) {
    return 0.5f * v * (1.0f + erff(v * 0.70710678118654752f));
}

__device__ __forceinline__ uint32_t smem_u32(const void* p) {
    uint32_t a;
    asm("{ .reg .u64 t; cvta.to.shared.u64 t, %1; cvt.u32.u64 %0, t; }" : "=r"(a) : "l"(p));
    return a;
}

__device__ __forceinline__ uint32_t h2_to_u32(__half2 h) {
    return *reinterpret_cast<uint32_t*>(&h);
}

#define LDM_X4(r, addr) \
    asm volatile("ldmatrix.sync.aligned.m8n8.x4.shared.b16 {%0,%1,%2,%3}, [%4];" \
        : "=r"((r)[0]), "=r"((r)[1]), "=r"((r)[2]), "=r"((r)[3]) : "r"(addr))

#define LDM_X4_T(r, addr) \
    asm volatile("ldmatrix.sync.aligned.m8n8.x4.trans.shared.b16 {%0,%1,%2,%3}, [%4];" \
        : "=r"((r)[0]), "=r"((r)[1]), "=r"((r)[2]), "=r"((r)[3]) : "r"(addr))

#define MMA16816(d, a, b0, b1) \
    asm volatile("mma.sync.aligned.m16n8k16.row.col.f32.f16.f16.f32 " \
        "{%0,%1,%2,%3}, {%4,%5,%6,%7}, {%8,%9}, {%0,%1,%2,%3};" \
        : "+f"((d)[0]), "+f"((d)[1]), "+f"((d)[2]), "+f"((d)[3]) \
        : "r"((a)[0]), "r"((a)[1]), "r"((a)[2]), "r"((a)[3]), "r"(b0), "r"(b1))

#define CP_ASYNC16(dst, src) \
    asm volatile("cp.async.cg.shared.global [%0], [%1], 16;" :: "r"(dst), "l"(src))
#define CP_COMMIT() asm volatile("cp.async.commit_group;")
#define CP_WAIT1()  asm volatile("cp.async.wait_group 1;" ::: "memory")
#define CP_WAIT0()  asm volatile("cp.async.wait_group 0;" ::: "memory")

// ---------------------------------------------------------------------------
// K0: merged prep — blocks [0,16384): xn = n1bn(x) fp16; rest: weight convert
// ---------------------------------------------------------------------------
__global__ void __launch_bounds__(512) k_prep_all(
    const float* __restrict__ w1, const float* __restrict__ w2,
    const float* __restrict__ qkvw, const float* __restrict__ pw,
    const float* __restrict__ x,
    const float* __restrict__ n1g, const float* __restrict__ n1b,
    const float* __restrict__ n1m, const float* __restrict__ n1v)
{
    const int blk = blockIdx.x;
    if (blk < 16384) {
        __shared__ float ss, tt;
        const int c = blk & 255;
        if (threadIdx.x == 0) {
            float s = n1g[c] * rsqrtf(n1v[c] + 1e-5f);
            ss = s;
            tt = n1b[c] - n1m[c] * s;
        }
        __syncthreads();
        const float* xr = x + (size_t)blk * TJ;
        __half* xo = g_xn + (size_t)blk * TJ;
        float s = ss, t = tt;
        for (int p = threadIdx.x; p < TJ; p += 512)
            xo[p] = __float2half(xr[p] * s + t);
        return;
    }
    int idx = (blk - 16384) * 512 + threadIdx.x;
    if (idx < 262144) {
        int j = idx >> 8, i = idx & 255;
        int nt = j >> 7, jl = j & 127;
        g_w1h[(uint32_t)nt * 32768 + (uint32_t)jl * 256 + i] = __float2half(w1[idx]);
    } else if (idx < 524288) {
        int t = idx - 262144;
        int c = t >> 10, j = t & 1023;
        int nt = j >> 7, jl = j & 127;
        g_w2h[(uint32_t)nt * 32768 + (uint32_t)c * 128 + jl] = __float2half(w2[t]);
    } else if (idx < 2293760) {
        int t = idx - 524288;
        g_qwh[t] = __float2half(qkvw[t]);
    } else {
        int t = idx - 2293760;
        g_pwh[t] = __float2half(pw[t]);
    }
}

// ---------------------------------------------------------------------------
// K1: conv QKV on HMMA (unchanged)
// ---------------------------------------------------------------------------
#define CV_KTAB  0
#define CV_SO    4608
#define CV_TO    5632
#define CV_PBUF  6656
#define CV_WBUF  76288
#define CV_STAGE CV_PBUF
#define CV_TOT   215552

__global__ void __launch_bounds__(512, 1) k_conv_mma(
    const float* __restrict__ qg, const float* __restrict__ qb,
    const float* __restrict__ qm, const float* __restrict__ qv)
{
    extern __shared__ char smem[];
    const uint32_t sbase = smem_u32(smem);
    const int tid = threadIdx.x;
    const int wid = tid >> 5, lane = tid & 31;
    const int wy = wid & 3, wx = wid >> 2;

    const int m0 = blockIdx.x * 256;
    const int n0 = blockIdx.y * 128;

    uint16_t* ktab = (uint16_t*)(smem + CV_KTAB);
    float*    s_o  = (float*)(smem + CV_SO);
    float*    t_o  = (float*)(smem + CV_TO);

    if (tid < 256) {
        int o = m0 + tid;
        float s = qg[o] * rsqrtf(qv[o] + 1e-5f);
        s_o[tid] = s;
        t_o[tid] = qb[o] - qm[o] * s;
    }
    for (int k = tid; k < 2304; k += 512) {
        int i = k / 9, r = k - i * 9;
        int ky = r / 3, kx = r - ky * 3;
        ktab[k] = (uint16_t)((i << 4) | (ky << 2) | kx);
    }
    __syncthreads();

    const int gl    = tid & 127;
    const int kslot = tid >> 7;
    int p_xo, p_iy, p_ix;
    {
        int g = n0 + gl;
        int b = g / HW, hw = g - b * HW;
        int y = hw / WCC, xx = hw - y * WCC;
        p_xo = b * (CDIM * TJ);
        p_iy = 3 * y - 1;
        p_ix = 3 * xx - 1;
    }

    const uint32_t a_row  = (lane & 7) + ((lane >> 3) & 1) * 8;
    const uint32_t a_koff = (lane >> 4) * 8;
    const uint32_t b_row  = (lane & 7) + (lane >> 4) * 8;
    const uint32_t b_koff = ((lane >> 3) & 1) * 8;

    __align__(16) unsigned short pv[32];

    auto cpW = [&](int kc, int bsel) {
        uint32_t dstb = sbase + CV_WBUF + (uint32_t)bsel * 69632;
#pragma unroll
        for (int t = 0; t < 8; t++) {
            int e = tid + t * 512;
            int row = e >> 4, col = e & 15;
            CP_ASYNC16(dstb + ((uint32_t)row * 136 + col * 8) * 2,
                       (const void*)(g_qwh + (size_t)(m0 + row) * 2304 + kc + col * 8));
        }
    };
    auto gatherP = [&](int kc) {
        const int kb = kc + kslot * 32;
#pragma unroll
        for (int t = 0; t < 32; t++) {
            uint32_t kt = ktab[kb + t];
            int i = kt >> 4, ky = (kt >> 2) & 3, kx = kt & 3;
            int iy = p_iy + ky, ix = p_ix + kx;
            unsigned short v = 0;
            if ((unsigned)iy < (unsigned)TDIM && (unsigned)ix < (unsigned)JDIM)
                v = *(const unsigned short*)&g_xn[p_xo + i * TJ + iy * JDIM + ix];
            pv[t] = v;
        }
    };
    auto storeP = [&](int bsel) {
        char* pb2 = smem + CV_PBUF + bsel * 34816;
        uint32_t off = ((uint32_t)gl * 136 + kslot * 32) * 2;
#pragma unroll
        for (int j = 0; j < 4; j++)
            *(uint4*)(pb2 + off + j * 16) = ((const uint4*)pv)[j];
    };

    float d[4][4][4];
#pragma unroll
    for (int mi = 0; mi < 4; mi++)
#pragma unroll
        for (int nf = 0; nf < 4; nf++)
#pragma unroll
            for (int q = 0; q < 4; q++) d[mi][nf][q] = 0.f;

    cpW(0, 0); CP_COMMIT();
    gatherP(0); storeP(0);

    for (int c = 0; c < 18; c++) {
        if (c < 17) {
            cpW((c + 1) * 128, (c + 1) & 1); CP_COMMIT();
            gatherP((c + 1) * 128);
            CP_WAIT1();
        } else {
            CP_WAIT0();
        }
        __syncthreads();

        const uint32_t wsb = sbase + CV_WBUF + (uint32_t)(c & 1) * 69632;
        const uint32_t psb = sbase + CV_PBUF + (uint32_t)(c & 1) * 34816;
#pragma unroll
        for (int ks = 0; ks < 8; ks++) {
            const int k0 = ks * 16;
            uint32_t b0[4], b1[4];
            LDM_X4(b0, psb + (((uint32_t)(wx * 32)      + b_row) * 136 + k0 + b_koff) * 2);
            LDM_X4(b1, psb + (((uint32_t)(wx * 32 + 16) + b_row) * 136 + k0 + b_koff) * 2);
            uint32_t a[4][4];
#pragma unroll
            for (int mi = 0; mi < 4; mi++)
                LDM_X4(a[mi], wsb + (((uint32_t)(wy * 64 + mi * 16) + a_row) * 136
                                      + k0 + a_koff) * 2);
#pragma unroll
            for (int mi = 0; mi < 4; mi++) {
                MMA16816(d[mi][0], a[mi], b0[0], b0[1]);
                MMA16816(d[mi][1], a[mi], b0[2], b0[3]);
                MMA16816(d[mi][2], a[mi], b1[0], b1[1]);
                MMA16816(d[mi][3], a[mi], b1[2], b1[3]);
            }
        }
        if (c < 17) storeP((c + 1) & 1);
        __syncthreads();
    }

    float* stage = (float*)(smem + CV_STAGE);
    const int tpart = blockIdx.x;
#pragma unroll
    for (int h = 0; h < 2; h++) {
        if ((wy >> 1) == h) {
            int r = lane >> 2, c2 = (lane & 3) * 2;
#pragma unroll
            for (int mi = 0; mi < 4; mi++) {
                int row = wy * 64 + mi * 16 + r - 128 * h;
#pragma unroll
                for (int nf = 0; nf < 4; nf++) {
                    int col = wx * 32 + nf * 8 + c2;
                    stage[col * 129 + row]           = d[mi][nf][0];
                    stage[(col + 1) * 129 + row]     = d[mi][nf][1];
                    stage[col * 129 + row + 8]       = d[mi][nf][2];
                    stage[(col + 1) * 129 + row + 8] = d[mi][nf][3];
                }
            }
        }
        __syncthreads();
        for (int e = tid; e < 16384; e += 512) {
            int gl2 = e >> 7, cl = e & 127;
            int g = n0 + gl2;
            int b = g / HW, hw = g - b * HW;
            int ch = 128 * h + cl;
            float v = stage[gl2 * 129 + cl] * s_o[ch] + t_o[ch];
            g_qkv[(((size_t)b * 3 + tpart) * HW + hw) * CDIM + ch]
                = __float2half(gelu_exact(v));
        }
        __syncthreads();
    }
}

// ---------------------------------------------------------------------------
// K2: attention on HMMA (unchanged)
// ---------------------------------------------------------------------------
#define AT_STR  40
#define AT_Q    0
#define AT_K    21760
#define AT_V    43520
#define AT_TOT  65280

__global__ void __launch_bounds__(544) k_attn_mma()
{
    extern __shared__ char smem[];
    const uint32_t sbase = smem_u32(smem);
    __half* qs = (__half*)(smem + AT_Q);
    __half* ks = (__half*)(smem + AT_K);
    __half* vs = (__half*)(smem + AT_V);

    const int bh = blockIdx.x;
    const int b = bh >> 3, h = bh & 7;
    const int tid = threadIdx.x;
    const int wid = tid >> 5, lane = tid & 31;

    const __half* qg = g_qkv + (((size_t)b * 3 + 0) * HW) * CDIM + h * 32;
    const __half* kg = g_qkv + (((size_t)b * 3 + 1) * HW) * CDIM + h * 32;
    const __half* vg = g_qkv + (((size_t)b * 3 + 2) * HW) * CDIM + h * 32;

    const __half2 sc2 = __float2half2_rn(0.17677669529663687f);
    for (int e = tid; e < 272 * 4; e += 544) {
        int r = e >> 2, d8 = (e & 3) * 8;
        uint4 q4 = make_uint4(0, 0, 0, 0), k4 = q4, v4 = q4;
        if (r < HW) {
            size_t off = (size_t)r * CDIM + d8;
            q4 = *(const uint4*)(qg + off);
            k4 = *(const uint4*)(kg + off);
            v4 = *(const uint4*)(vg + off);
        }
        __half2* qh = (__half2*)&q4;
#pragma unroll
        for (int j = 0; j < 4; j++) qh[j] = __hmul2(qh[j], sc2);
        *(uint4*)(qs + r * AT_STR + d8) = q4;
        *(uint4*)(ks + r * AT_STR + d8) = k4;
        *(uint4*)(vs + r * AT_STR + d8) = v4;
    }
    __syncthreads();

    const int m0 = wid * 16;
    const uint32_t a_row  = (lane & 7) + ((lane >> 3) & 1) * 8;
    const uint32_t a_koff = (lane >> 4) * 8;
    const uint32_t b_row  = (lane & 7) + (lane >> 4) * 8;
    const uint32_t b_koff = ((lane >> 3) & 1) * 8;
    const uint32_t v_row  = (lane & 7) + ((lane >> 3) & 1) * 8;
    const uint32_t v_col  = (lane >> 4) * 8;

    const uint32_t qs_base = sbase + AT_Q;
    const uint32_t ks_base = sbase + AT_K;
    const uint32_t vs_base = sbase + AT_V;

    uint32_t qa[2][4];
    LDM_X4(qa[0], qs_base + (((uint32_t)m0 + a_row) * AT_STR + 0  + a_koff) * 2);
    LDM_X4(qa[1], qs_base + (((uint32_t)m0 + a_row) * AT_STR + 16 + a_koff) * 2);

    float o[4][4];
#pragma unroll
    for (int nt = 0; nt < 4; nt++)
#pragma unroll
        for (int q = 0; q < 4; q++) o[nt][q] = 0.f;
    float mr = -1e30f, mr8 = -1e30f, lr = 0.f, lr8 = 0.f;

    const int c2 = (lane & 3) * 2;

    for (int jt = 0; jt < 17; jt++) {
        float s0[4] = {0.f, 0.f, 0.f, 0.f};
        float s1[4] = {0.f, 0.f, 0.f, 0.f};
        {
            uint32_t bb[4];
            LDM_X4(bb, ks_base + (((uint32_t)(jt * 16) + b_row) * AT_STR + 0 + b_koff) * 2);
            MMA16816(s0, qa[0], bb[0], bb[1]);
            MMA16816(s1, qa[0], bb[2], bb[3]);
            LDM_X4(bb, ks_base + (((uint32_t)(jt * 16) + b_row) * AT_STR + 16 + b_koff) * 2);
            MMA16816(s0, qa[1], bb[0], bb[1]);
            MMA16816(s1, qa[1], bb[2], bb[3]);
        }
        if (jt == 16) {
            if (256 + c2     >= HW) { s0[0] = -1e30f; s0[2] = -1e30f; }
            if (256 + c2 + 1 >= HW) { s0[1] = -1e30f; s0[3] = -1e30f; }
            if (256 + c2 + 8 >= HW) { s1[0] = -1e30f; s1[2] = -1e30f; }
            if (256 + c2 + 9 >= HW) { s1[1] = -1e30f; s1[3] = -1e30f; }
        }

        float cmr  = fmaxf(fmaxf(s0[0], s0[1]), fmaxf(s1[0], s1[1]));
        float cmr8 = fmaxf(fmaxf(s0[2], s0[3]), fmaxf(s1[2], s1[3]));
        cmr  = fmaxf(cmr,  __shfl_xor_sync(0xffffffffu, cmr, 1));
        cmr  = fmaxf(cmr,  __shfl_xor_sync(0xffffffffu, cmr, 2));
        cmr8 = fmaxf(cmr8, __shfl_xor_sync(0xffffffffu, cmr8, 1));
        cmr8 = fmaxf(cmr8, __shfl_xor_sync(0xffffffffu, cmr8, 2));
        float mnr  = fmaxf(mr, cmr);
        float mnr8 = fmaxf(mr8, cmr8);
        float corr  = __expf(mr - mnr);
        float corr8 = __expf(mr8 - mnr8);
        float p00 = __expf(s0[0] - mnr),  p01 = __expf(s0[1] - mnr);
        float p02 = __expf(s1[0] - mnr),  p03 = __expf(s1[1] - mnr);
        float p80 = __expf(s0[2] - mnr8), p81 = __expf(s0[3] - mnr8);
        float p82 = __expf(s1[2] - mnr8), p83 = __expf(s1[3] - mnr8);
        float ps  = p00 + p01 + p02 + p03;
        float ps8 = p80 + p81 + p82 + p83;
        ps  += __shfl_xor_sync(0xffffffffu, ps, 1);
        ps  += __shfl_xor_sync(0xffffffffu, ps, 2);
        ps8 += __shfl_xor_sync(0xffffffffu, ps8, 1);
        ps8 += __shfl_xor_sync(0xffffffffu, ps8, 2);
        lr  = lr  * corr  + ps;
        lr8 = lr8 * corr8 + ps8;
        mr = mnr; mr8 = mnr8;

        uint32_t pa[4];
        pa[0] = h2_to_u32(__floats2half2_rn(p00, p01));
        pa[1] = h2_to_u32(__floats2half2_rn(p80, p81));
        pa[2] = h2_to_u32(__floats2half2_rn(p02, p03));
        pa[3] = h2_to_u32(__floats2half2_rn(p82, p83));

#pragma unroll
        for (int nt = 0; nt < 4; nt++) {
            o[nt][0] *= corr;  o[nt][1] *= corr;
            o[nt][2] *= corr8; o[nt][3] *= corr8;
        }

        {
            uint32_t vb[4];
            LDM_X4_T(vb, vs_base + (((uint32_t)(jt * 16) + v_row) * AT_STR + 0 + v_col) * 2);
            MMA16816(o[0], pa, vb[0], vb[1]);
            MMA16816(o[1], pa, vb[2], vb[3]);
            LDM_X4_T(vb, vs_base + (((uint32_t)(jt * 16) + v_row) * AT_STR + 16 + v_col) * 2);
            MMA16816(o[2], pa, vb[0], vb[1]);
            MMA16816(o[3], pa, vb[2], vb[3]);
        }
    }

    const int r0 = m0 + (lane >> 2);
    float invr  = 1.f / lr;
    float invr8 = 1.f / lr8;
    if (r0 < HW) {
        __half* og = g_att + ((size_t)b * HW + r0) * CDIM + h * 32 + c2;
#pragma unroll
        for (int nt = 0; nt < 4; nt++)
            *(__half2*)(og + nt * 8) = __floats2half2_rn(o[nt][0] * invr, o[nt][1] * invr);
    }
    if (r0 + 8 < HW) {
        __half* og = g_att + ((size_t)b * HW + r0 + 8) * CDIM + h * 32 + c2;
#pragma unroll
        for (int nt = 0; nt < 4; nt++)
            *(__half2*)(og + nt * 8) = __floats2half2_rn(o[nt][2] * invr8, o[nt][3] * invr8);
    }
}

// ---------------------------------------------------------------------------
// K3a: proj on COMPRESSED grid (unchanged)
// ---------------------------------------------------------------------------
#define PC_WS    0
#define PC_PS    135168
#define PC_STAGE PC_PS
#define PC_TOT   202752

__global__ void __launch_bounds__(512, 1) k_projc_mma()
{
    extern __shared__ char smem[];
    const uint32_t sbase = smem_u32(smem);
    const int tid = threadIdx.x;
    const int wid = tid >> 5, lane = tid & 31;
    const int wy = wid & 3, wx = wid >> 2;

    const int n0 = blockIdx.x * 128;

    {
        uint32_t ws = sbase + PC_WS;
#pragma unroll
        for (int t = 0; t < 16; t++) {
            int e = tid + t * 512;
            int row = e >> 5, col = e & 31;
            CP_ASYNC16(ws + ((uint32_t)row * 264 + col * 8) * 2,
                       (const void*)(g_pwh + (size_t)row * 256 + col * 8));
        }
    }
    {
        uint32_t ps = sbase + PC_PS;
#pragma unroll
        for (int t = 0; t < 8; t++) {
            int e = tid + t * 512;
            int gl = e >> 5, col = e & 31;
            CP_ASYNC16(ps + ((uint32_t)gl * 264 + col * 8) * 2,
                       (const void*)(g_att + (size_t)(n0 + gl) * 256 + col * 8));
        }
    }
    CP_COMMIT(); CP_WAIT0();
    __syncthreads();

    const uint32_t a_row  = (lane & 7) + ((lane >> 3) & 1) * 8;
    const uint32_t a_koff = (lane >> 4) * 8;
    const uint32_t b_row  = (lane & 7) + (lane >> 4) * 8;
    const uint32_t b_koff = ((lane >> 3) & 1) * 8;
    const uint32_t ps_base = sbase + PC_PS;
    const uint32_t ws_base = sbase + PC_WS;

    float d[4][4][4];
#pragma unroll
    for (int mi = 0; mi < 4; mi++)
#pragma unroll
        for (int nf = 0; nf < 4; nf++)
#pragma unroll
            for (int q = 0; q < 4; q++) d[mi][nf][q] = 0.f;

#pragma unroll 4
    for (int k0 = 0; k0 < 256; k0 += 16) {
        uint32_t b0[4], b1[4];
        LDM_X4(b0, ps_base + (((uint32_t)(wx * 32)      + b_row) * 264 + k0 + b_koff) * 2);
        LDM_X4(b1, ps_base + (((uint32_t)(wx * 32 + 16) + b_row) * 264 + k0 + b_koff) * 2);
        uint32_t a[4][4];
#pragma unroll
        for (int mi = 0; mi < 4; mi++)
            LDM_X4(a[mi], ws_base + (((uint32_t)(wy * 64 + mi * 16) + a_row) * 264
                                      + k0 + a_koff) * 2);
#pragma unroll
        for (int mi = 0; mi < 4; mi++) {
            MMA16816(d[mi][0], a[mi], b0[0], b0[1]);
            MMA16816(d[mi][1], a[mi], b0[2], b0[3]);
            MMA16816(d[mi][2], a[mi], b1[0], b1[1]);
            MMA16816(d[mi][3], a[mi], b1[2], b1[3]);
        }
    }
    __syncthreads();

    float* stage = (float*)(smem + PC_STAGE);
#pragma unroll
    for (int h = 0; h < 2; h++) {
        if ((wy >> 1) == h) {
            int r = lane >> 2, c2 = (lane & 3) * 2;
#pragma unroll
            for (int mi = 0; mi < 4; mi++) {
                int row = wy * 64 + mi * 16 + r - 128 * h;
#pragma unroll
                for (int nf = 0; nf < 4; nf++) {
                    int col = wx * 32 + nf * 8 + c2;
                    stage[col * 129 + row]           = d[mi][nf][0];
                    stage[(col + 1) * 129 + row]     = d[mi][nf][1];
                    stage[col * 129 + row + 8]       = d[mi][nf][2];
                    stage[(col + 1) * 129 + row + 8] = d[mi][nf][3];
                }
            }
        }
        __syncthreads();
        for (int e = tid; e < 16384; e += 512) {
            int cl = e & 127, gl = e >> 7;
            g_y[(size_t)(n0 + gl) * 256 + 128 * h + cl]
                = __float2half(stage[gl * 129 + cl]);
        }
        __syncthreads();
    }
}

// ---------------------------------------------------------------------------
// K3b: resize epilogue (unchanged from round 15)
// ---------------------------------------------------------------------------
#define RZ_O00  0
#define RZ_O01  256
#define RZ_O10  512
#define RZ_O11  768
#define RZ_WX   1024
#define RZ_WY   1280
#define RZ_PB   1536
#define RZ_ST   2560
#define RZ_TOT  35584

__global__ void __launch_bounds__(256) k_resize(
    const float* __restrict__ pb,
    const float* __restrict__ x, float* __restrict__ x1)
{
    extern __shared__ char smem[];
    const int tid = threadIdx.x;
    const int b  = blockIdx.y;
    const int p0 = blockIdx.x * 64;

    int*   o00 = (int*)(smem + RZ_O00);
    int*   o01 = (int*)(smem + RZ_O01);
    int*   o10 = (int*)(smem + RZ_O10);
    int*   o11 = (int*)(smem + RZ_O11);
    float* wxs = (float*)(smem + RZ_WX);
    float* wys = (float*)(smem + RZ_WY);
    float* pbs = (float*)(smem + RZ_PB);
    __half* stage = (__half*)(smem + RZ_ST);

    if (tid < 64) {
        int p = p0 + tid;
        int t = p / JDIM, j = p - t * JDIM;
        float sy = (t + 0.5f) * (43.0f / 128.0f) - 0.5f;
        sy = fminf(fmaxf(sy, 0.f), 42.f);
        int y0 = (int)sy;
        int y1 = min(y0 + 1, 42);
        float fy = sy - y0;
        float sx = (j + 0.5f) * (6.0f / 17.0f) - 0.5f;
        sx = fminf(fmaxf(sx, 0.f), 5.f);
        int x0 = (int)sx;
        int x1i = min(x0 + 1, 5);
        float fx = sx - x0;
        o00[tid] = (y0 * WCC + x0) * CDIM;
        o01[tid] = (y0 * WCC + x1i) * CDIM;
        o10[tid] = (y1 * WCC + x0) * CDIM;
        o11[tid] = (y1 * WCC + x1i) * CDIM;
        wxs[tid] = fx;
        wys[tid] = fy;
    }
    pbs[tid] = pb[tid];
    __syncthreads();

    const __half* yb = g_y + (size_t)b * HW * CDIM;
    for (int e = tid; e < 16384; e += 256) {
        int c = e & 255, gl = e >> 8;
        const __half* bp = yb + c;
        float fx = wxs[gl], fy = wys[gl];
        float a00 = __half2float(bp[o00[gl]]);
        float a01 = __half2float(bp[o01[gl]]);
        float a10 = __half2float(bp[o10[gl]]);
        float a11 = __half2float(bp[o11[gl]]);
        float v = (a00 * (1.f - fx) + a01 * fx) * (1.f - fy)
                + (a10 * (1.f - fx) + a11 * fx) * fy;
        stage[gl * 258 + c] = __float2half(v);
    }
    __syncthreads();

    for (int e = tid; e < 16384; e += 256) {
        int ch = e >> 6, gl = e & 63;
        size_t idx = ((size_t)b * CDIM + ch) * TJ + p0 + gl;
        x1[idx] = x[idx] + __half2float(stage[gl * 258 + ch]) + pbs[ch];
    }
}

// ---------------------------------------------------------------------------
// K4: fused MLP on HMMA — coalesced Xn fill + hoisted bn1 table
// ---------------------------------------------------------------------------
#define M2_SN   0
#define M2_TN   1024
#define M2_S2   2048
#define M2_T2   3072
#define M2_S1   4096                     // float[1024] = 4096
#define M2_T1   8192                     // float[1024] = 4096
#define M2_XS   12288                    // [128 pos][264] half = 67584
#define M2_HS   79872                    // [128 pos][136] half = 34816
#define M2_WB   114688                   // 2 x 36864 = 73728
#define M2_ST   M2_XS
#define M2_TOT  188416

__global__ void __launch_bounds__(512, 1) k_mlp_mma2(
    const float* x1,
    const float* __restrict__ b1g, const float* __restrict__ b1b,
    const float* __restrict__ b1m, const float* __restrict__ b1v,
    const float* __restrict__ fb1,
    const float* __restrict__ b2g, const float* __restrict__ b2b,
    const float* __restrict__ b2m, const float* __restrict__ b2v,
    const float* __restrict__ fb2,
    const float* __restrict__ n2g, const float* __restrict__ n2b,
    const float* __restrict__ n2m, const float* __restrict__ n2v,
    float* out)
{
    extern __shared__ char smem[];
    const uint32_t sbase = smem_u32(smem);
    const int tid = threadIdx.x;
    const int wid = tid >> 5, lane = tid & 31;
    const int wy = wid & 3, wx = wid >> 2;

    const int b  = blockIdx.x / 17;
    const int p0 = (blockIdx.x - b * 17) * 128;

    float* sn = (float*)(smem + M2_SN);
    float* tn = (float*)(smem + M2_TN);
    float* s2 = (float*)(smem + M2_S2);
    float* t2 = (float*)(smem + M2_T2);
    float* s1 = (float*)(smem + M2_S1);   // [1024]
    float* t1 = (float*)(smem + M2_T1);   // [1024]

    auto cpW1 = [&](int nt, int c, int bsel) {
        uint32_t dstb = sbase + M2_WB + (uint32_t)bsel * 36864;
        const __half* src = g_w1h + nt * 32768 + c * 64;
#pragma unroll
        for (int t = 0; t < 2; t++) {
            int e = tid + t * 512;
            int row = e >> 3, col = e & 7;
            CP_ASYNC16(dstb + ((uint32_t)row * 72 + col * 8) * 2,
                       (const void*)(src + (size_t)row * 256 + col * 8));
        }
    };
    auto cpW2 = [&](int nt, int c, int bsel) {
        uint32_t dstb = sbase + M2_WB + (uint32_t)bsel * 36864;
        const __half* src = g_w2h + nt * 32768 + c * 64;
#pragma unroll
        for (int t = 0; t < 4; t++) {
            int e = tid + t * 512;
            int row = e >> 3, col = e & 7;
            CP_ASYNC16(dstb + ((uint32_t)row * 72 + col * 8) * 2,
                       (const void*)(src + (size_t)row * 128 + col * 8));
        }
    };

    cpW1(0, 0, 0); CP_COMMIT();

    if (tid < 256) {
        float s = n2g[tid] * rsqrtf(n2v[tid] + 1e-5f);
        sn[tid] = s;
        tn[tid] = n2b[tid] - n2m[tid] * s;
    } else {
        int c = tid - 256;
        float s = b2g[c] * rsqrtf(b2v[c] + 1e-5f);
        s2[c] = s;
        t2[c] = b2b[c] - b2m[c] * s + fb2[c] * s;
    }
    // bn1 fold: all 1024 hidden channels once
    for (int j = tid; j < HIDDEN; j += 512) {
        float s = b1g[j] * rsqrtf(b1v[j] + 1e-5f);
        s1[j] = s;
        t1[j] = b1b[j] - b1m[j] * s + fb1[j] * s;
    }
    __syncthreads();

    // coalesced Xn fill: consecutive lanes -> consecutive positions
    const float* xb = x1 + (size_t)b * CDIM * TJ;
    for (int e = tid; e < 32768; e += 512) {
        int p = e & 127, i = e >> 7;
        float v = xb[(size_t)i * TJ + p0 + p] * sn[i] + tn[i];
        *(__half*)(smem + M2_XS + ((uint32_t)p * 264 + i) * 2) = __float2half(v);
    }

    const uint32_t a_row  = (lane & 7) + ((lane >> 3) & 1) * 8;
    const uint32_t a_koff = (lane >> 4) * 8;
    const uint32_t b_row  = (lane & 7) + (lane >> 4) * 8;
    const uint32_t b_koff = ((lane >> 3) & 1) * 8;

    const uint32_t xs_base = sbase + M2_XS;
    const uint32_t hs_base = sbase + M2_HS;

    float d2[4][4][4];
#pragma unroll
    for (int mi = 0; mi < 4; mi++)
#pragma unroll
        for (int nf = 0; nf < 4; nf++)
#pragma unroll
            for (int q = 0; q < 4; q++) d2[mi][nf][q] = 0.f;

    int buf = 0;

    for (int nt = 0; nt < 8; nt++) {
        float d1[2][4][4];
#pragma unroll
        for (int mi = 0; mi < 2; mi++)
#pragma unroll
            for (int nf = 0; nf < 4; nf++)
#pragma unroll
                for (int q = 0; q < 4; q++) d1[mi][nf][q] = 0.f;

        for (int c = 0; c < 4; c++) {
            if (c < 3) cpW1(nt, c + 1, buf ^ 1);
            else       cpW2(nt, 0, buf ^ 1);
            CP_COMMIT(); CP_WAIT1();
            __syncthreads();

            const uint32_t wsb = sbase + M2_WB + (uint32_t)buf * 36864;
#pragma unroll
            for (int ks = 0; ks < 4; ks++) {
                const int k0 = ks * 16;
                const int kg = c * 64 + k0;
                uint32_t b0[4], b1[4];
                LDM_X4(b0, xs_base + (((uint32_t)(wx * 32)      + b_row) * 264 + kg + b_koff) * 2);
                LDM_X4(b1, xs_base + (((uint32_t)(wx * 32 + 16) + b_row) * 264 + kg + b_koff) * 2);
                uint32_t a[2][4];
#pragma unroll
                for (int mi = 0; mi < 2; mi++)
                    LDM_X4(a[mi], wsb + (((uint32_t)(wy * 32 + mi * 16) + a_row) * 72
                                          + k0 + a_koff) * 2);
#pragma unroll
                for (int mi = 0; mi < 2; mi++) {
                    MMA16816(d1[mi][0], a[mi], b0[0], b0[1]);
                    MMA16816(d1[mi][1], a[mi], b0[2], b0[3]);
                    MMA16816(d1[mi][2], a[mi], b1[0], b1[1]);
                    MMA16816(d1[mi][3], a[mi], b1[2], b1[3]);
                }
            }
            buf ^= 1;
            __syncthreads();
        }

        {
            int r = lane >> 2, c2l = (lane & 3) * 2;
#pragma unroll
            for (int mi = 0; mi < 2; mi++) {
                int j = wy * 32 + mi * 16 + r;
                float sj0 = s1[nt * 128 + j],     tj0 = t1[nt * 128 + j];
                float sj8 = s1[nt * 128 + j + 8], tj8 = t1[nt * 128 + j + 8];
#pragma unroll
                for (int nf = 0; nf < 4; nf++) {
                    int pos = wx * 32 + nf * 8 + c2l;
                    __half* h0 = (__half*)(smem + M2_HS + ((uint32_t)pos * 136 + j) * 2);
                    __half* h1 = (__half*)(smem + M2_HS + ((uint32_t)(pos + 1) * 136 + j) * 2);
                    h0[0] = __float2half(gelu_exact(d1[mi][nf][0] * sj0 + tj0));
                    h1[0] = __float2half(gelu_exact(d1[mi][nf][1] * sj0 + tj0));
                    h0[8] = __float2half(gelu_exact(d1[mi][nf][2] * sj8 + tj8));
                    h1[8] = __float2half(gelu_exact(d1[mi][nf][3] * sj8 + tj8));
                }
            }
        }

        for (int c = 0; c < 2; c++) {
            if (c == 0)        { cpW2(nt, 1, buf ^ 1); CP_COMMIT(); CP_WAIT1(); }
            else if (nt < 7)   { cpW1(nt + 1, 0, buf ^ 1); CP_COMMIT(); CP_WAIT1(); }
            else               { CP_WAIT0(); }
            __syncthreads();

            const uint32_t wsb = sbase + M2_WB + (uint32_t)buf * 36864;
#pragma unroll
            for (int ks = 0; ks < 4; ks++) {
                const int k0 = ks * 16;
                const int kg = c * 64 + k0;
                uint32_t b0[4], b1[4];
                LDM_X4(b0, hs_base + (((uint32_t)(wx * 32)      + b_row) * 136 + kg + b_koff) * 2);
                LDM_X4(b1, hs_base + (((uint32_t)(wx * 32 + 16) + b_row) * 136 + kg + b_koff) * 2);
                uint32_t a[4][4];
#pragma unroll
                for (int mi = 0; mi < 4; mi++)
                    LDM_X4(a[mi], wsb + (((uint32_t)(wy * 64 + mi * 16) + a_row) * 72
                                          + k0 + a_koff) * 2);
#pragma unroll
                for (int mi = 0; mi < 4; mi++) {
                    MMA16816(d2[mi][0], a[mi], b0[0], b0[1]);
                    MMA16816(d2[mi][1], a[mi], b0[2], b0[3]);
                    MMA16816(d2[mi][2], a[mi], b1[0], b1[1]);
                    MMA16816(d2[mi][3], a[mi], b1[2], b1[3]);
                }
            }
            buf ^= 1;
            __syncthreads();
        }
    }

    float* stage = (float*)(smem + M2_ST);
#pragma unroll
    for (int h = 0; h < 2; h++) {
        if ((wy >> 1) == h) {
            int r = lane >> 2, c2l = (lane & 3) * 2;
#pragma unroll
            for (int mi = 0; mi < 4; mi++) {
                int row = wy * 64 + mi * 16 + r - 128 * h;
#pragma unroll
                for (int nf = 0; nf < 4; nf++) {
                    int col = wx * 32 + nf * 8 + c2l;
                    stage[col * 129 + row]           = d2[mi][nf][0];
                    stage[(col + 1) * 129 + row]     = d2[mi][nf][1];
                    stage[col * 129 + row + 8]       = d2[mi][nf][2];
                    stage[(col + 1) * 129 + row + 8] = d2[mi][nf][3];
                }
            }
        }
        __syncthreads();
        for (int e = tid; e < 16384; e += 512) {
            int gl = e & 127, cl = e >> 7;
            int ch = 128 * h + cl;
            size_t idx = ((size_t)b * CDIM + ch) * TJ + p0 + gl;
            out[idx] = x1[idx] + stage[gl * 129 + cl] * s2[ch] + t2[ch];
        }
        __syncthreads();
    }
}

// ---------------------------------------------------------------------------
extern "C" void kernel_launch(void* const* d_in, const int* in_sizes, int n_in,
                              void* d_out, int out_size)
{
    const float* x    = (const float*)d_in[0];
    const float* n1g  = (const float*)d_in[1];
    const float* n1b  = (const float*)d_in[2];
    const float* n1m  = (const float*)d_in[3];
    const float* n1v  = (const float*)d_in[4];
    const float* qkvw = (const float*)d_in[5];
    const float* qg   = (const float*)d_in[6];
    const float* qb   = (const float*)d_in[7];
    const float* qm   = (const float*)d_in[8];
    const float* qv   = (const float*)d_in[9];
    const float* pw   = (const float*)d_in[10];
    const float* pb   = (const float*)d_in[11];
    const float* n2g  = (const float*)d_in[12];
    const float* n2b  = (const float*)d_in[13];
    const float* n2m  = (const float*)d_in[14];
    const float* n2v  = (const float*)d_in[15];
    const float* w1   = (const float*)d_in[16];
    const float* fb1  = (const float*)d_in[17];
    const float* b1g  = (const float*)d_in[18];
    const float* b1b  = (const float*)d_in[19];
    const float* b1m  = (const float*)d_in[20];
    const float* b1v  = (const float*)d_in[21];
    const float* w2   = (const float*)d_in[22];
    const float* fb2  = (const float*)d_in[23];
    const float* b2g  = (const float*)d_in[24];
    const float* b2b  = (const float*)d_in[25];
    const float* b2m  = (const float*)d_in[26];
    const float* b2v  = (const float*)d_in[27];
    float* out = (float*)d_out;

    cudaFuncSetAttribute(k_attn_mma,  cudaFuncAttributeMaxDynamicSharedMemorySize, AT_TOT);
    cudaFuncSetAttribute(k_conv_mma,  cudaFuncAttributeMaxDynamicSharedMemorySize, CV_TOT);
    cudaFuncSetAttribute(k_projc_mma, cudaFuncAttributeMaxDynamicSharedMemorySize, PC_TOT);
    cudaFuncSetAttribute(k_resize,    cudaFuncAttributeMaxDynamicSharedMemorySize, RZ_TOT);
    cudaFuncSetAttribute(k_mlp_mma2,  cudaFuncAttributeMaxDynamicSharedMemorySize, M2_TOT);

    k_prep_all<<<16384 + 4608, 512>>>(w1, w2, qkvw, pw, x, n1g, n1b, n1m, n1v);
    k_conv_mma<<<dim3(3, 129), 512, CV_TOT>>>(qg, qb, qm, qv);
    k_attn_mma<<<512, 544, AT_TOT>>>();
    k_projc_mma<<<129, 512, PC_TOT>>>();
    k_resize<<<dim3(34, 64), 256, RZ_TOT>>>(pb, x, out);
    k_mlp_mma2<<<1088, 512, M2_TOT>>>(out,
                                      b1g, b1b, b1m, b1v, fb1,
                                      b2g, b2b, b2m, b2v, fb2,
                                      n2g, n2b, n2m, n2v, out);
}

// round 17
// speedup vs baseline: 1.1528x; 1.0158x over previous
#include <cuda_runtime.h>
#include <cuda_fp16.h>
#include <math.h>
#include <stdint.h>

#define BATCH 64
#define CDIM 256
#define TDIM 128
#define JDIM 17
#define TJ 2176     // TDIM*JDIM
#define HCC 43
#define WCC 6
#define HW 258      // HCC*WCC
#define HIDDEN 1024

// scratch (static __device__ globals per harness rules)
__device__ __half g_qkv[(size_t)3 * BATCH * HW * CDIM];  // fp16 [b][t][hw][c]
__device__ __half g_att[(size_t)BATCH * HW * CDIM];      // fp16 [b][hw][c]
__device__ __half g_y[(size_t)BATCH * HW * CDIM];        // proj output (compressed grid)
__device__ __half g_xn[(size_t)BATCH * CDIM * TJ];       // n1bn(x) fp16
// fp16 weights
__device__ __half g_w1h[8 * 32768];            // W1 per-tile [128 j][256 i]
__device__ __half g_w2h[8 * 32768];            // W2 per-tile [256 c][128 j]
__device__ __half g_qwh[768 * 2304];           // qkv conv weight row-major
__device__ __half g_pwh[256 * 256];            // proj weight row-major

__device__ __forceinline__ float gelu_exact(float v) {
    return 0.5f * v * (1.0f + erff(v * 0.70710678118654752f));
}

__device__ __forceinline__ uint32_t smem_u32(const void* p) {
    uint32_t a;
    asm("{ .reg .u64 t; cvta.to.shared.u64 t, %1; cvt.u32.u64 %0, t; }" : "=r"(a) : "l"(p));
    return a;
}

__device__ __forceinline__ uint32_t h2_to_u32(__half2 h) {
    return *reinterpret_cast<uint32_t*>(&h);
}

#define LDM_X4(r, addr) \
    asm volatile("ldmatrix.sync.aligned.m8n8.x4.shared.b16 {%0,%1,%2,%3}, [%4];" \
        : "=r"((r)[0]), "=r"((r)[1]), "=r"((r)[2]), "=r"((r)[3]) : "r"(addr))

#define LDM_X4_T(r, addr) \
    asm volatile("ldmatrix.sync.aligned.m8n8.x4.trans.shared.b16 {%0,%1,%2,%3}, [%4];" \
        : "=r"((r)[0]), "=r"((r)[1]), "=r"((r)[2]), "=r"((r)[3]) : "r"(addr))

#define MMA16816(d, a, b0, b1) \
    asm volatile("mma.sync.aligned.m16n8k16.row.col.f32.f16.f16.f32 " \
        "{%0,%1,%2,%3}, {%4,%5,%6,%7}, {%8,%9}, {%0,%1,%2,%3};" \
        : "+f"((d)[0]), "+f"((d)[1]), "+f"((d)[2]), "+f"((d)[3]) \
        : "r"((a)[0]), "r"((a)[1]), "r"((a)[2]), "r"((a)[3]), "r"(b0), "r"(b1))

#define CP_ASYNC16(dst, src) \
    asm volatile("cp.async.cg.shared.global [%0], [%1], 16;" :: "r"(dst), "l"(src))
#define CP_COMMIT() asm volatile("cp.async.commit_group;")
#define CP_WAIT1()  asm volatile("cp.async.wait_group 1;" ::: "memory")
#define CP_WAIT0()  asm volatile("cp.async.wait_group 0;" ::: "memory")

// ---------------------------------------------------------------------------
// K0: merged prep — blocks [0,16384): xn = n1bn(x) fp16; rest: weight convert
// ---------------------------------------------------------------------------
__global__ void __launch_bounds__(512) k_prep_all(
    const float* __restrict__ w1, const float* __restrict__ w2,
    const float* __restrict__ qkvw, const float* __restrict__ pw,
    const float* __restrict__ x,
    const float* __restrict__ n1g, const float* __restrict__ n1b,
    const float* __restrict__ n1m, const float* __restrict__ n1v)
{
    const int blk = blockIdx.x;
    if (blk < 16384) {
        __shared__ float ss, tt;
        const int c = blk & 255;
        if (threadIdx.x == 0) {
            float s = n1g[c] * rsqrtf(n1v[c] + 1e-5f);
            ss = s;
            tt = n1b[c] - n1m[c] * s;
        }
        __syncthreads();
        const float* xr = x + (size_t)blk * TJ;
        __half* xo = g_xn + (size_t)blk * TJ;
        float s = ss, t = tt;
        for (int p = threadIdx.x; p < TJ; p += 512)
            xo[p] = __float2half(xr[p] * s + t);
        return;
    }
    int idx = (blk - 16384) * 512 + threadIdx.x;
    if (idx < 262144) {
        int j = idx >> 8, i = idx & 255;
        int nt = j >> 7, jl = j & 127;
        g_w1h[(uint32_t)nt * 32768 + (uint32_t)jl * 256 + i] = __float2half(w1[idx]);
    } else if (idx < 524288) {
        int t = idx - 262144;
        int c = t >> 10, j = t & 1023;
        int nt = j >> 7, jl = j & 127;
        g_w2h[(uint32_t)nt * 32768 + (uint32_t)c * 128 + jl] = __float2half(w2[t]);
    } else if (idx < 2293760) {
        int t = idx - 524288;
        g_qwh[t] = __float2half(qkvw[t]);
    } else {
        int t = idx - 2293760;
        g_pwh[t] = __float2half(pw[t]);
    }
}

// ---------------------------------------------------------------------------
// K1: conv QKV on HMMA (unchanged)
// ---------------------------------------------------------------------------
#define CV_KTAB  0
#define CV_SO    4608
#define CV_TO    5632
#define CV_PBUF  6656
#define CV_WBUF  76288
#define CV_STAGE CV_PBUF
#define CV_TOT   215552

__global__ void __launch_bounds__(512, 1) k_conv_mma(
    const float* __restrict__ qg, const float* __restrict__ qb,
    const float* __restrict__ qm, const float* __restrict__ qv)
{
    extern __shared__ char smem[];
    const uint32_t sbase = smem_u32(smem);
    const int tid = threadIdx.x;
    const int wid = tid >> 5, lane = tid & 31;
    const int wy = wid & 3, wx = wid >> 2;

    const int m0 = blockIdx.x * 256;
    const int n0 = blockIdx.y * 128;

    uint16_t* ktab = (uint16_t*)(smem + CV_KTAB);
    float*    s_o  = (float*)(smem + CV_SO);
    float*    t_o  = (float*)(smem + CV_TO);

    if (tid < 256) {
        int o = m0 + tid;
        float s = qg[o] * rsqrtf(qv[o] + 1e-5f);
        s_o[tid] = s;
        t_o[tid] = qb[o] - qm[o] * s;
    }
    for (int k = tid; k < 2304; k += 512) {
        int i = k / 9, r = k - i * 9;
        int ky = r / 3, kx = r - ky * 3;
        ktab[k] = (uint16_t)((i << 4) | (ky << 2) | kx);
    }
    __syncthreads();

    const int gl    = tid & 127;
    const int kslot = tid >> 7;
    int p_xo, p_iy, p_ix;
    {
        int g = n0 + gl;
        int b = g / HW, hw = g - b * HW;
        int y = hw / WCC, xx = hw - y * WCC;
        p_xo = b * (CDIM * TJ);
        p_iy = 3 * y - 1;
        p_ix = 3 * xx - 1;
    }

    const uint32_t a_row  = (lane & 7) + ((lane >> 3) & 1) * 8;
    const uint32_t a_koff = (lane >> 4) * 8;
    const uint32_t b_row  = (lane & 7) + (lane >> 4) * 8;
    const uint32_t b_koff = ((lane >> 3) & 1) * 8;

    __align__(16) unsigned short pv[32];

    auto cpW = [&](int kc, int bsel) {
        uint32_t dstb = sbase + CV_WBUF + (uint32_t)bsel * 69632;
#pragma unroll
        for (int t = 0; t < 8; t++) {
            int e = tid + t * 512;
            int row = e >> 4, col = e & 15;
            CP_ASYNC16(dstb + ((uint32_t)row * 136 + col * 8) * 2,
                       (const void*)(g_qwh + (size_t)(m0 + row) * 2304 + kc + col * 8));
        }
    };
    auto gatherP = [&](int kc) {
        const int kb = kc + kslot * 32;
#pragma unroll
        for (int t = 0; t < 32; t++) {
            uint32_t kt = ktab[kb + t];
            int i = kt >> 4, ky = (kt >> 2) & 3, kx = kt & 3;
            int iy = p_iy + ky, ix = p_ix + kx;
            unsigned short v = 0;
            if ((unsigned)iy < (unsigned)TDIM && (unsigned)ix < (unsigned)JDIM)
                v = *(const unsigned short*)&g_xn[p_xo + i * TJ + iy * JDIM + ix];
            pv[t] = v;
        }
    };
    auto storeP = [&](int bsel) {
        char* pb2 = smem + CV_PBUF + bsel * 34816;
        uint32_t off = ((uint32_t)gl * 136 + kslot * 32) * 2;
#pragma unroll
        for (int j = 0; j < 4; j++)
            *(uint4*)(pb2 + off + j * 16) = ((const uint4*)pv)[j];
    };

    float d[4][4][4];
#pragma unroll
    for (int mi = 0; mi < 4; mi++)
#pragma unroll
        for (int nf = 0; nf < 4; nf++)
#pragma unroll
            for (int q = 0; q < 4; q++) d[mi][nf][q] = 0.f;

    cpW(0, 0); CP_COMMIT();
    gatherP(0); storeP(0);

    for (int c = 0; c < 18; c++) {
        if (c < 17) {
            cpW((c + 1) * 128, (c + 1) & 1); CP_COMMIT();
            gatherP((c + 1) * 128);
            CP_WAIT1();
        } else {
            CP_WAIT0();
        }
        __syncthreads();

        const uint32_t wsb = sbase + CV_WBUF + (uint32_t)(c & 1) * 69632;
        const uint32_t psb = sbase + CV_PBUF + (uint32_t)(c & 1) * 34816;
#pragma unroll
        for (int ks = 0; ks < 8; ks++) {
            const int k0 = ks * 16;
            uint32_t b0[4], b1[4];
            LDM_X4(b0, psb + (((uint32_t)(wx * 32)      + b_row) * 136 + k0 + b_koff) * 2);
            LDM_X4(b1, psb + (((uint32_t)(wx * 32 + 16) + b_row) * 136 + k0 + b_koff) * 2);
            uint32_t a[4][4];
#pragma unroll
            for (int mi = 0; mi < 4; mi++)
                LDM_X4(a[mi], wsb + (((uint32_t)(wy * 64 + mi * 16) + a_row) * 136
                                      + k0 + a_koff) * 2);
#pragma unroll
            for (int mi = 0; mi < 4; mi++) {
                MMA16816(d[mi][0], a[mi], b0[0], b0[1]);
                MMA16816(d[mi][1], a[mi], b0[2], b0[3]);
                MMA16816(d[mi][2], a[mi], b1[0], b1[1]);
                MMA16816(d[mi][3], a[mi], b1[2], b1[3]);
            }
        }
        if (c < 17) storeP((c + 1) & 1);
        __syncthreads();
    }

    float* stage = (float*)(smem + CV_STAGE);
    const int tpart = blockIdx.x;
#pragma unroll
    for (int h = 0; h < 2; h++) {
        if ((wy >> 1) == h) {
            int r = lane >> 2, c2 = (lane & 3) * 2;
#pragma unroll
            for (int mi = 0; mi < 4; mi++) {
                int row = wy * 64 + mi * 16 + r - 128 * h;
#pragma unroll
                for (int nf = 0; nf < 4; nf++) {
                    int col = wx * 32 + nf * 8 + c2;
                    stage[col * 129 + row]           = d[mi][nf][0];
                    stage[(col + 1) * 129 + row]     = d[mi][nf][1];
                    stage[col * 129 + row + 8]       = d[mi][nf][2];
                    stage[(col + 1) * 129 + row + 8] = d[mi][nf][3];
                }
            }
        }
        __syncthreads();
        for (int e = tid; e < 16384; e += 512) {
            int gl2 = e >> 7, cl = e & 127;
            int g = n0 + gl2;
            int b = g / HW, hw = g - b * HW;
            int ch = 128 * h + cl;
            float v = stage[gl2 * 129 + cl] * s_o[ch] + t_o[ch];
            g_qkv[(((size_t)b * 3 + tpart) * HW + hw) * CDIM + ch]
                = __float2half(gelu_exact(v));
        }
        __syncthreads();
    }
}

// ---------------------------------------------------------------------------
// K2: attention on HMMA (unchanged)
// ---------------------------------------------------------------------------
#define AT_STR  40
#define AT_Q    0
#define AT_K    21760
#define AT_V    43520
#define AT_TOT  65280

__global__ void __launch_bounds__(544) k_attn_mma()
{
    extern __shared__ char smem[];
    const uint32_t sbase = smem_u32(smem);
    __half* qs = (__half*)(smem + AT_Q);
    __half* ks = (__half*)(smem + AT_K);
    __half* vs = (__half*)(smem + AT_V);

    const int bh = blockIdx.x;
    const int b = bh >> 3, h = bh & 7;
    const int tid = threadIdx.x;
    const int wid = tid >> 5, lane = tid & 31;

    const __half* qg = g_qkv + (((size_t)b * 3 + 0) * HW) * CDIM + h * 32;
    const __half* kg = g_qkv + (((size_t)b * 3 + 1) * HW) * CDIM + h * 32;
    const __half* vg = g_qkv + (((size_t)b * 3 + 2) * HW) * CDIM + h * 32;

    const __half2 sc2 = __float2half2_rn(0.17677669529663687f);
    for (int e = tid; e < 272 * 4; e += 544) {
        int r = e >> 2, d8 = (e & 3) * 8;
        uint4 q4 = make_uint4(0, 0, 0, 0), k4 = q4, v4 = q4;
        if (r < HW) {
            size_t off = (size_t)r * CDIM + d8;
            q4 = *(const uint4*)(qg + off);
            k4 = *(const uint4*)(kg + off);
            v4 = *(const uint4*)(vg + off);
        }
        __half2* qh = (__half2*)&q4;
#pragma unroll
        for (int j = 0; j < 4; j++) qh[j] = __hmul2(qh[j], sc2);
        *(uint4*)(qs + r * AT_STR + d8) = q4;
        *(uint4*)(ks + r * AT_STR + d8) = k4;
        *(uint4*)(vs + r * AT_STR + d8) = v4;
    }
    __syncthreads();

    const int m0 = wid * 16;
    const uint32_t a_row  = (lane & 7) + ((lane >> 3) & 1) * 8;
    const uint32_t a_koff = (lane >> 4) * 8;
    const uint32_t b_row  = (lane & 7) + (lane >> 4) * 8;
    const uint32_t b_koff = ((lane >> 3) & 1) * 8;
    const uint32_t v_row  = (lane & 7) + ((lane >> 3) & 1) * 8;
    const uint32_t v_col  = (lane >> 4) * 8;

    const uint32_t qs_base = sbase + AT_Q;
    const uint32_t ks_base = sbase + AT_K;
    const uint32_t vs_base = sbase + AT_V;

    uint32_t qa[2][4];
    LDM_X4(qa[0], qs_base + (((uint32_t)m0 + a_row) * AT_STR + 0  + a_koff) * 2);
    LDM_X4(qa[1], qs_base + (((uint32_t)m0 + a_row) * AT_STR + 16 + a_koff) * 2);

    float o[4][4];
#pragma unroll
    for (int nt = 0; nt < 4; nt++)
#pragma unroll
        for (int q = 0; q < 4; q++) o[nt][q] = 0.f;
    float mr = -1e30f, mr8 = -1e30f, lr = 0.f, lr8 = 0.f;

    const int c2 = (lane & 3) * 2;

    for (int jt = 0; jt < 17; jt++) {
        float s0[4] = {0.f, 0.f, 0.f, 0.f};
        float s1[4] = {0.f, 0.f, 0.f, 0.f};
        {
            uint32_t bb[4];
            LDM_X4(bb, ks_base + (((uint32_t)(jt * 16) + b_row) * AT_STR + 0 + b_koff) * 2);
            MMA16816(s0, qa[0], bb[0], bb[1]);
            MMA16816(s1, qa[0], bb[2], bb[3]);
            LDM_X4(bb, ks_base + (((uint32_t)(jt * 16) + b_row) * AT_STR + 16 + b_koff) * 2);
            MMA16816(s0, qa[1], bb[0], bb[1]);
            MMA16816(s1, qa[1], bb[2], bb[3]);
        }
        if (jt == 16) {
            if (256 + c2     >= HW) { s0[0] = -1e30f; s0[2] = -1e30f; }
            if (256 + c2 + 1 >= HW) { s0[1] = -1e30f; s0[3] = -1e30f; }
            if (256 + c2 + 8 >= HW) { s1[0] = -1e30f; s1[2] = -1e30f; }
            if (256 + c2 + 9 >= HW) { s1[1] = -1e30f; s1[3] = -1e30f; }
        }

        float cmr  = fmaxf(fmaxf(s0[0], s0[1]), fmaxf(s1[0], s1[1]));
        float cmr8 = fmaxf(fmaxf(s0[2], s0[3]), fmaxf(s1[2], s1[3]));
        cmr  = fmaxf(cmr,  __shfl_xor_sync(0xffffffffu, cmr, 1));
        cmr  = fmaxf(cmr,  __shfl_xor_sync(0xffffffffu, cmr, 2));
        cmr8 = fmaxf(cmr8, __shfl_xor_sync(0xffffffffu, cmr8, 1));
        cmr8 = fmaxf(cmr8, __shfl_xor_sync(0xffffffffu, cmr8, 2));
        float mnr  = fmaxf(mr, cmr);
        float mnr8 = fmaxf(mr8, cmr8);
        float corr  = __expf(mr - mnr);
        float corr8 = __expf(mr8 - mnr8);
        float p00 = __expf(s0[0] - mnr),  p01 = __expf(s0[1] - mnr);
        float p02 = __expf(s1[0] - mnr),  p03 = __expf(s1[1] - mnr);
        float p80 = __expf(s0[2] - mnr8), p81 = __expf(s0[3] - mnr8);
        float p82 = __expf(s1[2] - mnr8), p83 = __expf(s1[3] - mnr8);
        float ps  = p00 + p01 + p02 + p03;
        float ps8 = p80 + p81 + p82 + p83;
        ps  += __shfl_xor_sync(0xffffffffu, ps, 1);
        ps  += __shfl_xor_sync(0xffffffffu, ps, 2);
        ps8 += __shfl_xor_sync(0xffffffffu, ps8, 1);
        ps8 += __shfl_xor_sync(0xffffffffu, ps8, 2);
        lr  = lr  * corr  + ps;
        lr8 = lr8 * corr8 + ps8;
        mr = mnr; mr8 = mnr8;

        uint32_t pa[4];
        pa[0] = h2_to_u32(__floats2half2_rn(p00, p01));
        pa[1] = h2_to_u32(__floats2half2_rn(p80, p81));
        pa[2] = h2_to_u32(__floats2half2_rn(p02, p03));
        pa[3] = h2_to_u32(__floats2half2_rn(p82, p83));

#pragma unroll
        for (int nt = 0; nt < 4; nt++) {
            o[nt][0] *= corr;  o[nt][1] *= corr;
            o[nt][2] *= corr8; o[nt][3] *= corr8;
        }

        {
            uint32_t vb[4];
            LDM_X4_T(vb, vs_base + (((uint32_t)(jt * 16) + v_row) * AT_STR + 0 + v_col) * 2);
            MMA16816(o[0], pa, vb[0], vb[1]);
            MMA16816(o[1], pa, vb[2], vb[3]);
            LDM_X4_T(vb, vs_base + (((uint32_t)(jt * 16) + v_row) * AT_STR + 16 + v_col) * 2);
            MMA16816(o[2], pa, vb[0], vb[1]);
            MMA16816(o[3], pa, vb[2], vb[3]);
        }
    }

    const int r0 = m0 + (lane >> 2);
    float invr  = 1.f / lr;
    float invr8 = 1.f / lr8;
    if (r0 < HW) {
        __half* og = g_att + ((size_t)b * HW + r0) * CDIM + h * 32 + c2;
#pragma unroll
        for (int nt = 0; nt < 4; nt++)
            *(__half2*)(og + nt * 8) = __floats2half2_rn(o[nt][0] * invr, o[nt][1] * invr);
    }
    if (r0 + 8 < HW) {
        __half* og = g_att + ((size_t)b * HW + r0 + 8) * CDIM + h * 32 + c2;
#pragma unroll
        for (int nt = 0; nt < 4; nt++)
            *(__half2*)(og + nt * 8) = __floats2half2_rn(o[nt][2] * invr8, o[nt][3] * invr8);
    }
}

// ---------------------------------------------------------------------------
// K3a: proj on COMPRESSED grid (unchanged)
// ---------------------------------------------------------------------------
#define PC_WS    0
#define PC_PS    135168
#define PC_STAGE PC_PS
#define PC_TOT   202752

__global__ void __launch_bounds__(512, 1) k_projc_mma()
{
    extern __shared__ char smem[];
    const uint32_t sbase = smem_u32(smem);
    const int tid = threadIdx.x;
    const int wid = tid >> 5, lane = tid & 31;
    const int wy = wid & 3, wx = wid >> 2;

    const int n0 = blockIdx.x * 128;

    {
        uint32_t ws = sbase + PC_WS;
#pragma unroll
        for (int t = 0; t < 16; t++) {
            int e = tid + t * 512;
            int row = e >> 5, col = e & 31;
            CP_ASYNC16(ws + ((uint32_t)row * 264 + col * 8) * 2,
                       (const void*)(g_pwh + (size_t)row * 256 + col * 8));
        }
    }
    {
        uint32_t ps = sbase + PC_PS;
#pragma unroll
        for (int t = 0; t < 8; t++) {
            int e = tid + t * 512;
            int gl = e >> 5, col = e & 31;
            CP_ASYNC16(ps + ((uint32_t)gl * 264 + col * 8) * 2,
                       (const void*)(g_att + (size_t)(n0 + gl) * 256 + col * 8));
        }
    }
    CP_COMMIT(); CP_WAIT0();
    __syncthreads();

    const uint32_t a_row  = (lane & 7) + ((lane >> 3) & 1) * 8;
    const uint32_t a_koff = (lane >> 4) * 8;
    const uint32_t b_row  = (lane & 7) + (lane >> 4) * 8;
    const uint32_t b_koff = ((lane >> 3) & 1) * 8;
    const uint32_t ps_base = sbase + PC_PS;
    const uint32_t ws_base = sbase + PC_WS;

    float d[4][4][4];
#pragma unroll
    for (int mi = 0; mi < 4; mi++)
#pragma unroll
        for (int nf = 0; nf < 4; nf++)
#pragma unroll
            for (int q = 0; q < 4; q++) d[mi][nf][q] = 0.f;

#pragma unroll 4
    for (int k0 = 0; k0 < 256; k0 += 16) {
        uint32_t b0[4], b1[4];
        LDM_X4(b0, ps_base + (((uint32_t)(wx * 32)      + b_row) * 264 + k0 + b_koff) * 2);
        LDM_X4(b1, ps_base + (((uint32_t)(wx * 32 + 16) + b_row) * 264 + k0 + b_koff) * 2);
        uint32_t a[4][4];
#pragma unroll
        for (int mi = 0; mi < 4; mi++)
            LDM_X4(a[mi], ws_base + (((uint32_t)(wy * 64 + mi * 16) + a_row) * 264
                                      + k0 + a_koff) * 2);
#pragma unroll
        for (int mi = 0; mi < 4; mi++) {
            MMA16816(d[mi][0], a[mi], b0[0], b0[1]);
            MMA16816(d[mi][1], a[mi], b0[2], b0[3]);
            MMA16816(d[mi][2], a[mi], b1[0], b1[1]);
            MMA16816(d[mi][3], a[mi], b1[2], b1[3]);
        }
    }
    __syncthreads();

    float* stage = (float*)(smem + PC_STAGE);
#pragma unroll
    for (int h = 0; h < 2; h++) {
        if ((wy >> 1) == h) {
            int r = lane >> 2, c2 = (lane & 3) * 2;
#pragma unroll
            for (int mi = 0; mi < 4; mi++) {
                int row = wy * 64 + mi * 16 + r - 128 * h;
#pragma unroll
                for (int nf = 0; nf < 4; nf++) {
                    int col = wx * 32 + nf * 8 + c2;
                    stage[col * 129 + row]           = d[mi][nf][0];
                    stage[(col + 1) * 129 + row]     = d[mi][nf][1];
                    stage[col * 129 + row + 8]       = d[mi][nf][2];
                    stage[(col + 1) * 129 + row + 8] = d[mi][nf][3];
                }
            }
        }
        __syncthreads();
        for (int e = tid; e < 16384; e += 512) {
            int cl = e & 127, gl = e >> 7;
            g_y[(size_t)(n0 + gl) * 256 + 128 * h + cl]
                = __float2half(stage[gl * 129 + cl]);
        }
        __syncthreads();
    }
}

// ---------------------------------------------------------------------------
// K4: fused resize + MLP on HMMA.
// Prologue: pass A gathers bilinear(Y) into XS (c-coalesced); pass B reads x
// coalesced, forms x1 = x + bilin + pb, writes x1 -> out (L2-resident for the
// epilogue), and overwrites the same XS slot with Xn = x1*sn+tn (fp16).
// ---------------------------------------------------------------------------
#define M2_SN   0
#define M2_TN   1024
#define M2_S2   2048
#define M2_T2   3072
#define M2_S1   4096                     // float[1024]
#define M2_T1   8192                     // float[1024]
#define M2_PB   12288                    // float[256]
#define M2_O00  13312                    // int[128]
#define M2_O01  13824
#define M2_O10  14336
#define M2_O11  14848
#define M2_WXT  15360                    // float[128]
#define M2_WYT  15872                    // -> 16384
#define M2_XS   16384                    // [128 pos][264] half = 67584
#define M2_HS   83968                    // [128 pos][136] half = 34816
#define M2_WB   118784                   // 2 x 36864 = 73728 -> 192512
#define M2_ST   M2_XS
#define M2_TOT  192512

__global__ void __launch_bounds__(512, 1) k_mlp_mma2(
    const float* __restrict__ xin, const float* __restrict__ pbv,
    const float* __restrict__ b1g, const float* __restrict__ b1b,
    const float* __restrict__ b1m, const float* __restrict__ b1v,
    const float* __restrict__ fb1,
    const float* __restrict__ b2g, const float* __restrict__ b2b,
    const float* __restrict__ b2m, const float* __restrict__ b2v,
    const float* __restrict__ fb2,
    const float* __restrict__ n2g, const float* __restrict__ n2b,
    const float* __restrict__ n2m, const float* __restrict__ n2v,
    float* out)
{
    extern __shared__ char smem[];
    const uint32_t sbase = smem_u32(smem);
    const int tid = threadIdx.x;
    const int wid = tid >> 5, lane = tid & 31;
    const int wy = wid & 3, wx = wid >> 2;

    const int b  = blockIdx.x / 17;
    const int p0 = (blockIdx.x - b * 17) * 128;

    float* sn  = (float*)(smem + M2_SN);
    float* tn  = (float*)(smem + M2_TN);
    float* s2  = (float*)(smem + M2_S2);
    float* t2  = (float*)(smem + M2_T2);
    float* s1  = (float*)(smem + M2_S1);
    float* t1  = (float*)(smem + M2_T1);
    float* pbs = (float*)(smem + M2_PB);
    int*   o00 = (int*)(smem + M2_O00);
    int*   o01 = (int*)(smem + M2_O01);
    int*   o10 = (int*)(smem + M2_O10);
    int*   o11 = (int*)(smem + M2_O11);
    float* wxs = (float*)(smem + M2_WXT);
    float* wys = (float*)(smem + M2_WYT);

    auto cpW1 = [&](int nt, int c, int bsel) {
        uint32_t dstb = sbase + M2_WB + (uint32_t)bsel * 36864;
        const __half* src = g_w1h + nt * 32768 + c * 64;
#pragma unroll
        for (int t = 0; t < 2; t++) {
            int e = tid + t * 512;
            int row = e >> 3, col = e & 7;
            CP_ASYNC16(dstb + ((uint32_t)row * 72 + col * 8) * 2,
                       (const void*)(src + (size_t)row * 256 + col * 8));
        }
    };
    auto cpW2 = [&](int nt, int c, int bsel) {
        uint32_t dstb = sbase + M2_WB + (uint32_t)bsel * 36864;
        const __half* src = g_w2h + nt * 32768 + c * 64;
#pragma unroll
        for (int t = 0; t < 4; t++) {
            int e = tid + t * 512;
            int row = e >> 3, col = e & 7;
            CP_ASYNC16(dstb + ((uint32_t)row * 72 + col * 8) * 2,
                       (const void*)(src + (size_t)row * 128 + col * 8));
        }
    };

    cpW1(0, 0, 0); CP_COMMIT();

    if (tid < 256) {
        float s = n2g[tid] * rsqrtf(n2v[tid] + 1e-5f);
        sn[tid] = s;
        tn[tid] = n2b[tid] - n2m[tid] * s;
        pbs[tid] = pbv[tid];
    } else {
        int c = tid - 256;
        float s = b2g[c] * rsqrtf(b2v[c] + 1e-5f);
        s2[c] = s;
        t2[c] = b2b[c] - b2m[c] * s + fb2[c] * s;
    }
    for (int j = tid; j < HIDDEN; j += 512) {
        float s = b1g[j] * rsqrtf(b1v[j] + 1e-5f);
        s1[j] = s;
        t1[j] = b1b[j] - b1m[j] * s + fb1[j] * s;
    }
    if (tid < 128) {   // bilinear tables for the 128 positions of this tile
        int p = p0 + tid;
        int t = p / JDIM, j = p - t * JDIM;
        float sy = (t + 0.5f) * (43.0f / 128.0f) - 0.5f;
        sy = fminf(fmaxf(sy, 0.f), 42.f);
        int y0 = (int)sy;
        int y1 = min(y0 + 1, 42);
        float fy = sy - y0;
        float sx = (j + 0.5f) * (6.0f / 17.0f) - 0.5f;
        sx = fminf(fmaxf(sx, 0.f), 5.f);
        int x0 = (int)sx;
        int x1i = min(x0 + 1, 5);
        float fx = sx - x0;
        o00[tid] = (y0 * WCC + x0) * CDIM;
        o01[tid] = (y0 * WCC + x1i) * CDIM;
        o10[tid] = (y1 * WCC + x0) * CDIM;
        o11[tid] = (y1 * WCC + x1i) * CDIM;
        wxs[tid] = fx;
        wys[tid] = fy;
    }
    __syncthreads();

    // ---- pass A: bilinear(Y) -> XS (c-coalesced), fp16 ----
    const __half* yb = g_y + (size_t)b * HW * CDIM;
    for (int e = tid; e < 32768; e += 512) {
        int c = e & 255, gl = e >> 8;
        const __half* bp = yb + c;
        float fx = wxs[gl], fy = wys[gl];
        float a00 = __half2float(bp[o00[gl]]);
        float a01 = __half2float(bp[o01[gl]]);
        float a10 = __half2float(bp[o10[gl]]);
        float a11 = __half2float(bp[o11[gl]]);
        float v = (a00 * (1.f - fx) + a01 * fx) * (1.f - fy)
                + (a10 * (1.f - fx) + a11 * fx) * fy;
        *(__half*)(smem + M2_XS + ((uint32_t)gl * 264 + c) * 2) = __float2half(v);
    }
    __syncthreads();

    // ---- pass B: x1 = x + bilin + pb -> out; Xn = x1*sn+tn back into slot ----
    const float* xb = xin + (size_t)b * CDIM * TJ;
    for (int e = tid; e < 32768; e += 512) {
        int p = e & 127, i = e >> 7;
        __half* slot = (__half*)(smem + M2_XS + ((uint32_t)p * 264 + i) * 2);
        float att = __half2float(*slot);
        size_t idx = ((size_t)b * CDIM + i) * TJ + p0 + p;
        float x1v = xb[(size_t)i * TJ + p0 + p] + att + pbs[i];
        out[idx] = x1v;
        *slot = __float2half(x1v * sn[i] + tn[i]);
    }

    const uint32_t a_row  = (lane & 7) + ((lane >> 3) & 1) * 8;
    const uint32_t a_koff = (lane >> 4) * 8;
    const uint32_t b_row  = (lane & 7) + (lane >> 4) * 8;
    const uint32_t b_koff = ((lane >> 3) & 1) * 8;

    const uint32_t xs_base = sbase + M2_XS;
    const uint32_t hs_base = sbase + M2_HS;

    float d2[4][4][4];
#pragma unroll
    for (int mi = 0; mi < 4; mi++)
#pragma unroll
        for (int nf = 0; nf < 4; nf++)
#pragma unroll
            for (int q = 0; q < 4; q++) d2[mi][nf][q] = 0.f;

    int buf = 0;

    for (int nt = 0; nt < 8; nt++) {
        float d1[2][4][4];
#pragma unroll
        for (int mi = 0; mi < 2; mi++)
#pragma unroll
            for (int nf = 0; nf < 4; nf++)
#pragma unroll
                for (int q = 0; q < 4; q++) d1[mi][nf][q] = 0.f;

        for (int c = 0; c < 4; c++) {
            if (c < 3) cpW1(nt, c + 1, buf ^ 1);
            else       cpW2(nt, 0, buf ^ 1);
            CP_COMMIT(); CP_WAIT1();
            __syncthreads();

            const uint32_t wsb = sbase + M2_WB + (uint32_t)buf * 36864;
#pragma unroll
            for (int ks = 0; ks < 4; ks++) {
                const int k0 = ks * 16;
                const int kg = c * 64 + k0;
                uint32_t b0[4], b1[4];
                LDM_X4(b0, xs_base + (((uint32_t)(wx * 32)      + b_row) * 264 + kg + b_koff) * 2);
                LDM_X4(b1, xs_base + (((uint32_t)(wx * 32 + 16) + b_row) * 264 + kg + b_koff) * 2);
                uint32_t a[2][4];
#pragma unroll
                for (int mi = 0; mi < 2; mi++)
                    LDM_X4(a[mi], wsb + (((uint32_t)(wy * 32 + mi * 16) + a_row) * 72
                                          + k0 + a_koff) * 2);
#pragma unroll
                for (int mi = 0; mi < 2; mi++) {
                    MMA16816(d1[mi][0], a[mi], b0[0], b0[1]);
                    MMA16816(d1[mi][1], a[mi], b0[2], b0[3]);
                    MMA16816(d1[mi][2], a[mi], b1[0], b1[1]);
                    MMA16816(d1[mi][3], a[mi], b1[2], b1[3]);
                }
            }
            buf ^= 1;
            __syncthreads();
        }

        {
            int r = lane >> 2, c2l = (lane & 3) * 2;
#pragma unroll
            for (int mi = 0; mi < 2; mi++) {
                int j = wy * 32 + mi * 16 + r;
                float sj0 = s1[nt * 128 + j],     tj0 = t1[nt * 128 + j];
                float sj8 = s1[nt * 128 + j + 8], tj8 = t1[nt * 128 + j + 8];
#pragma unroll
                for (int nf = 0; nf < 4; nf++) {
                    int pos = wx * 32 + nf * 8 + c2l;
                    __half* h0 = (__half*)(smem + M2_HS + ((uint32_t)pos * 136 + j) * 2);
                    __half* h1 = (__half*)(smem + M2_HS + ((uint32_t)(pos + 1) * 136 + j) * 2);
                    h0[0] = __float2half(gelu_exact(d1[mi][nf][0] * sj0 + tj0));
                    h1[0] = __float2half(gelu_exact(d1[mi][nf][1] * sj0 + tj0));
                    h0[8] = __float2half(gelu_exact(d1[mi][nf][2] * sj8 + tj8));
                    h1[8] = __float2half(gelu_exact(d1[mi][nf][3] * sj8 + tj8));
                }
            }
        }

        for (int c = 0; c < 2; c++) {
            if (c == 0)        { cpW2(nt, 1, buf ^ 1); CP_COMMIT(); CP_WAIT1(); }
            else if (nt < 7)   { cpW1(nt + 1, 0, buf ^ 1); CP_COMMIT(); CP_WAIT1(); }
            else               { CP_WAIT0(); }
            __syncthreads();

            const uint32_t wsb = sbase + M2_WB + (uint32_t)buf * 36864;
#pragma unroll
            for (int ks = 0; ks < 4; ks++) {
                const int k0 = ks * 16;
                const int kg = c * 64 + k0;
                uint32_t b0[4], b1[4];
                LDM_X4(b0, hs_base + (((uint32_t)(wx * 32)      + b_row) * 136 + kg + b_koff) * 2);
                LDM_X4(b1, hs_base + (((uint32_t)(wx * 32 + 16) + b_row) * 136 + kg + b_koff) * 2);
                uint32_t a[4][4];
#pragma unroll
                for (int mi = 0; mi < 4; mi++)
                    LDM_X4(a[mi], wsb + (((uint32_t)(wy * 64 + mi * 16) + a_row) * 72
                                          + k0 + a_koff) * 2);
#pragma unroll
                for (int mi = 0; mi < 4; mi++) {
                    MMA16816(d2[mi][0], a[mi], b0[0], b0[1]);
                    MMA16816(d2[mi][1], a[mi], b0[2], b0[3]);
                    MMA16816(d2[mi][2], a[mi], b1[0], b1[1]);
                    MMA16816(d2[mi][3], a[mi], b1[2], b1[3]);
                }
            }
            buf ^= 1;
            __syncthreads();
        }
    }

    float* stage = (float*)(smem + M2_ST);
#pragma unroll
    for (int h = 0; h < 2; h++) {
        if ((wy >> 1) == h) {
            int r = lane >> 2, c2l = (lane & 3) * 2;
#pragma unroll
            for (int mi = 0; mi < 4; mi++) {
                int row = wy * 64 + mi * 16 + r - 128 * h;
#pragma unroll
                for (int nf = 0; nf < 4; nf++) {
                    int col = wx * 32 + nf * 8 + c2l;
                    stage[col * 129 + row]           = d2[mi][nf][0];
                    stage[(col + 1) * 129 + row]     = d2[mi][nf][1];
                    stage[col * 129 + row + 8]       = d2[mi][nf][2];
                    stage[(col + 1) * 129 + row + 8] = d2[mi][nf][3];
                }
            }
        }
        __syncthreads();
        for (int e = tid; e < 16384; e += 512) {
            int gl = e & 127, cl = e >> 7;
            int ch = 128 * h + cl;
            size_t idx = ((size_t)b * CDIM + ch) * TJ + p0 + gl;
            out[idx] = out[idx] + stage[gl * 129 + cl] * s2[ch] + t2[ch];
        }
        __syncthreads();
    }
}

// ---------------------------------------------------------------------------
extern "C" void kernel_launch(void* const* d_in, const int* in_sizes, int n_in,
                              void* d_out, int out_size)
{
    const float* x    = (const float*)d_in[0];
    const float* n1g  = (const float*)d_in[1];
    const float* n1b  = (const float*)d_in[2];
    const float* n1m  = (const float*)d_in[3];
    const float* n1v  = (const float*)d_in[4];
    const float* qkvw = (const float*)d_in[5];
    const float* qg   = (const float*)d_in[6];
    const float* qb   = (const float*)d_in[7];
    const float* qm   = (const float*)d_in[8];
    const float* qv   = (const float*)d_in[9];
    const float* pw   = (const float*)d_in[10];
    const float* pb   = (const float*)d_in[11];
    const float* n2g  = (const float*)d_in[12];
    const float* n2b  = (const float*)d_in[13];
    const float* n2m  = (const float*)d_in[14];
    const float* n2v  = (const float*)d_in[15];
    const float* w1   = (const float*)d_in[16];
    const float* fb1  = (const float*)d_in[17];
    const float* b1g  = (const float*)d_in[18];
    const float* b1b  = (const float*)d_in[19];
    const float* b1m  = (const float*)d_in[20];
    const float* b1v  = (const float*)d_in[21];
    const float* w2   = (const float*)d_in[22];
    const float* fb2  = (const float*)d_in[23];
    const float* b2g  = (const float*)d_in[24];
    const float* b2b  = (const float*)d_in[25];
    const float* b2m  = (const float*)d_in[26];
    const float* b2v  = (const float*)d_in[27];
    float* out = (float*)d_out;

    cudaFuncSetAttribute(k_attn_mma,  cudaFuncAttributeMaxDynamicSharedMemorySize, AT_TOT);
    cudaFuncSetAttribute(k_conv_mma,  cudaFuncAttributeMaxDynamicSharedMemorySize, CV_TOT);
    cudaFuncSetAttribute(k_projc_mma, cudaFuncAttributeMaxDynamicSharedMemorySize, PC_TOT);
    cudaFuncSetAttribute(k_mlp_mma2,  cudaFuncAttributeMaxDynamicSharedMemorySize, M2_TOT);

    k_prep_all<<<16384 + 4608, 512>>>(w1, w2, qkvw, pw, x, n1g, n1b, n1m, n1v);
    k_conv_mma<<<dim3(3, 129), 512, CV_TOT>>>(qg, qb, qm, qv);
    k_attn_mma<<<512, 544, AT_TOT>>>();
    k_projc_mma<<<129, 512, PC_TOT>>>();
    k_mlp_mma2<<<1088, 512, M2_TOT>>>(x, pb,
                                      b1g, b1b, b1m, b1v, fb1,
                                      b2g, b2b, b2m, b2v, fb2,
                                      n2g, n2b, n2m, n2v, out);
}